// round 6
// baseline (speedup 1.0000x reference)
#include <cuda_runtime.h>
#include <cuda_bf16.h>
#include <math.h>
#include <stdint.h>

#define N_NODES 50000
#define MPAD    50048   // 391 * 128
#define E0      800000
#define NE      850000
#define F_IN    1433
#define K1PAD   1472    // 46 * 32
#define H1      512
#define H2      256
#define NC      7

// ==================== scratch (device globals) ====================
__device__ __nv_bfloat16 g_Ahi[(size_t)MPAD * K1PAD];
__device__ __nv_bfloat16 g_Alo[(size_t)MPAD * K1PAD];
__device__ __nv_bfloat16 g_Bhi[(size_t)H1 * K1PAD];
__device__ __nv_bfloat16 g_Blo[(size_t)H1 * K1PAD];
__device__ float g_buf1[(size_t)MPAD * H1];
__device__ float g_buf2[(size_t)MPAD * H1];
__device__ float g_ss[N_NODES];
__device__ float g_sd[N_NODES];
__device__ float g_m[N_NODES];
__device__ float g_den[N_NODES];
__device__ float g_ee[NE];
__device__ int   g_src[NE];
__device__ int   g_dst[NE];
__device__ float g_c[(size_t)N_NODES * NC];
__device__ int   g_is64;

// ==================== PTX helpers (base-arch only!) ====================
__device__ __forceinline__ uint32_t smem_u32(const void* p) {
    uint32_t a;
    asm("{ .reg .u64 t; cvta.to.shared.u64 t, %1; cvt.u32.u64 %0, t; }" : "=r"(a) : "l"(p));
    return a;
}
__device__ __forceinline__ void cp16(uint32_t dst, const void* src) {
    asm volatile("cp.async.cg.shared.global [%0], [%1], 16;" :: "r"(dst), "l"(src));
}
__device__ __forceinline__ void ldm_x4(uint32_t& r0, uint32_t& r1, uint32_t& r2, uint32_t& r3,
                                       uint32_t addr) {
    asm volatile("ldmatrix.sync.aligned.m8n8.x4.shared.b16 {%0,%1,%2,%3}, [%4];"
                 : "=r"(r0), "=r"(r1), "=r"(r2), "=r"(r3) : "r"(addr));
}
__device__ __forceinline__ void mma_bf16(float* c, const uint32_t* a, const uint32_t* b) {
    asm volatile("mma.sync.aligned.m16n8k16.row.col.f32.bf16.bf16.f32 "
                 "{%0,%1,%2,%3}, {%4,%5,%6,%7}, {%8,%9}, {%0,%1,%2,%3};"
                 : "+f"(c[0]), "+f"(c[1]), "+f"(c[2]), "+f"(c[3])
                 : "r"(a[0]), "r"(a[1]), "r"(a[2]), "r"(a[3]), "r"(b[0]), "r"(b[1]));
}

__device__ __forceinline__ void atomicMaxF(float* addr, float v) {
    if (v >= 0.0f) atomicMax((int*)addr, __float_as_int(v));
    else           atomicMin((unsigned int*)addr, __float_as_uint(v));
}

// ==================== graph / edge kernels ====================
__global__ void detect_kernel(const unsigned int* __restrict__ w) {
    __shared__ int nz;
    if (threadIdx.x == 0) nz = 0;
    __syncthreads();
    if (w[threadIdx.x * 2 + 1] != 0u) atomicOr(&nz, 1);
    __syncthreads();
    if (threadIdx.x == 0) g_is64 = (nz == 0);
}

__global__ void prep_edges_kernel(const void* __restrict__ ei) {
    int i = blockIdx.x * blockDim.x + threadIdx.x;
    if (i >= NE) return;
    int s, d;
    if (i < E0) {
        if (g_is64) {
            const long long* e = (const long long*)ei;
            s = (int)e[i]; d = (int)e[E0 + i];
        } else {
            const int* e = (const int*)ei;
            s = e[i]; d = e[E0 + i];
        }
    } else {
        s = d = i - E0;
    }
    s = min(max(s, 0), N_NODES - 1);
    d = min(max(d, 0), N_NODES - 1);
    g_src[i] = s;
    g_dst[i] = d;
}

__global__ void zero_kernel(float* __restrict__ p, size_t n) {
    size_t i = (size_t)blockIdx.x * blockDim.x + threadIdx.x;
    size_t stride = (size_t)gridDim.x * blockDim.x;
    for (; i < n; i += stride) p[i] = 0.0f;
}

// ==================== precision-split conversion ====================
__global__ void split_A_kernel(const float* __restrict__ A, int M, int K, int Kpad,
                               __nv_bfloat16* __restrict__ hi, __nv_bfloat16* __restrict__ lo) {
    size_t total = (size_t)MPAD * Kpad;
    size_t i = (size_t)blockIdx.x * blockDim.x + threadIdx.x;
    size_t stride = (size_t)gridDim.x * blockDim.x;
    for (; i < total; i += stride) {
        int r = (int)(i / Kpad), c = (int)(i % Kpad);
        float v = (r < M && c < K) ? A[(size_t)r * K + c] : 0.0f;
        __nv_bfloat16 h = __float2bfloat16(v);
        hi[i] = h;
        lo[i] = __float2bfloat16(v - __bfloat162float(h));
    }
}

__global__ void split_Wt_kernel(const float* __restrict__ W, int K, int N, int Kpad,
                                __nv_bfloat16* __restrict__ hi, __nv_bfloat16* __restrict__ lo) {
    size_t total = (size_t)N * Kpad;
    size_t i = (size_t)blockIdx.x * blockDim.x + threadIdx.x;
    size_t stride = (size_t)gridDim.x * blockDim.x;
    for (; i < total; i += stride) {
        int n = (int)(i / Kpad), k = (int)(i % Kpad);
        float v = (k < K) ? W[(size_t)k * N + n] : 0.0f;
        __nv_bfloat16 h = __float2bfloat16(v);
        hi[i] = h;
        lo[i] = __float2bfloat16(v - __bfloat162float(h));
    }
}

// ==================== mma.sync bf16x3 GEMM ====================
// C[MPAD,Nc] = A(hi+lo)[MPAD,Kpad] x (B(hi+lo)[Nc,Kpad])^T  (B rows are K-major)
// CTA tile 128x128, 8 warps (4x2), warp tile 32x64, K-chunk 32, double-buffered cp.async.
// smem pitch: 40 bf16 = 80 B per row (conflict-free for cp.async stores + ldmatrix).
#define KC        32
#define SPITCH    80            // bytes per smem row
#define ARR_BYTES (128 * SPITCH)    // 10240
#define STG_BYTES (4 * ARR_BYTES)   // 40960
#define OFF_AHI   0
#define OFF_ALO   ARR_BYTES
#define OFF_BHI   (2 * ARR_BYTES)
#define OFF_BLO   (3 * ARR_BYTES)
#define SMEM_DYN  (2 * STG_BYTES)   // 81920

__global__ void __launch_bounds__(256)
gemm_tc_kernel(const __nv_bfloat16* __restrict__ Ahi, const __nv_bfloat16* __restrict__ Alo,
               const __nv_bfloat16* __restrict__ Bhi, const __nv_bfloat16* __restrict__ Blo,
               float* __restrict__ C, int Kpad, int Nc) {
    extern __shared__ char smem[];
    const uint32_t sb = smem_u32(smem);
    const int tid = threadIdx.x;
    const int wid = tid >> 5, lane = tid & 31;
    const int warp_m = wid & 3, warp_n = wid >> 2;
    const int m0 = blockIdx.y * 128;
    const int n0 = blockIdx.x * 128;
    const int nchunks = Kpad / KC;

    // ---- per-thread load mapping: 2 tasks x (4 arrays) per chunk ----
    const int row0 = tid >> 2, seg = tid & 3;           // task 0: rows 0..63
    const int row1 = row0 + 64;                          // task 1: rows 64..127
    const uint32_t s0 = (uint32_t)row0 * SPITCH + seg * 16;
    const uint32_t s1 = (uint32_t)row1 * SPITCH + seg * 16;
    const size_t gA0 = (size_t)(m0 + row0) * Kpad + seg * 8;
    const size_t gA1 = (size_t)(m0 + row1) * Kpad + seg * 8;
    const size_t gB0 = (size_t)(n0 + row0) * Kpad + seg * 8;
    const size_t gB1 = (size_t)(n0 + row1) * Kpad + seg * 8;

    // ---- ldmatrix lane addressing ----
    const int lr = lane & 7, g = lane >> 3;
    // A tile (m16 x k16): matrices [m0-7,k0-7],[m8-15,k0-7],[m0-7,k8-15],[m8-15,k8-15]
    const uint32_t offA = (uint32_t)(warp_m * 32 + lr + (g & 1) * 8) * SPITCH + (g >> 1) * 16;
    // B tile-pair (n16 x k16): [n0-7,k0-7],[n0-7,k8-15],[n8-15,k0-7],[n8-15,k8-15]
    const uint32_t offB = (uint32_t)(warp_n * 64 + lr + (g >> 1) * 8) * SPITCH + (g & 1) * 16;

    float acc[2][8][4];
    #pragma unroll
    for (int mi = 0; mi < 2; mi++)
        #pragma unroll
        for (int ni = 0; ni < 8; ni++)
            #pragma unroll
            for (int q = 0; q < 4; q++) acc[mi][ni][q] = 0.0f;

    // ---- prologue: stage 0 ----
    {
        const uint32_t d = sb;
        cp16(d + OFF_AHI + s0, Ahi + gA0); cp16(d + OFF_AHI + s1, Ahi + gA1);
        cp16(d + OFF_ALO + s0, Alo + gA0); cp16(d + OFF_ALO + s1, Alo + gA1);
        cp16(d + OFF_BHI + s0, Bhi + gB0); cp16(d + OFF_BHI + s1, Bhi + gB1);
        cp16(d + OFF_BLO + s0, Blo + gB0); cp16(d + OFF_BLO + s1, Blo + gB1);
        asm volatile("cp.async.commit_group;");
    }

    for (int c = 0; c < nchunks; c++) {
        if (c + 1 < nchunks) {
            const uint32_t d = sb + ((c + 1) & 1) * STG_BYTES;
            const size_t ko = (size_t)(c + 1) * KC;
            cp16(d + OFF_AHI + s0, Ahi + gA0 + ko); cp16(d + OFF_AHI + s1, Ahi + gA1 + ko);
            cp16(d + OFF_ALO + s0, Alo + gA0 + ko); cp16(d + OFF_ALO + s1, Alo + gA1 + ko);
            cp16(d + OFF_BHI + s0, Bhi + gB0 + ko); cp16(d + OFF_BHI + s1, Bhi + gB1 + ko);
            cp16(d + OFF_BLO + s0, Blo + gB0 + ko); cp16(d + OFF_BLO + s1, Blo + gB1 + ko);
            asm volatile("cp.async.commit_group;");
            asm volatile("cp.async.wait_group 1;");
        } else {
            asm volatile("cp.async.wait_group 0;");
        }
        __syncthreads();

        const uint32_t base = sb + (c & 1) * STG_BYTES;
        #pragma unroll
        for (int ks = 0; ks < 2; ks++) {           // two k16 steps per chunk
            const uint32_t kadd = ks * 32;         // 16 bf16 = 32 bytes
            uint32_t ahi[2][4], alo[2][4], bhi[8][2], blo[8][2];
            #pragma unroll
            for (int mt = 0; mt < 2; mt++) {
                ldm_x4(ahi[mt][0], ahi[mt][1], ahi[mt][2], ahi[mt][3],
                       base + OFF_AHI + offA + mt * 16 * SPITCH + kadd);
                ldm_x4(alo[mt][0], alo[mt][1], alo[mt][2], alo[mt][3],
                       base + OFF_ALO + offA + mt * 16 * SPITCH + kadd);
            }
            #pragma unroll
            for (int np = 0; np < 4; np++) {
                ldm_x4(bhi[2*np][0], bhi[2*np][1], bhi[2*np+1][0], bhi[2*np+1][1],
                       base + OFF_BHI + offB + np * 16 * SPITCH + kadd);
                ldm_x4(blo[2*np][0], blo[2*np][1], blo[2*np+1][0], blo[2*np+1][1],
                       base + OFF_BLO + offB + np * 16 * SPITCH + kadd);
            }
            #pragma unroll
            for (int mi = 0; mi < 2; mi++)
                #pragma unroll
                for (int ni = 0; ni < 8; ni++) {
                    mma_bf16(acc[mi][ni], ahi[mi], bhi[ni]);
                    mma_bf16(acc[mi][ni], ahi[mi], blo[ni]);
                    mma_bf16(acc[mi][ni], alo[mi], bhi[ni]);
                }
        }
        __syncthreads();
    }

    // ---- epilogue: direct global stores ----
    const int er = lane >> 2, ec = (lane & 3) * 2;
    #pragma unroll
    for (int mi = 0; mi < 2; mi++) {
        const int r_lo = m0 + warp_m * 32 + mi * 16 + er;
        #pragma unroll
        for (int ni = 0; ni < 8; ni++) {
            const int cc = n0 + warp_n * 64 + ni * 8 + ec;
            *(float2*)(C + (size_t)r_lo * Nc + cc)       = make_float2(acc[mi][ni][0], acc[mi][ni][1]);
            *(float2*)(C + (size_t)(r_lo + 8) * Nc + cc) = make_float2(acc[mi][ni][2], acc[mi][ni][3]);
        }
    }
}

// ==================== attention / aggregation kernels ====================
__global__ void s_kernel(const float* __restrict__ h, const float* __restrict__ a_s,
                         const float* __restrict__ a_d, int F) {
    int node = blockIdx.x * (blockDim.x >> 5) + (threadIdx.x >> 5);
    int lane = threadIdx.x & 31;
    if (node >= N_NODES) return;
    const float* hr = h + (size_t)node * F;
    float vs = 0.0f, vd = 0.0f;
    for (int f = lane; f < F; f += 32) {
        float x = hr[f];
        vs += x * a_s[f];
        vd += x * a_d[f];
    }
    #pragma unroll
    for (int o = 16; o > 0; o >>= 1) {
        vs += __shfl_down_sync(0xffffffffu, vs, o);
        vd += __shfl_down_sync(0xffffffffu, vd, o);
    }
    if (lane == 0) {
        g_ss[node] = vs;
        g_sd[node] = vd;
        g_m[node]  = -INFINITY;
        g_den[node] = 0.0f;
    }
}

__global__ void edge_max_kernel() {
    int e = blockIdx.x * blockDim.x + threadIdx.x;
    if (e >= NE) return;
    int s = g_src[e], d = g_dst[e];
    float v = g_ss[s] + g_sd[d];
    v = v > 0.0f ? v : 0.2f * v;
    g_ee[e] = v;
    atomicMaxF(&g_m[d], v);
}

__global__ void edge_exp_kernel() {
    int e = blockIdx.x * blockDim.x + threadIdx.x;
    if (e >= NE) return;
    int d = g_dst[e];
    float ee = __expf(g_ee[e] - g_m[d]);
    g_ee[e] = ee;
    atomicAdd(&g_den[d], ee);
}

__global__ void edge_agg_kernel(const float* __restrict__ h, float* __restrict__ out, int F) {
    int e = blockIdx.x * (blockDim.x >> 5) + (threadIdx.x >> 5);
    if (e >= NE) return;
    int lane = threadIdx.x & 31;
    int s = g_src[e], d = g_dst[e];
    float w = g_ee[e] / g_den[d];
    const float4* hs = (const float4*)(h + (size_t)s * F);
    float* o = out + (size_t)d * F;
    int F4 = F >> 2;
    for (int f = lane; f < F4; f += 32) {
        float4 v = hs[f];
        atomicAdd(o + f * 4 + 0, w * v.x);
        atomicAdd(o + f * 4 + 1, w * v.y);
        atomicAdd(o + f * 4 + 2, w * v.z);
        atomicAdd(o + f * 4 + 3, w * v.w);
    }
}

__global__ void bias_relu_kernel(float* __restrict__ p, const float* __restrict__ b,
                                 int F, int do_relu) {
    size_t i = (size_t)blockIdx.x * blockDim.x + threadIdx.x;
    size_t n = (size_t)N_NODES * F;
    if (i >= n) return;
    int f = (int)(i % F);
    float x = p[i] + b[f];
    p[i] = do_relu ? fmaxf(x, 0.0f) : x;
}

__global__ void gemm3_kernel(const float* __restrict__ A, const float* __restrict__ W,
                             float* __restrict__ C) {
    int i = blockIdx.x * blockDim.x + threadIdx.x;
    if (i >= N_NODES) return;
    const float* a = A + (size_t)i * H2;
    float acc[NC] = {0,0,0,0,0,0,0};
    for (int k = 0; k < H2; k++) {
        float av = a[k];
        const float* wr = W + k * NC;
        #pragma unroll
        for (int c = 0; c < NC; c++) acc[c] += av * wr[c];
    }
    #pragma unroll
    for (int c = 0; c < NC; c++) C[(size_t)i * NC + c] = acc[c];
}

__global__ void edge_agg7_kernel(const float* __restrict__ h, float* __restrict__ out) {
    int e = blockIdx.x * blockDim.x + threadIdx.x;
    if (e >= NE) return;
    int s = g_src[e], d = g_dst[e];
    float w = g_ee[e] / g_den[d];
    const float* hs = h + (size_t)s * NC;
    float* o = out + (size_t)d * NC;
    #pragma unroll
    for (int c = 0; c < NC; c++) atomicAdd(o + c, w * hs[c]);
}

__global__ void final_kernel(const float* __restrict__ agg, const float* __restrict__ b,
                             float* __restrict__ out) {
    int i = blockIdx.x * blockDim.x + threadIdx.x;
    if (i >= N_NODES) return;
    float z[NC];
    float mx = -INFINITY;
    #pragma unroll
    for (int c = 0; c < NC; c++) {
        z[c] = agg[(size_t)i * NC + c] + b[c];
        mx = fmaxf(mx, z[c]);
    }
    float ssum = 0.0f;
    #pragma unroll
    for (int c = 0; c < NC; c++) ssum += __expf(z[c] - mx);
    float l = logf(ssum);
    #pragma unroll
    for (int c = 0; c < NC; c++) out[(size_t)i * NC + c] = z[c] - mx - l;
}

// ==================== launcher ====================
extern "C" void kernel_launch(void* const* d_in, const int* in_sizes, int n_in,
                              void* d_out, int out_size) {
    const float* x   = (const float*)d_in[0];
    const void*  ei  = d_in[1];
    const float* W1  = (const float*)d_in[2];
    const float* as1 = (const float*)d_in[3];
    const float* ad1 = (const float*)d_in[4];
    const float* b1  = (const float*)d_in[5];
    const float* W2  = (const float*)d_in[6];
    const float* as2 = (const float*)d_in[7];
    const float* ad2 = (const float*)d_in[8];
    const float* b2  = (const float*)d_in[9];
    const float* W3  = (const float*)d_in[10];
    const float* as3 = (const float*)d_in[11];
    const float* ad3 = (const float*)d_in[12];
    const float* b3  = (const float*)d_in[13];
    float* out = (float*)d_out;

    float *buf1, *buf2, *cbuf;
    __nv_bfloat16 *ahi, *alo, *bhi, *blo;
    cudaGetSymbolAddress((void**)&buf1, g_buf1);
    cudaGetSymbolAddress((void**)&buf2, g_buf2);
    cudaGetSymbolAddress((void**)&cbuf, g_c);
    cudaGetSymbolAddress((void**)&ahi, g_Ahi);
    cudaGetSymbolAddress((void**)&alo, g_Alo);
    cudaGetSymbolAddress((void**)&bhi, g_Bhi);
    cudaGetSymbolAddress((void**)&blo, g_Blo);

    cudaFuncSetAttribute(gemm_tc_kernel, cudaFuncAttributeMaxDynamicSharedMemorySize, SMEM_DYN);

    const int BT = 256;
    const int edge_blocks      = (NE + BT - 1) / BT;
    const int edge_warp_blocks = (NE + (BT / 32) - 1) / (BT / 32);
    const int node_warp_blocks = (N_NODES + (BT / 32) - 1) / (BT / 32);
    const int node_blocks      = (N_NODES + BT - 1) / BT;

    detect_kernel<<<1, 128>>>((const unsigned int*)ei);
    prep_edges_kernel<<<edge_blocks, BT>>>(ei);

    // ---------------- layer 1: F_IN -> H1 ----------------
    split_A_kernel<<<4096, BT>>>(x, N_NODES, F_IN, K1PAD, ahi, alo);
    split_Wt_kernel<<<2048, BT>>>(W1, F_IN, H1, K1PAD, bhi, blo);
    gemm_tc_kernel<<<dim3(H1 / 128, MPAD / 128), BT, SMEM_DYN>>>(ahi, alo, bhi, blo, buf1, K1PAD, H1);
    s_kernel<<<node_warp_blocks, BT>>>(buf1, as1, ad1, H1);
    zero_kernel<<<2048, BT>>>(buf2, (size_t)N_NODES * H1);
    edge_max_kernel<<<edge_blocks, BT>>>();
    edge_exp_kernel<<<edge_blocks, BT>>>();
    edge_agg_kernel<<<edge_warp_blocks, BT>>>(buf1, buf2, H1);
    bias_relu_kernel<<<(int)(((size_t)N_NODES * H1 + BT - 1) / BT), BT>>>(buf2, b1, H1, 1);

    // ---------------- layer 2: H1 -> H2 ----------------
    split_A_kernel<<<4096, BT>>>(buf2, N_NODES, H1, H1, ahi, alo);
    split_Wt_kernel<<<2048, BT>>>(W2, H1, H2, H1, bhi, blo);
    gemm_tc_kernel<<<dim3(H2 / 128, MPAD / 128), BT, SMEM_DYN>>>(ahi, alo, bhi, blo, buf1, H1, H2);
    s_kernel<<<node_warp_blocks, BT>>>(buf1, as2, ad2, H2);
    zero_kernel<<<2048, BT>>>(buf2, (size_t)N_NODES * H2);
    edge_max_kernel<<<edge_blocks, BT>>>();
    edge_exp_kernel<<<edge_blocks, BT>>>();
    edge_agg_kernel<<<edge_warp_blocks, BT>>>(buf1, buf2, H2);
    bias_relu_kernel<<<(int)(((size_t)N_NODES * H2 + BT - 1) / BT), BT>>>(buf2, b2, H2, 1);

    // ---------------- layer 3: H2 -> NC ----------------
    gemm3_kernel<<<node_blocks, BT>>>(buf2, W3, buf1);
    s_kernel<<<node_warp_blocks, BT>>>(buf1, as3, ad3, NC);
    zero_kernel<<<512, BT>>>(cbuf, (size_t)N_NODES * NC);
    edge_max_kernel<<<edge_blocks, BT>>>();
    edge_exp_kernel<<<edge_blocks, BT>>>();
    edge_agg7_kernel<<<edge_blocks, BT>>>(buf1, cbuf);
    final_kernel<<<node_blocks, BT>>>(cbuf, b3, out);
}

// round 7
// speedup vs baseline: 1.9061x; 1.9061x over previous
#include <cuda_runtime.h>
#include <cuda_bf16.h>
#include <math.h>
#include <stdint.h>

#define N_NODES 50000
#define MPAD    50048   // 391 * 128
#define E0      800000
#define NE      850000
#define F_IN    1433
#define K1PAD   1472    // 46 * 32
#define H1      512
#define H2      256
#define NC      7

// ==================== scratch (device globals) ====================
__device__ __nv_bfloat16 g_Ahi[(size_t)MPAD * K1PAD];
__device__ __nv_bfloat16 g_Alo[(size_t)MPAD * K1PAD];
__device__ __nv_bfloat16 g_Bhi[(size_t)H1 * K1PAD];
__device__ __nv_bfloat16 g_Blo[(size_t)H1 * K1PAD];
__device__ float g_buf1[(size_t)MPAD * H1];
__device__ float g_buf2[(size_t)MPAD * H1];
__device__ float g_ss[N_NODES];
__device__ float g_sd[N_NODES];
__device__ int   g_src[NE];
__device__ int   g_dst[NE];
__device__ int   g_csr_src[NE];
__device__ int   g_deg[N_NODES];
__device__ int   g_rowoff[N_NODES + 1];
__device__ int   g_cursor[N_NODES];
__device__ int   g_is64;

// ==================== PTX helpers (base-arch only) ====================
__device__ __forceinline__ uint32_t smem_u32(const void* p) {
    uint32_t a;
    asm("{ .reg .u64 t; cvta.to.shared.u64 t, %1; cvt.u32.u64 %0, t; }" : "=r"(a) : "l"(p));
    return a;
}
__device__ __forceinline__ void cp16(uint32_t dst, const void* src) {
    asm volatile("cp.async.cg.shared.global [%0], [%1], 16;" :: "r"(dst), "l"(src));
}
__device__ __forceinline__ void ldm_x4(uint32_t& r0, uint32_t& r1, uint32_t& r2, uint32_t& r3,
                                       uint32_t addr) {
    asm volatile("ldmatrix.sync.aligned.m8n8.x4.shared.b16 {%0,%1,%2,%3}, [%4];"
                 : "=r"(r0), "=r"(r1), "=r"(r2), "=r"(r3) : "r"(addr));
}
__device__ __forceinline__ void mma_bf16(float* c, const uint32_t* a, const uint32_t* b) {
    asm volatile("mma.sync.aligned.m16n8k16.row.col.f32.bf16.bf16.f32 "
                 "{%0,%1,%2,%3}, {%4,%5,%6,%7}, {%8,%9}, {%0,%1,%2,%3};"
                 : "+f"(c[0]), "+f"(c[1]), "+f"(c[2]), "+f"(c[3])
                 : "r"(a[0]), "r"(a[1]), "r"(a[2]), "r"(a[3]), "r"(b[0]), "r"(b[1]));
}

// ==================== edge prep + CSR build ====================
__global__ void detect_kernel(const unsigned int* __restrict__ w) {
    __shared__ int nz;
    if (threadIdx.x == 0) nz = 0;
    __syncthreads();
    if (w[threadIdx.x * 2 + 1] != 0u) atomicOr(&nz, 1);
    __syncthreads();
    if (threadIdx.x == 0) g_is64 = (nz == 0);
}

__global__ void zero_deg_kernel() {
    int i = blockIdx.x * blockDim.x + threadIdx.x;
    if (i < N_NODES) g_deg[i] = 0;
}

__global__ void prep_edges_kernel(const void* __restrict__ ei) {
    int i = blockIdx.x * blockDim.x + threadIdx.x;
    if (i >= NE) return;
    int s, d;
    if (i < E0) {
        if (g_is64) {
            const long long* e = (const long long*)ei;
            s = (int)e[i]; d = (int)e[E0 + i];
        } else {
            const int* e = (const int*)ei;
            s = e[i]; d = e[E0 + i];
        }
    } else {
        s = d = i - E0;
    }
    s = min(max(s, 0), N_NODES - 1);
    d = min(max(d, 0), N_NODES - 1);
    g_src[i] = s;
    g_dst[i] = d;
    atomicAdd(&g_deg[d], 1);
}

// single-block exclusive scan of g_deg -> g_rowoff, g_cursor
__global__ void scan_kernel() {
    __shared__ int sums[1024];
    const int CH = (N_NODES + 1023) / 1024;
    int t = threadIdx.x;
    int base = t * CH;
    int s = 0;
    for (int i = 0; i < CH; i++) {
        int idx = base + i;
        if (idx < N_NODES) s += g_deg[idx];
    }
    sums[t] = s;
    __syncthreads();
    for (int off = 1; off < 1024; off <<= 1) {
        int v = (t >= off) ? sums[t - off] : 0;
        __syncthreads();
        sums[t] += v;
        __syncthreads();
    }
    int run = (t == 0) ? 0 : sums[t - 1];
    for (int i = 0; i < CH; i++) {
        int idx = base + i;
        if (idx < N_NODES) {
            g_rowoff[idx] = run;
            g_cursor[idx] = run;
            run += g_deg[idx];
        }
    }
    if (t == 1023) g_rowoff[N_NODES] = NE;
}

__global__ void scatter_kernel() {
    int i = blockIdx.x * blockDim.x + threadIdx.x;
    if (i >= NE) return;
    int pos = atomicAdd(&g_cursor[g_dst[i]], 1);
    g_csr_src[pos] = g_src[i];
}

// ==================== precision-split conversion ====================
__global__ void split_A_kernel(const float* __restrict__ A, int M, int K, int Kpad,
                               __nv_bfloat16* __restrict__ hi, __nv_bfloat16* __restrict__ lo) {
    size_t total = (size_t)MPAD * Kpad;
    size_t i = (size_t)blockIdx.x * blockDim.x + threadIdx.x;
    size_t stride = (size_t)gridDim.x * blockDim.x;
    for (; i < total; i += stride) {
        int r = (int)(i / Kpad), c = (int)(i % Kpad);
        float v = (r < M && c < K) ? A[(size_t)r * K + c] : 0.0f;
        __nv_bfloat16 h = __float2bfloat16(v);
        hi[i] = h;
        lo[i] = __float2bfloat16(v - __bfloat162float(h));
    }
}

__global__ void split_Wt_kernel(const float* __restrict__ W, int K, int N, int Kpad,
                                __nv_bfloat16* __restrict__ hi, __nv_bfloat16* __restrict__ lo) {
    size_t total = (size_t)N * Kpad;
    size_t i = (size_t)blockIdx.x * blockDim.x + threadIdx.x;
    size_t stride = (size_t)gridDim.x * blockDim.x;
    for (; i < total; i += stride) {
        int n = (int)(i / Kpad), k = (int)(i % Kpad);
        float v = (k < K) ? W[(size_t)k * N + n] : 0.0f;
        __nv_bfloat16 h = __float2bfloat16(v);
        hi[i] = h;
        lo[i] = __float2bfloat16(v - __bfloat162float(h));
    }
}

// ==================== mma.sync bf16x3 GEMM ====================
#define KC        32
#define SPITCH    80
#define ARR_BYTES (128 * SPITCH)
#define STG_BYTES (4 * ARR_BYTES)
#define OFF_AHI   0
#define OFF_ALO   ARR_BYTES
#define OFF_BHI   (2 * ARR_BYTES)
#define OFF_BLO   (3 * ARR_BYTES)
#define SMEM_DYN  (2 * STG_BYTES)

__global__ void __launch_bounds__(256)
gemm_tc_kernel(const __nv_bfloat16* __restrict__ Ahi, const __nv_bfloat16* __restrict__ Alo,
               const __nv_bfloat16* __restrict__ Bhi, const __nv_bfloat16* __restrict__ Blo,
               float* __restrict__ C, int Kpad, int Nc) {
    extern __shared__ char smem[];
    const uint32_t sb = smem_u32(smem);
    const int tid = threadIdx.x;
    const int wid = tid >> 5, lane = tid & 31;
    const int warp_m = wid & 3, warp_n = wid >> 2;
    const int m0 = blockIdx.y * 128;
    const int n0 = blockIdx.x * 128;
    const int nchunks = Kpad / KC;

    const int row0 = tid >> 2, seg = tid & 3;
    const int row1 = row0 + 64;
    const uint32_t s0 = (uint32_t)row0 * SPITCH + seg * 16;
    const uint32_t s1 = (uint32_t)row1 * SPITCH + seg * 16;
    const size_t gA0 = (size_t)(m0 + row0) * Kpad + seg * 8;
    const size_t gA1 = (size_t)(m0 + row1) * Kpad + seg * 8;
    const size_t gB0 = (size_t)(n0 + row0) * Kpad + seg * 8;
    const size_t gB1 = (size_t)(n0 + row1) * Kpad + seg * 8;

    const int lr = lane & 7, g = lane >> 3;
    const uint32_t offA = (uint32_t)(warp_m * 32 + lr + (g & 1) * 8) * SPITCH + (g >> 1) * 16;
    const uint32_t offB = (uint32_t)(warp_n * 64 + lr + (g >> 1) * 8) * SPITCH + (g & 1) * 16;

    float acc[2][8][4];
    #pragma unroll
    for (int mi = 0; mi < 2; mi++)
        #pragma unroll
        for (int ni = 0; ni < 8; ni++)
            #pragma unroll
            for (int q = 0; q < 4; q++) acc[mi][ni][q] = 0.0f;

    {
        const uint32_t d = sb;
        cp16(d + OFF_AHI + s0, Ahi + gA0); cp16(d + OFF_AHI + s1, Ahi + gA1);
        cp16(d + OFF_ALO + s0, Alo + gA0); cp16(d + OFF_ALO + s1, Alo + gA1);
        cp16(d + OFF_BHI + s0, Bhi + gB0); cp16(d + OFF_BHI + s1, Bhi + gB1);
        cp16(d + OFF_BLO + s0, Blo + gB0); cp16(d + OFF_BLO + s1, Blo + gB1);
        asm volatile("cp.async.commit_group;");
    }

    for (int c = 0; c < nchunks; c++) {
        if (c + 1 < nchunks) {
            const uint32_t d = sb + ((c + 1) & 1) * STG_BYTES;
            const size_t ko = (size_t)(c + 1) * KC;
            cp16(d + OFF_AHI + s0, Ahi + gA0 + ko); cp16(d + OFF_AHI + s1, Ahi + gA1 + ko);
            cp16(d + OFF_ALO + s0, Alo + gA0 + ko); cp16(d + OFF_ALO + s1, Alo + gA1 + ko);
            cp16(d + OFF_BHI + s0, Bhi + gB0 + ko); cp16(d + OFF_BHI + s1, Bhi + gB1 + ko);
            cp16(d + OFF_BLO + s0, Blo + gB0 + ko); cp16(d + OFF_BLO + s1, Blo + gB1 + ko);
            asm volatile("cp.async.commit_group;");
            asm volatile("cp.async.wait_group 1;");
        } else {
            asm volatile("cp.async.wait_group 0;");
        }
        __syncthreads();

        const uint32_t base = sb + (c & 1) * STG_BYTES;
        #pragma unroll
        for (int ks = 0; ks < 2; ks++) {
            const uint32_t kadd = ks * 32;
            uint32_t ahi[2][4], alo[2][4], bhi[8][2], blo[8][2];
            #pragma unroll
            for (int mt = 0; mt < 2; mt++) {
                ldm_x4(ahi[mt][0], ahi[mt][1], ahi[mt][2], ahi[mt][3],
                       base + OFF_AHI + offA + mt * 16 * SPITCH + kadd);
                ldm_x4(alo[mt][0], alo[mt][1], alo[mt][2], alo[mt][3],
                       base + OFF_ALO + offA + mt * 16 * SPITCH + kadd);
            }
            #pragma unroll
            for (int np = 0; np < 4; np++) {
                ldm_x4(bhi[2*np][0], bhi[2*np][1], bhi[2*np+1][0], bhi[2*np+1][1],
                       base + OFF_BHI + offB + np * 16 * SPITCH + kadd);
                ldm_x4(blo[2*np][0], blo[2*np][1], blo[2*np+1][0], blo[2*np+1][1],
                       base + OFF_BLO + offB + np * 16 * SPITCH + kadd);
            }
            #pragma unroll
            for (int mi = 0; mi < 2; mi++)
                #pragma unroll
                for (int ni = 0; ni < 8; ni++) {
                    mma_bf16(acc[mi][ni], ahi[mi], bhi[ni]);
                    mma_bf16(acc[mi][ni], ahi[mi], blo[ni]);
                    mma_bf16(acc[mi][ni], alo[mi], bhi[ni]);
                }
        }
        __syncthreads();
    }

    const int er = lane >> 2, ec = (lane & 3) * 2;
    #pragma unroll
    for (int mi = 0; mi < 2; mi++) {
        const int r_lo = m0 + warp_m * 32 + mi * 16 + er;
        #pragma unroll
        for (int ni = 0; ni < 8; ni++) {
            const int cc = n0 + warp_n * 64 + ni * 8 + ec;
            *(float2*)(C + (size_t)r_lo * Nc + cc)       = make_float2(acc[mi][ni][0], acc[mi][ni][1]);
            *(float2*)(C + (size_t)(r_lo + 8) * Nc + cc) = make_float2(acc[mi][ni][2], acc[mi][ni][3]);
        }
    }
}

// ==================== attention scores ====================
__global__ void s_kernel(const float* __restrict__ h, const float* __restrict__ a_s,
                         const float* __restrict__ a_d, int F) {
    int node = blockIdx.x * (blockDim.x >> 5) + (threadIdx.x >> 5);
    int lane = threadIdx.x & 31;
    if (node >= N_NODES) return;
    const float* hr = h + (size_t)node * F;
    float vs = 0.0f, vd = 0.0f;
    for (int f = lane; f < F; f += 32) {
        float x = hr[f];
        vs += x * a_s[f];
        vd += x * a_d[f];
    }
    #pragma unroll
    for (int o = 16; o > 0; o >>= 1) {
        vs += __shfl_down_sync(0xffffffffu, vs, o);
        vd += __shfl_down_sync(0xffffffffu, vd, o);
    }
    if (lane == 0) {
        g_ss[node] = vs;
        g_sd[node] = vd;
    }
}

// ==================== fused GAT aggregation (warp per node) ====================
// out[node] = relu?( (sum_e ee_e * h[src_e]) / den + bias )
template <int F, int DO_RELU>
__global__ void __launch_bounds__(256)
gat_agg_kernel(const float* __restrict__ h, const float* __restrict__ bias,
               float* __restrict__ out) {
    int node = blockIdx.x * 8 + (threadIdx.x >> 5);
    int lane = threadIdx.x & 31;
    if (node >= N_NODES) return;
    const int beg = g_rowoff[node], end = g_rowoff[node + 1];
    const float sd = g_sd[node];

    // pass 1: max over incoming edges (lane-strided)
    float m = -INFINITY;
    for (int i = beg + lane; i < end; i += 32) {
        float e = g_ss[g_csr_src[i]] + sd;
        e = e > 0.0f ? e : 0.2f * e;
        m = fmaxf(m, e);
    }
    #pragma unroll
    for (int o = 16; o > 0; o >>= 1) m = fmaxf(m, __shfl_xor_sync(0xffffffffu, m, o));

    // pass 2: weighted row accumulation (edges serial, cols lane-parallel)
    constexpr int R = F / 32;
    float acc[R];
    #pragma unroll
    for (int j = 0; j < R; j++) acc[j] = 0.0f;
    float den = 0.0f;
    for (int i = beg; i < end; i++) {
        int s = g_csr_src[i];                      // broadcast load
        float e = g_ss[s] + sd;                    // broadcast load
        e = e > 0.0f ? e : 0.2f * e;
        float ee = __expf(e - m);
        den += ee;
        const float* hr = h + (size_t)s * F;
        #pragma unroll
        for (int j = 0; j < R; j++) acc[j] += ee * hr[j * 32 + lane];
    }
    float inv = 1.0f / den;
    float* o = out + (size_t)node * F;
    #pragma unroll
    for (int j = 0; j < R; j++) {
        float v = acc[j] * inv + bias[j * 32 + lane];
        if (DO_RELU) v = fmaxf(v, 0.0f);
        o[j * 32 + lane] = v;
    }
}

// ==================== layer 3: skinny GEMM + fused agg+logsoftmax ====================
__global__ void gemm3_kernel(const float* __restrict__ A, const float* __restrict__ W,
                             float* __restrict__ C) {
    int i = blockIdx.x * blockDim.x + threadIdx.x;
    if (i >= N_NODES) return;
    const float* a = A + (size_t)i * H2;
    float acc[NC] = {0,0,0,0,0,0,0};
    for (int k = 0; k < H2; k++) {
        float av = a[k];
        const float* wr = W + k * NC;
        #pragma unroll
        for (int c = 0; c < NC; c++) acc[c] += av * wr[c];
    }
    #pragma unroll
    for (int c = 0; c < NC; c++) C[(size_t)i * NC + c] = acc[c];
}

__global__ void __launch_bounds__(256)
gat_agg3_final_kernel(const float* __restrict__ h, const float* __restrict__ bias,
                      float* __restrict__ out) {
    int node = blockIdx.x * 8 + (threadIdx.x >> 5);
    int lane = threadIdx.x & 31;
    if (node >= N_NODES) return;
    const int beg = g_rowoff[node], end = g_rowoff[node + 1];
    const float sd = g_sd[node];

    float m = -INFINITY;
    for (int i = beg + lane; i < end; i += 32) {
        float e = g_ss[g_csr_src[i]] + sd;
        e = e > 0.0f ? e : 0.2f * e;
        m = fmaxf(m, e);
    }
    #pragma unroll
    for (int o = 16; o > 0; o >>= 1) m = fmaxf(m, __shfl_xor_sync(0xffffffffu, m, o));

    float acc[NC] = {0,0,0,0,0,0,0};
    float den = 0.0f;
    for (int i = beg + lane; i < end; i += 32) {
        int s = g_csr_src[i];
        float e = g_ss[s] + sd;
        e = e > 0.0f ? e : 0.2f * e;
        float ee = __expf(e - m);
        den += ee;
        const float* hr = h + (size_t)s * NC;
        #pragma unroll
        for (int c = 0; c < NC; c++) acc[c] += ee * hr[c];
    }
    #pragma unroll
    for (int o = 16; o > 0; o >>= 1) {
        den += __shfl_xor_sync(0xffffffffu, den, o);
        #pragma unroll
        for (int c = 0; c < NC; c++) acc[c] += __shfl_xor_sync(0xffffffffu, acc[c], o);
    }
    if (lane == 0) {
        float inv = 1.0f / den;
        float z[NC], mx = -INFINITY;
        #pragma unroll
        for (int c = 0; c < NC; c++) {
            z[c] = acc[c] * inv + bias[c];
            mx = fmaxf(mx, z[c]);
        }
        float ssum = 0.0f;
        #pragma unroll
        for (int c = 0; c < NC; c++) ssum += __expf(z[c] - mx);
        float l = logf(ssum);
        float* o = out + (size_t)node * NC;
        #pragma unroll
        for (int c = 0; c < NC; c++) o[c] = z[c] - mx - l;
    }
}

// ==================== launcher ====================
extern "C" void kernel_launch(void* const* d_in, const int* in_sizes, int n_in,
                              void* d_out, int out_size) {
    const float* x   = (const float*)d_in[0];
    const void*  ei  = d_in[1];
    const float* W1  = (const float*)d_in[2];
    const float* as1 = (const float*)d_in[3];
    const float* ad1 = (const float*)d_in[4];
    const float* b1  = (const float*)d_in[5];
    const float* W2  = (const float*)d_in[6];
    const float* as2 = (const float*)d_in[7];
    const float* ad2 = (const float*)d_in[8];
    const float* b2  = (const float*)d_in[9];
    const float* W3  = (const float*)d_in[10];
    const float* as3 = (const float*)d_in[11];
    const float* ad3 = (const float*)d_in[12];
    const float* b3  = (const float*)d_in[13];
    float* out = (float*)d_out;

    float *buf1, *buf2;
    __nv_bfloat16 *ahi, *alo, *bhi, *blo;
    cudaGetSymbolAddress((void**)&buf1, g_buf1);
    cudaGetSymbolAddress((void**)&buf2, g_buf2);
    cudaGetSymbolAddress((void**)&ahi, g_Ahi);
    cudaGetSymbolAddress((void**)&alo, g_Alo);
    cudaGetSymbolAddress((void**)&bhi, g_Bhi);
    cudaGetSymbolAddress((void**)&blo, g_Blo);

    cudaFuncSetAttribute(gemm_tc_kernel, cudaFuncAttributeMaxDynamicSharedMemorySize, SMEM_DYN);

    const int BT = 256;
    const int edge_blocks      = (NE + BT - 1) / BT;
    const int node_warp_blocks = (N_NODES + (BT / 32) - 1) / (BT / 32);
    const int node_blocks      = (N_NODES + BT - 1) / BT;

    // ---- CSR build ----
    detect_kernel<<<1, 128>>>((const unsigned int*)ei);
    zero_deg_kernel<<<node_blocks, BT>>>();
    prep_edges_kernel<<<edge_blocks, BT>>>(ei);
    scan_kernel<<<1, 1024>>>();
    scatter_kernel<<<edge_blocks, BT>>>();

    // ---------------- layer 1: F_IN -> H1 ----------------
    split_A_kernel<<<4096, BT>>>(x, N_NODES, F_IN, K1PAD, ahi, alo);
    split_Wt_kernel<<<2048, BT>>>(W1, F_IN, H1, K1PAD, bhi, blo);
    gemm_tc_kernel<<<dim3(H1 / 128, MPAD / 128), BT, SMEM_DYN>>>(ahi, alo, bhi, blo, buf1, K1PAD, H1);
    s_kernel<<<node_warp_blocks, BT>>>(buf1, as1, ad1, H1);
    gat_agg_kernel<H1, 1><<<node_warp_blocks, BT>>>(buf1, b1, buf2);

    // ---------------- layer 2: H1 -> H2 ----------------
    split_A_kernel<<<4096, BT>>>(buf2, N_NODES, H1, H1, ahi, alo);
    split_Wt_kernel<<<2048, BT>>>(W2, H1, H2, H1, bhi, blo);
    gemm_tc_kernel<<<dim3(H2 / 128, MPAD / 128), BT, SMEM_DYN>>>(ahi, alo, bhi, blo, buf1, H1, H2);
    s_kernel<<<node_warp_blocks, BT>>>(buf1, as2, ad2, H2);
    gat_agg_kernel<H2, 1><<<node_warp_blocks, BT>>>(buf1, b2, buf2);

    // ---------------- layer 3: H2 -> NC ----------------
    gemm3_kernel<<<node_blocks, BT>>>(buf2, W3, buf1);
    s_kernel<<<node_warp_blocks, BT>>>(buf1, as3, ad3, NC);
    gat_agg3_final_kernel<<<node_warp_blocks, BT>>>(buf1, b3, out);
}

// round 9
// speedup vs baseline: 2.1144x; 1.1093x over previous
#include <cuda_runtime.h>
#include <cuda_bf16.h>
#include <math.h>
#include <stdint.h>

#define N_NODES 50000
#define MPAD    50048   // 391 * 128
#define E0      800000
#define NE      850000
#define F_IN    1433
#define K1PAD   1472    // 46 * 32
#define H1      512
#define H2      256
#define NC      7
#define NB      196     // ceil(N_NODES / 256)

// ==================== scratch (device globals) ====================
__device__ __nv_bfloat16 g_Ahi[(size_t)MPAD * K1PAD];
__device__ __nv_bfloat16 g_Alo[(size_t)MPAD * K1PAD];
__device__ __nv_bfloat16 g_Bhi[(size_t)H1 * K1PAD];
__device__ __nv_bfloat16 g_Blo[(size_t)H1 * K1PAD];
__device__ float g_buf1[(size_t)MPAD * H1];
__device__ float g_buf2[(size_t)MPAD * H1];
__device__ float g_ss[N_NODES];
__device__ float g_sd[N_NODES];
__device__ int   g_src[NE];
__device__ int   g_dst[NE];
__device__ int   g_csr_src[NE];
__device__ int   g_deg[N_NODES];
__device__ int   g_rowoff[N_NODES + 1];
__device__ int   g_cursor[N_NODES];
__device__ int   g_bsum[NB];
__device__ int   g_boff[NB];
__device__ int   g_is64;

// ==================== PTX helpers (base-arch only) ====================
__device__ __forceinline__ uint32_t smem_u32(const void* p) {
    uint32_t a;
    asm("{ .reg .u64 t; cvta.to.shared.u64 t, %1; cvt.u32.u64 %0, t; }" : "=r"(a) : "l"(p));
    return a;
}
__device__ __forceinline__ void cp16(uint32_t dst, const void* src) {
    asm volatile("cp.async.cg.shared.global [%0], [%1], 16;" :: "r"(dst), "l"(src));
}
__device__ __forceinline__ void ldm_x4(uint32_t& r0, uint32_t& r1, uint32_t& r2, uint32_t& r3,
                                       uint32_t addr) {
    asm volatile("ldmatrix.sync.aligned.m8n8.x4.shared.b16 {%0,%1,%2,%3}, [%4];"
                 : "=r"(r0), "=r"(r1), "=r"(r2), "=r"(r3) : "r"(addr));
}
__device__ __forceinline__ void mma_bf16(float* c, const uint32_t* a, const uint32_t* b) {
    asm volatile("mma.sync.aligned.m16n8k16.row.col.f32.bf16.bf16.f32 "
                 "{%0,%1,%2,%3}, {%4,%5,%6,%7}, {%8,%9}, {%0,%1,%2,%3};"
                 : "+f"(c[0]), "+f"(c[1]), "+f"(c[2]), "+f"(c[3])
                 : "r"(a[0]), "r"(a[1]), "r"(a[2]), "r"(a[3]), "r"(b[0]), "r"(b[1]));
}

// ==================== edge prep + CSR build ====================
__global__ void detect_kernel(const unsigned int* __restrict__ w) {
    __shared__ int nz;
    if (threadIdx.x == 0) nz = 0;
    __syncthreads();
    if (w[threadIdx.x * 2 + 1] != 0u) atomicOr(&nz, 1);
    __syncthreads();
    if (threadIdx.x == 0) g_is64 = (nz == 0);
}

__global__ void zero_deg_kernel() {
    int i = blockIdx.x * blockDim.x + threadIdx.x;
    if (i < N_NODES) g_deg[i] = 0;
}

__global__ void prep_edges_kernel(const void* __restrict__ ei) {
    int i = blockIdx.x * blockDim.x + threadIdx.x;
    if (i >= NE) return;
    int s, d;
    if (i < E0) {
        if (g_is64) {
            const long long* e = (const long long*)ei;
            s = (int)e[i]; d = (int)e[E0 + i];
        } else {
            const int* e = (const int*)ei;
            s = e[i]; d = e[E0 + i];
        }
    } else {
        s = d = i - E0;
    }
    s = min(max(s, 0), N_NODES - 1);
    d = min(max(d, 0), N_NODES - 1);
    g_src[i] = s;
    g_dst[i] = d;
    atomicAdd(&g_deg[d], 1);
}

// ---- parallel exclusive scan of g_deg (3 small kernels) ----
__global__ void reduce_deg_kernel() {          // grid NB, 256
    __shared__ int sh[256];
    int i = blockIdx.x * 256 + threadIdx.x;
    sh[threadIdx.x] = (i < N_NODES) ? g_deg[i] : 0;
    __syncthreads();
    for (int o = 128; o > 0; o >>= 1) {
        if (threadIdx.x < o) sh[threadIdx.x] += sh[threadIdx.x + o];
        __syncthreads();
    }
    if (threadIdx.x == 0) g_bsum[blockIdx.x] = sh[0];
}

__global__ void scan_bsums_kernel() {          // 1 block, 256
    __shared__ int sh[256];
    int t = threadIdx.x;
    int mine = (t < NB) ? g_bsum[t] : 0;
    sh[t] = mine;
    __syncthreads();
    for (int o = 1; o < 256; o <<= 1) {
        int v = (t >= o) ? sh[t - o] : 0;
        __syncthreads();
        sh[t] += v;
        __syncthreads();
    }
    if (t < NB) g_boff[t] = sh[t] - mine;      // exclusive
    if (t == 0) g_rowoff[N_NODES] = NE;
}

__global__ void scan_write_kernel() {          // grid NB, 256
    __shared__ int sh[256];
    int i = blockIdx.x * 256 + threadIdx.x;
    int v = (i < N_NODES) ? g_deg[i] : 0;
    sh[threadIdx.x] = v;
    __syncthreads();
    for (int o = 1; o < 256; o <<= 1) {
        int u = (threadIdx.x >= o) ? sh[threadIdx.x - o] : 0;
        __syncthreads();
        sh[threadIdx.x] += u;
        __syncthreads();
    }
    if (i < N_NODES) {
        int excl = g_boff[blockIdx.x] + sh[threadIdx.x] - v;
        g_rowoff[i] = excl;
        g_cursor[i] = excl;
    }
}

__global__ void scatter_kernel() {
    int i = blockIdx.x * blockDim.x + threadIdx.x;
    if (i >= NE) return;
    int pos = atomicAdd(&g_cursor[g_dst[i]], 1);
    g_csr_src[pos] = g_src[i];
}

// ==================== precision-split conversion ====================
__global__ void split_A_kernel(const float* __restrict__ A, int M, int K, int Kpad,
                               __nv_bfloat16* __restrict__ hi, __nv_bfloat16* __restrict__ lo) {
    size_t total = (size_t)MPAD * Kpad;
    size_t i = (size_t)blockIdx.x * blockDim.x + threadIdx.x;
    size_t stride = (size_t)gridDim.x * blockDim.x;
    for (; i < total; i += stride) {
        int r = (int)(i / Kpad), c = (int)(i % Kpad);
        float v = (r < M && c < K) ? A[(size_t)r * K + c] : 0.0f;
        __nv_bfloat16 h = __float2bfloat16(v);
        hi[i] = h;
        lo[i] = __float2bfloat16(v - __bfloat162float(h));
    }
}

__global__ void split_Wt_kernel(const float* __restrict__ W, int K, int N, int Kpad,
                                __nv_bfloat16* __restrict__ hi, __nv_bfloat16* __restrict__ lo) {
    size_t total = (size_t)N * Kpad;
    size_t i = (size_t)blockIdx.x * blockDim.x + threadIdx.x;
    size_t stride = (size_t)gridDim.x * blockDim.x;
    for (; i < total; i += stride) {
        int n = (int)(i / Kpad), k = (int)(i % Kpad);
        float v = (k < K) ? W[(size_t)k * N + n] : 0.0f;
        __nv_bfloat16 h = __float2bfloat16(v);
        hi[i] = h;
        lo[i] = __float2bfloat16(v - __bfloat162float(h));
    }
}

// ==================== mma.sync bf16x3 GEMM ====================
#define KC        32
#define SPITCH    80
#define ARR_BYTES (128 * SPITCH)
#define STG_BYTES (4 * ARR_BYTES)
#define OFF_AHI   0
#define OFF_ALO   ARR_BYTES
#define OFF_BHI   (2 * ARR_BYTES)
#define OFF_BLO   (3 * ARR_BYTES)
#define SMEM_DYN  (2 * STG_BYTES)

__global__ void __launch_bounds__(256)
gemm_tc_kernel(const __nv_bfloat16* __restrict__ Ahi, const __nv_bfloat16* __restrict__ Alo,
               const __nv_bfloat16* __restrict__ Bhi, const __nv_bfloat16* __restrict__ Blo,
               float* __restrict__ C, int Kpad, int Nc) {
    extern __shared__ char smem[];
    const uint32_t sb = smem_u32(smem);
    const int tid = threadIdx.x;
    const int wid = tid >> 5, lane = tid & 31;
    const int warp_m = wid & 3, warp_n = wid >> 2;
    const int m0 = blockIdx.y * 128;
    const int n0 = blockIdx.x * 128;
    const int nchunks = Kpad / KC;

    const int row0 = tid >> 2, seg = tid & 3;
    const int row1 = row0 + 64;
    const uint32_t s0 = (uint32_t)row0 * SPITCH + seg * 16;
    const uint32_t s1 = (uint32_t)row1 * SPITCH + seg * 16;
    const size_t gA0 = (size_t)(m0 + row0) * Kpad + seg * 8;
    const size_t gA1 = (size_t)(m0 + row1) * Kpad + seg * 8;
    const size_t gB0 = (size_t)(n0 + row0) * Kpad + seg * 8;
    const size_t gB1 = (size_t)(n0 + row1) * Kpad + seg * 8;

    const int lr = lane & 7, g = lane >> 3;
    const uint32_t offA = (uint32_t)(warp_m * 32 + lr + (g & 1) * 8) * SPITCH + (g >> 1) * 16;
    const uint32_t offB = (uint32_t)(warp_n * 64 + lr + (g >> 1) * 8) * SPITCH + (g & 1) * 16;

    float acc[2][8][4];
    #pragma unroll
    for (int mi = 0; mi < 2; mi++)
        #pragma unroll
        for (int ni = 0; ni < 8; ni++)
            #pragma unroll
            for (int q = 0; q < 4; q++) acc[mi][ni][q] = 0.0f;

    {
        const uint32_t d = sb;
        cp16(d + OFF_AHI + s0, Ahi + gA0); cp16(d + OFF_AHI + s1, Ahi + gA1);
        cp16(d + OFF_ALO + s0, Alo + gA0); cp16(d + OFF_ALO + s1, Alo + gA1);
        cp16(d + OFF_BHI + s0, Bhi + gB0); cp16(d + OFF_BHI + s1, Bhi + gB1);
        cp16(d + OFF_BLO + s0, Blo + gB0); cp16(d + OFF_BLO + s1, Blo + gB1);
        asm volatile("cp.async.commit_group;");
    }

    for (int c = 0; c < nchunks; c++) {
        if (c + 1 < nchunks) {
            const uint32_t d = sb + ((c + 1) & 1) * STG_BYTES;
            const size_t ko = (size_t)(c + 1) * KC;
            cp16(d + OFF_AHI + s0, Ahi + gA0 + ko); cp16(d + OFF_AHI + s1, Ahi + gA1 + ko);
            cp16(d + OFF_ALO + s0, Alo + gA0 + ko); cp16(d + OFF_ALO + s1, Alo + gA1 + ko);
            cp16(d + OFF_BHI + s0, Bhi + gB0 + ko); cp16(d + OFF_BHI + s1, Bhi + gB1 + ko);
            cp16(d + OFF_BLO + s0, Blo + gB0 + ko); cp16(d + OFF_BLO + s1, Blo + gB1 + ko);
            asm volatile("cp.async.commit_group;");
            asm volatile("cp.async.wait_group 1;");
        } else {
            asm volatile("cp.async.wait_group 0;");
        }
        __syncthreads();

        const uint32_t base = sb + (c & 1) * STG_BYTES;
        #pragma unroll
        for (int ks = 0; ks < 2; ks++) {
            const uint32_t kadd = ks * 32;
            uint32_t ahi[2][4], alo[2][4], bhi[8][2], blo[8][2];
            #pragma unroll
            for (int mt = 0; mt < 2; mt++) {
                ldm_x4(ahi[mt][0], ahi[mt][1], ahi[mt][2], ahi[mt][3],
                       base + OFF_AHI + offA + mt * 16 * SPITCH + kadd);
                ldm_x4(alo[mt][0], alo[mt][1], alo[mt][2], alo[mt][3],
                       base + OFF_ALO + offA + mt * 16 * SPITCH + kadd);
            }
            #pragma unroll
            for (int np = 0; np < 4; np++) {
                ldm_x4(bhi[2*np][0], bhi[2*np][1], bhi[2*np+1][0], bhi[2*np+1][1],
                       base + OFF_BHI + offB + np * 16 * SPITCH + kadd);
                ldm_x4(blo[2*np][0], blo[2*np][1], blo[2*np+1][0], blo[2*np+1][1],
                       base + OFF_BLO + offB + np * 16 * SPITCH + kadd);
            }
            #pragma unroll
            for (int mi = 0; mi < 2; mi++)
                #pragma unroll
                for (int ni = 0; ni < 8; ni++) {
                    mma_bf16(acc[mi][ni], ahi[mi], bhi[ni]);
                    mma_bf16(acc[mi][ni], ahi[mi], blo[ni]);
                    mma_bf16(acc[mi][ni], alo[mi], bhi[ni]);
                }
        }
        __syncthreads();
    }

    const int er = lane >> 2, ec = (lane & 3) * 2;
    #pragma unroll
    for (int mi = 0; mi < 2; mi++) {
        const int r_lo = m0 + warp_m * 32 + mi * 16 + er;
        #pragma unroll
        for (int ni = 0; ni < 8; ni++) {
            const int cc = n0 + warp_n * 64 + ni * 8 + ec;
            *(float2*)(C + (size_t)r_lo * Nc + cc)       = make_float2(acc[mi][ni][0], acc[mi][ni][1]);
            *(float2*)(C + (size_t)(r_lo + 8) * Nc + cc) = make_float2(acc[mi][ni][2], acc[mi][ni][3]);
        }
    }
}

// ==================== attention scores ====================
// vectorized variant: F must be a multiple of 128 (rows 16B-aligned)
__global__ void s_kernel_vec(const float* __restrict__ h, const float* __restrict__ a_s,
                             const float* __restrict__ a_d, int F) {
    int node = blockIdx.x * (blockDim.x >> 5) + (threadIdx.x >> 5);
    int lane = threadIdx.x & 31;
    if (node >= N_NODES) return;
    const float* hr = h + (size_t)node * F;
    float vs = 0.0f, vd = 0.0f;
    for (int f = lane * 4; f < F; f += 128) {
        float4 x = *(const float4*)(hr + f);
        float4 as4 = *(const float4*)(a_s + f);
        float4 ad4 = *(const float4*)(a_d + f);
        vs += x.x * as4.x + x.y * as4.y + x.z * as4.z + x.w * as4.w;
        vd += x.x * ad4.x + x.y * ad4.y + x.z * ad4.z + x.w * ad4.w;
    }
    #pragma unroll
    for (int o = 16; o > 0; o >>= 1) {
        vs += __shfl_down_sync(0xffffffffu, vs, o);
        vd += __shfl_down_sync(0xffffffffu, vd, o);
    }
    if (lane == 0) {
        g_ss[node] = vs;
        g_sd[node] = vd;
    }
}

// scalar variant (small / unaligned F, e.g. F=7)
__global__ void s_kernel_scalar(const float* __restrict__ h, const float* __restrict__ a_s,
                                const float* __restrict__ a_d, int F) {
    int node = blockIdx.x * (blockDim.x >> 5) + (threadIdx.x >> 5);
    int lane = threadIdx.x & 31;
    if (node >= N_NODES) return;
    const float* hr = h + (size_t)node * F;
    float vs = 0.0f, vd = 0.0f;
    for (int f = lane; f < F; f += 32) {
        float x = hr[f];
        vs += x * a_s[f];
        vd += x * a_d[f];
    }
    #pragma unroll
    for (int o = 16; o > 0; o >>= 1) {
        vs += __shfl_down_sync(0xffffffffu, vs, o);
        vd += __shfl_down_sync(0xffffffffu, vd, o);
    }
    if (lane == 0) {
        g_ss[node] = vs;
        g_sd[node] = vd;
    }
}

// ==================== fused GAT aggregation (warp per node) ====================
// OUT_BF16=1: write bf16 hi/lo split (next GEMM's A operand) instead of fp32.
template <int F, int OUT_BF16>
__global__ void __launch_bounds__(256)
gat_agg_kernel(const float* __restrict__ h, const float* __restrict__ bias,
               float* __restrict__ outf,
               __nv_bfloat16* __restrict__ ohi, __nv_bfloat16* __restrict__ olo) {
    int node = blockIdx.x * 8 + (threadIdx.x >> 5);
    int lane = threadIdx.x & 31;
    if (node >= N_NODES) return;
    const int beg = g_rowoff[node], end = g_rowoff[node + 1];
    const float sd = g_sd[node];

    // pass 1: max over incoming edges
    float m = -INFINITY;
    for (int i = beg + lane; i < end; i += 32) {
        float e = g_ss[g_csr_src[i]] + sd;
        e = e > 0.0f ? e : 0.2f * e;
        m = fmaxf(m, e);
    }
    #pragma unroll
    for (int o = 16; o > 0; o >>= 1) m = fmaxf(m, __shfl_xor_sync(0xffffffffu, m, o));

    // pass 2: weighted row accumulation, edges unrolled x2, float4 lanes
    constexpr int R4 = F / 128;
    float4 acc[R4];
    #pragma unroll
    for (int j = 0; j < R4; j++) acc[j] = make_float4(0.f, 0.f, 0.f, 0.f);
    float den = 0.0f;
    const uint32_t c4 = lane * 4;

    int i = beg;
    for (; i + 1 < end; i += 2) {
        int s0 = g_csr_src[i], s1 = g_csr_src[i + 1];
        float e0 = g_ss[s0] + sd; e0 = e0 > 0.0f ? e0 : 0.2f * e0;
        float e1 = g_ss[s1] + sd; e1 = e1 > 0.0f ? e1 : 0.2f * e1;
        float ee0 = __expf(e0 - m), ee1 = __expf(e1 - m);
        den += ee0 + ee1;
        const float* h0 = h + (size_t)s0 * F + c4;
        const float* h1 = h + (size_t)s1 * F + c4;
        #pragma unroll
        for (int j = 0; j < R4; j++) {
            float4 v0 = *(const float4*)(h0 + j * 128);
            float4 v1 = *(const float4*)(h1 + j * 128);
            acc[j].x += ee0 * v0.x + ee1 * v1.x;
            acc[j].y += ee0 * v0.y + ee1 * v1.y;
            acc[j].z += ee0 * v0.z + ee1 * v1.z;
            acc[j].w += ee0 * v0.w + ee1 * v1.w;
        }
    }
    if (i < end) {
        int s0 = g_csr_src[i];
        float e0 = g_ss[s0] + sd; e0 = e0 > 0.0f ? e0 : 0.2f * e0;
        float ee0 = __expf(e0 - m);
        den += ee0;
        const float* h0 = h + (size_t)s0 * F + c4;
        #pragma unroll
        for (int j = 0; j < R4; j++) {
            float4 v0 = *(const float4*)(h0 + j * 128);
            acc[j].x += ee0 * v0.x; acc[j].y += ee0 * v0.y;
            acc[j].z += ee0 * v0.z; acc[j].w += ee0 * v0.w;
        }
    }

    float inv = 1.0f / den;
    #pragma unroll
    for (int j = 0; j < R4; j++) {
        float4 b4 = *(const float4*)(bias + j * 128 + c4);
        float v0 = fmaxf(acc[j].x * inv + b4.x, 0.0f);
        float v1 = fmaxf(acc[j].y * inv + b4.y, 0.0f);
        float v2 = fmaxf(acc[j].z * inv + b4.z, 0.0f);
        float v3 = fmaxf(acc[j].w * inv + b4.w, 0.0f);
        size_t o = (size_t)node * F + j * 128 + c4;
        if (OUT_BF16) {
            __nv_bfloat16 h0 = __float2bfloat16(v0), h1 = __float2bfloat16(v1);
            __nv_bfloat16 h2 = __float2bfloat16(v2), h3 = __float2bfloat16(v3);
            ohi[o + 0] = h0; ohi[o + 1] = h1; ohi[o + 2] = h2; ohi[o + 3] = h3;
            olo[o + 0] = __float2bfloat16(v0 - __bfloat162float(h0));
            olo[o + 1] = __float2bfloat16(v1 - __bfloat162float(h1));
            olo[o + 2] = __float2bfloat16(v2 - __bfloat162float(h2));
            olo[o + 3] = __float2bfloat16(v3 - __bfloat162float(h3));
        } else {
            *(float4*)(outf + o) = make_float4(v0, v1, v2, v3);
        }
    }
}

// ==================== layer 3: skinny GEMM + fused agg+logsoftmax ====================
__global__ void gemm3_kernel(const float* __restrict__ A, const float* __restrict__ W,
                             float* __restrict__ C) {
    int i = blockIdx.x * blockDim.x + threadIdx.x;
    if (i >= N_NODES) return;
    const float* a = A + (size_t)i * H2;
    float acc[NC] = {0,0,0,0,0,0,0};
    for (int k = 0; k < H2; k++) {
        float av = a[k];
        const float* wr = W + k * NC;
        #pragma unroll
        for (int c = 0; c < NC; c++) acc[c] += av * wr[c];
    }
    #pragma unroll
    for (int c = 0; c < NC; c++) C[(size_t)i * NC + c] = acc[c];
}

__global__ void __launch_bounds__(256)
gat_agg3_final_kernel(const float* __restrict__ h, const float* __restrict__ bias,
                      float* __restrict__ out) {
    int node = blockIdx.x * 8 + (threadIdx.x >> 5);
    int lane = threadIdx.x & 31;
    if (node >= N_NODES) return;
    const int beg = g_rowoff[node], end = g_rowoff[node + 1];
    const float sd = g_sd[node];

    float m = -INFINITY;
    for (int i = beg + lane; i < end; i += 32) {
        float e = g_ss[g_csr_src[i]] + sd;
        e = e > 0.0f ? e : 0.2f * e;
        m = fmaxf(m, e);
    }
    #pragma unroll
    for (int o = 16; o > 0; o >>= 1) m = fmaxf(m, __shfl_xor_sync(0xffffffffu, m, o));

    float acc[NC] = {0,0,0,0,0,0,0};
    float den = 0.0f;
    for (int i = beg + lane; i < end; i += 32) {
        int s = g_csr_src[i];
        float e = g_ss[s] + sd;
        e = e > 0.0f ? e : 0.2f * e;
        float ee = __expf(e - m);
        den += ee;
        const float* hr = h + (size_t)s * NC;
        #pragma unroll
        for (int c = 0; c < NC; c++) acc[c] += ee * hr[c];
    }
    #pragma unroll
    for (int o = 16; o > 0; o >>= 1) {
        den += __shfl_xor_sync(0xffffffffu, den, o);
        #pragma unroll
        for (int c = 0; c < NC; c++) acc[c] += __shfl_xor_sync(0xffffffffu, acc[c], o);
    }
    if (lane == 0) {
        float inv = 1.0f / den;
        float z[NC], mx = -INFINITY;
        #pragma unroll
        for (int c = 0; c < NC; c++) {
            z[c] = acc[c] * inv + bias[c];
            mx = fmaxf(mx, z[c]);
        }
        float ssum = 0.0f;
        #pragma unroll
        for (int c = 0; c < NC; c++) ssum += __expf(z[c] - mx);
        float l = logf(ssum);
        float* o = out + (size_t)node * NC;
        #pragma unroll
        for (int c = 0; c < NC; c++) o[c] = z[c] - mx - l;
    }
}

// ==================== launcher ====================
extern "C" void kernel_launch(void* const* d_in, const int* in_sizes, int n_in,
                              void* d_out, int out_size) {
    const float* x   = (const float*)d_in[0];
    const void*  ei  = d_in[1];
    const float* W1  = (const float*)d_in[2];
    const float* as1 = (const float*)d_in[3];
    const float* ad1 = (const float*)d_in[4];
    const float* b1  = (const float*)d_in[5];
    const float* W2  = (const float*)d_in[6];
    const float* as2 = (const float*)d_in[7];
    const float* ad2 = (const float*)d_in[8];
    const float* b2  = (const float*)d_in[9];
    const float* W3  = (const float*)d_in[10];
    const float* as3 = (const float*)d_in[11];
    const float* ad3 = (const float*)d_in[12];
    const float* b3  = (const float*)d_in[13];
    float* out = (float*)d_out;

    float *buf1, *buf2;
    __nv_bfloat16 *ahi, *alo, *bhi, *blo;
    cudaGetSymbolAddress((void**)&buf1, g_buf1);
    cudaGetSymbolAddress((void**)&buf2, g_buf2);
    cudaGetSymbolAddress((void**)&ahi, g_Ahi);
    cudaGetSymbolAddress((void**)&alo, g_Alo);
    cudaGetSymbolAddress((void**)&bhi, g_Bhi);
    cudaGetSymbolAddress((void**)&blo, g_Blo);

    cudaFuncSetAttribute(gemm_tc_kernel, cudaFuncAttributeMaxDynamicSharedMemorySize, SMEM_DYN);

    const int BT = 256;
    const int edge_blocks      = (NE + BT - 1) / BT;
    const int node_warp_blocks = (N_NODES + (BT / 32) - 1) / (BT / 32);
    const int node_blocks      = (N_NODES + BT - 1) / BT;

    // ---- CSR build ----
    detect_kernel<<<1, 128>>>((const unsigned int*)ei);
    zero_deg_kernel<<<node_blocks, BT>>>();
    prep_edges_kernel<<<edge_blocks, BT>>>(ei);
    reduce_deg_kernel<<<NB, 256>>>();
    scan_bsums_kernel<<<1, 256>>>();
    scan_write_kernel<<<NB, 256>>>();
    scatter_kernel<<<edge_blocks, BT>>>();

    // ---------------- layer 1: F_IN -> H1 ----------------
    split_A_kernel<<<4096, BT>>>(x, N_NODES, F_IN, K1PAD, ahi, alo);
    split_Wt_kernel<<<2048, BT>>>(W1, F_IN, H1, K1PAD, bhi, blo);
    gemm_tc_kernel<<<dim3(H1 / 128, MPAD / 128), BT, SMEM_DYN>>>(ahi, alo, bhi, blo, buf1, K1PAD, H1);
    s_kernel_vec<<<node_warp_blocks, BT>>>(buf1, as1, ad1, H1);
    // writes bf16 hi/lo directly (layer-2 GEMM A operand); no fp32 intermediate
    gat_agg_kernel<H1, 1><<<node_warp_blocks, BT>>>(buf1, b1, nullptr, ahi, alo);

    // ---------------- layer 2: H1 -> H2 ----------------
    split_Wt_kernel<<<2048, BT>>>(W2, H1, H2, H1, bhi, blo);
    gemm_tc_kernel<<<dim3(H2 / 128, MPAD / 128), BT, SMEM_DYN>>>(ahi, alo, bhi, blo, buf1, H1, H2);
    s_kernel_vec<<<node_warp_blocks, BT>>>(buf1, as2, ad2, H2);
    gat_agg_kernel<H2, 0><<<node_warp_blocks, BT>>>(buf1, b2, buf2, nullptr, nullptr);

    // ---------------- layer 3: H2 -> NC ----------------
    gemm3_kernel<<<node_blocks, BT>>>(buf2, W3, buf1);
    s_kernel_scalar<<<node_warp_blocks, BT>>>(buf1, as3, ad3, NC);
    gat_agg3_final_kernel<<<node_warp_blocks, BT>>>(buf1, b3, out);
}

// round 10
// speedup vs baseline: 2.1162x; 1.0008x over previous
#include <cuda_runtime.h>
#include <cuda_bf16.h>
#include <math.h>
#include <stdint.h>

#define N_NODES 50000
#define MPAD    50048   // 391 * 128
#define E0      800000
#define NE      850000
#define F_IN    1433
#define K1PAD   1472    // 46 * 32
#define H1      512
#define H2      256
#define NC      7
#define NB      196     // ceil(N_NODES / 256)

// ==================== scratch (device globals) ====================
__device__ __nv_bfloat16 g_Ahi[(size_t)MPAD * H1];
__device__ __nv_bfloat16 g_Alo[(size_t)MPAD * H1];
__device__ __nv_bfloat16 g_Bhi[(size_t)H1 * K1PAD];
__device__ __nv_bfloat16 g_Blo[(size_t)H1 * K1PAD];
__device__ float g_buf1[(size_t)MPAD * H1];
__device__ float g_buf2[(size_t)MPAD * H1];
__device__ float g_ss[N_NODES];
__device__ float g_sd[N_NODES];
__device__ int   g_src[NE];
__device__ int   g_dst[NE];
__device__ int   g_csr_src[NE];
__device__ int   g_deg[N_NODES];
__device__ int   g_rowoff[N_NODES + 1];
__device__ int   g_cursor[N_NODES];
__device__ int   g_bsum[NB];
__device__ int   g_boff[NB];
__device__ int   g_is64;

// ==================== PTX helpers (base-arch only) ====================
__device__ __forceinline__ uint32_t smem_u32(const void* p) {
    uint32_t a;
    asm("{ .reg .u64 t; cvta.to.shared.u64 t, %1; cvt.u32.u64 %0, t; }" : "=r"(a) : "l"(p));
    return a;
}
__device__ __forceinline__ void cp16(uint32_t dst, const void* src) {
    asm volatile("cp.async.cg.shared.global [%0], [%1], 16;" :: "r"(dst), "l"(src));
}
__device__ __forceinline__ void ldm_x4(uint32_t& r0, uint32_t& r1, uint32_t& r2, uint32_t& r3,
                                       uint32_t addr) {
    asm volatile("ldmatrix.sync.aligned.m8n8.x4.shared.b16 {%0,%1,%2,%3}, [%4];"
                 : "=r"(r0), "=r"(r1), "=r"(r2), "=r"(r3) : "r"(addr));
}
__device__ __forceinline__ void mma_bf16(float* c, const uint32_t* a, const uint32_t* b) {
    asm volatile("mma.sync.aligned.m16n8k16.row.col.f32.bf16.bf16.f32 "
                 "{%0,%1,%2,%3}, {%4,%5,%6,%7}, {%8,%9}, {%0,%1,%2,%3};"
                 : "+f"(c[0]), "+f"(c[1]), "+f"(c[2]), "+f"(c[3])
                 : "r"(a[0]), "r"(a[1]), "r"(a[2]), "r"(a[3]), "r"(b[0]), "r"(b[1]));
}

// ==================== edge prep + CSR build ====================
__global__ void detect_kernel(const unsigned int* __restrict__ w) {
    __shared__ int nz;
    if (threadIdx.x == 0) nz = 0;
    __syncthreads();
    if (w[threadIdx.x * 2 + 1] != 0u) atomicOr(&nz, 1);
    __syncthreads();
    if (threadIdx.x == 0) g_is64 = (nz == 0);
}

__global__ void zero_deg_kernel() {
    int i = blockIdx.x * blockDim.x + threadIdx.x;
    if (i < N_NODES) g_deg[i] = 0;
}

__global__ void prep_edges_kernel(const void* __restrict__ ei) {
    int i = blockIdx.x * blockDim.x + threadIdx.x;
    if (i >= NE) return;
    int s, d;
    if (i < E0) {
        if (g_is64) {
            const long long* e = (const long long*)ei;
            s = (int)e[i]; d = (int)e[E0 + i];
        } else {
            const int* e = (const int*)ei;
            s = e[i]; d = e[E0 + i];
        }
    } else {
        s = d = i - E0;
    }
    s = min(max(s, 0), N_NODES - 1);
    d = min(max(d, 0), N_NODES - 1);
    g_src[i] = s;
    g_dst[i] = d;
    atomicAdd(&g_deg[d], 1);
}

// ---- parallel exclusive scan of g_deg ----
__global__ void reduce_deg_kernel() {          // grid NB, 256
    __shared__ int sh[256];
    int i = blockIdx.x * 256 + threadIdx.x;
    sh[threadIdx.x] = (i < N_NODES) ? g_deg[i] : 0;
    __syncthreads();
    for (int o = 128; o > 0; o >>= 1) {
        if (threadIdx.x < o) sh[threadIdx.x] += sh[threadIdx.x + o];
        __syncthreads();
    }
    if (threadIdx.x == 0) g_bsum[blockIdx.x] = sh[0];
}

__global__ void scan_bsums_kernel() {          // 1 block, 256
    __shared__ int sh[256];
    int t = threadIdx.x;
    int mine = (t < NB) ? g_bsum[t] : 0;
    sh[t] = mine;
    __syncthreads();
    for (int o = 1; o < 256; o <<= 1) {
        int v = (t >= o) ? sh[t - o] : 0;
        __syncthreads();
        sh[t] += v;
        __syncthreads();
    }
    if (t < NB) g_boff[t] = sh[t] - mine;      // exclusive
    if (t == 0) g_rowoff[N_NODES] = NE;
}

__global__ void scan_write_kernel() {          // grid NB, 256
    __shared__ int sh[256];
    int i = blockIdx.x * 256 + threadIdx.x;
    int v = (i < N_NODES) ? g_deg[i] : 0;
    sh[threadIdx.x] = v;
    __syncthreads();
    for (int o = 1; o < 256; o <<= 1) {
        int u = (threadIdx.x >= o) ? sh[threadIdx.x - o] : 0;
        __syncthreads();
        sh[threadIdx.x] += u;
        __syncthreads();
    }
    if (i < N_NODES) {
        int excl = g_boff[blockIdx.x] + sh[threadIdx.x] - v;
        g_rowoff[i] = excl;
        g_cursor[i] = excl;
    }
}

__global__ void scatter_kernel() {
    int i = blockIdx.x * blockDim.x + threadIdx.x;
    if (i >= NE) return;
    int pos = atomicAdd(&g_cursor[g_dst[i]], 1);
    g_csr_src[pos] = g_src[i];
}

// ==================== weight split (small) ====================
__global__ void split_Wt_kernel(const float* __restrict__ W, int K, int N, int Kpad,
                                __nv_bfloat16* __restrict__ hi, __nv_bfloat16* __restrict__ lo) {
    size_t total = (size_t)N * Kpad;
    size_t i = (size_t)blockIdx.x * blockDim.x + threadIdx.x;
    size_t stride = (size_t)gridDim.x * blockDim.x;
    for (; i < total; i += stride) {
        int n = (int)(i / Kpad), k = (int)(i % Kpad);
        float v = (k < K) ? W[(size_t)k * N + n] : 0.0f;
        __nv_bfloat16 h = __float2bfloat16(v);
        hi[i] = h;
        lo[i] = __float2bfloat16(v - __bfloat162float(h));
    }
}

// ==================== GEMM common ====================
#define KC        32
#define SPITCH    80
#define ARR_BYTES (128 * SPITCH)    // 10240

// ---------- layer-1 GEMM: fp32 A loaded+split in-kernel ----------
// smem: AHI [0,10240), ALO [10240,20480), B stage s at 20480 + s*20480 (BHI +0, BLO +10240)
#define G1_OFF_AHI 0
#define G1_OFF_ALO ARR_BYTES
#define G1_B(s)    (2 * ARR_BYTES + (s) * 2 * ARR_BYTES)
#define G1_SMEM    (6 * ARR_BYTES)  // 61440

__global__ void __launch_bounds__(256)
gemm1_tc_kernel(const float* __restrict__ Af,
                const __nv_bfloat16* __restrict__ Bhi, const __nv_bfloat16* __restrict__ Blo,
                float* __restrict__ C) {
    extern __shared__ char smem[];
    const uint32_t sb = smem_u32(smem);
    const int tid = threadIdx.x;
    const int wid = tid >> 5, lane = tid & 31;
    const int warp_m = wid & 3, warp_n = wid >> 2;
    const int m0 = blockIdx.y * 128;
    const int n0 = blockIdx.x * 128;
    const int nchunks = K1PAD / KC;   // 46

    // B cp.async mapping
    const int row0 = tid >> 2, seg = tid & 3;
    const int row1 = row0 + 64;
    const uint32_t bs0 = (uint32_t)row0 * SPITCH + seg * 16;
    const uint32_t bs1 = (uint32_t)row1 * SPITCH + seg * 16;
    const size_t gB0 = (size_t)(n0 + row0) * K1PAD + seg * 8;
    const size_t gB1 = (size_t)(n0 + row1) * K1PAD + seg * 8;

    // A fp32 load mapping: thread covers one half-row (16 floats) per chunk
    const int arow = tid >> 1;
    const int acol0 = (tid & 1) * 16;
    const bool row_ok = (m0 + arow) < N_NODES;
    const float* arow_ptr = Af + (size_t)(m0 + arow) * F_IN;

    // ldmatrix addressing
    const int lr = lane & 7, g = lane >> 3;
    const uint32_t offA = (uint32_t)(warp_m * 32 + lr + (g & 1) * 8) * SPITCH + (g >> 1) * 16;
    const uint32_t offB = (uint32_t)(warp_n * 64 + lr + (g >> 1) * 8) * SPITCH + (g & 1) * 16;

    float acc[2][8][4];
    #pragma unroll
    for (int mi = 0; mi < 2; mi++)
        #pragma unroll
        for (int ni = 0; ni < 8; ni++)
            #pragma unroll
            for (int q = 0; q < 4; q++) acc[mi][ni][q] = 0.0f;

    float areg[16];
    // ---- prologue: B(0) cp.async + A(0) LDG ----
    {
        const uint32_t d = sb + G1_B(0);
        cp16(d + bs0, Bhi + gB0); cp16(d + bs1, Bhi + gB1);
        cp16(d + ARR_BYTES + bs0, Blo + gB0); cp16(d + ARR_BYTES + bs1, Blo + gB1);
        asm volatile("cp.async.commit_group;");
        const int cb = acol0;   // k0 = 0
        if (row_ok) {
            #pragma unroll
            for (int j = 0; j < 16; j++) areg[j] = arow_ptr[cb + j];   // cb+16 <= F_IN always here
        } else {
            #pragma unroll
            for (int j = 0; j < 16; j++) areg[j] = 0.0f;
        }
    }

    char* const aHi = smem + G1_OFF_AHI + (size_t)arow * SPITCH + acol0 * 2;
    char* const aLo = smem + G1_OFF_ALO + (size_t)arow * SPITCH + acol0 * 2;

    for (int c = 0; c < nchunks; c++) {
        // convert + store A chunk c into (single-buffered) AHI/ALO
        #pragma unroll
        for (int j = 0; j < 8; j++) {
            float v0 = areg[2 * j], v1 = areg[2 * j + 1];
            __nv_bfloat16 h0 = __float2bfloat16(v0), h1 = __float2bfloat16(v1);
            __nv_bfloat162 hh; hh.x = h0; hh.y = h1;
            __nv_bfloat162 ll;
            ll.x = __float2bfloat16(v0 - __bfloat162float(h0));
            ll.y = __float2bfloat16(v1 - __bfloat162float(h1));
            *(__nv_bfloat162*)(aHi + j * 4) = hh;
            *(__nv_bfloat162*)(aLo + j * 4) = ll;
        }
        if (c + 1 < nchunks) {
            // prefetch B(c+1)
            const uint32_t d = sb + G1_B((c + 1) & 1);
            const size_t ko = (size_t)(c + 1) * KC;
            cp16(d + bs0, Bhi + gB0 + ko); cp16(d + bs1, Bhi + gB1 + ko);
            cp16(d + ARR_BYTES + bs0, Blo + gB0 + ko); cp16(d + ARR_BYTES + bs1, Blo + gB1 + ko);
            asm volatile("cp.async.commit_group;");
            // LDG A(c+1) with bounds guards
            const int cb = (c + 1) * KC + acol0;
            if (row_ok && cb + 16 <= F_IN) {
                #pragma unroll
                for (int j = 0; j < 16; j++) areg[j] = arow_ptr[cb + j];
            } else if (row_ok) {
                #pragma unroll
                for (int j = 0; j < 16; j++) areg[j] = (cb + j < F_IN) ? arow_ptr[cb + j] : 0.0f;
            } else {
                #pragma unroll
                for (int j = 0; j < 16; j++) areg[j] = 0.0f;
            }
            asm volatile("cp.async.wait_group 1;");
        } else {
            asm volatile("cp.async.wait_group 0;");
        }
        __syncthreads();

        const uint32_t bbase = sb + G1_B(c & 1);
        #pragma unroll
        for (int ks = 0; ks < 2; ks++) {
            const uint32_t kadd = ks * 32;
            uint32_t ahi[2][4], alo[2][4], bhi[8][2], blo[8][2];
            #pragma unroll
            for (int mt = 0; mt < 2; mt++) {
                ldm_x4(ahi[mt][0], ahi[mt][1], ahi[mt][2], ahi[mt][3],
                       sb + G1_OFF_AHI + offA + mt * 16 * SPITCH + kadd);
                ldm_x4(alo[mt][0], alo[mt][1], alo[mt][2], alo[mt][3],
                       sb + G1_OFF_ALO + offA + mt * 16 * SPITCH + kadd);
            }
            #pragma unroll
            for (int np = 0; np < 4; np++) {
                ldm_x4(bhi[2*np][0], bhi[2*np][1], bhi[2*np+1][0], bhi[2*np+1][1],
                       bbase + offB + np * 16 * SPITCH + kadd);
                ldm_x4(blo[2*np][0], blo[2*np][1], blo[2*np+1][0], blo[2*np+1][1],
                       bbase + ARR_BYTES + offB + np * 16 * SPITCH + kadd);
            }
            #pragma unroll
            for (int mi = 0; mi < 2; mi++)
                #pragma unroll
                for (int ni = 0; ni < 8; ni++) {
                    mma_bf16(acc[mi][ni], ahi[mi], bhi[ni]);
                    mma_bf16(acc[mi][ni], ahi[mi], blo[ni]);
                    mma_bf16(acc[mi][ni], alo[mi], bhi[ni]);
                }
        }
        __syncthreads();
    }

    const int er = lane >> 2, ec = (lane & 3) * 2;
    #pragma unroll
    for (int mi = 0; mi < 2; mi++) {
        const int r_lo = m0 + warp_m * 32 + mi * 16 + er;
        #pragma unroll
        for (int ni = 0; ni < 8; ni++) {
            const int cc = n0 + warp_n * 64 + ni * 8 + ec;
            *(float2*)(C + (size_t)r_lo * H1 + cc)       = make_float2(acc[mi][ni][0], acc[mi][ni][1]);
            *(float2*)(C + (size_t)(r_lo + 8) * H1 + cc) = make_float2(acc[mi][ni][2], acc[mi][ni][3]);
        }
    }
}

// ---------- layer-2 GEMM: pre-split bf16 A (cp.async double-buffered) ----------
#define STG_BYTES (4 * ARR_BYTES)   // 40960
#define OFF_AHI   0
#define OFF_ALO   ARR_BYTES
#define OFF_BHI   (2 * ARR_BYTES)
#define OFF_BLO   (3 * ARR_BYTES)
#define SMEM_DYN  (2 * STG_BYTES)   // 81920

__global__ void __launch_bounds__(256)
gemm_tc_kernel(const __nv_bfloat16* __restrict__ Ahi, const __nv_bfloat16* __restrict__ Alo,
               const __nv_bfloat16* __restrict__ Bhi, const __nv_bfloat16* __restrict__ Blo,
               float* __restrict__ C, int Kpad, int Nc) {
    extern __shared__ char smem[];
    const uint32_t sb = smem_u32(smem);
    const int tid = threadIdx.x;
    const int wid = tid >> 5, lane = tid & 31;
    const int warp_m = wid & 3, warp_n = wid >> 2;
    const int m0 = blockIdx.y * 128;
    const int n0 = blockIdx.x * 128;
    const int nchunks = Kpad / KC;

    const int row0 = tid >> 2, seg = tid & 3;
    const int row1 = row0 + 64;
    const uint32_t s0 = (uint32_t)row0 * SPITCH + seg * 16;
    const uint32_t s1 = (uint32_t)row1 * SPITCH + seg * 16;
    const size_t gA0 = (size_t)(m0 + row0) * Kpad + seg * 8;
    const size_t gA1 = (size_t)(m0 + row1) * Kpad + seg * 8;
    const size_t gB0 = (size_t)(n0 + row0) * Kpad + seg * 8;
    const size_t gB1 = (size_t)(n0 + row1) * Kpad + seg * 8;

    const int lr = lane & 7, g = lane >> 3;
    const uint32_t offA = (uint32_t)(warp_m * 32 + lr + (g & 1) * 8) * SPITCH + (g >> 1) * 16;
    const uint32_t offB = (uint32_t)(warp_n * 64 + lr + (g >> 1) * 8) * SPITCH + (g & 1) * 16;

    float acc[2][8][4];
    #pragma unroll
    for (int mi = 0; mi < 2; mi++)
        #pragma unroll
        for (int ni = 0; ni < 8; ni++)
            #pragma unroll
            for (int q = 0; q < 4; q++) acc[mi][ni][q] = 0.0f;

    {
        const uint32_t d = sb;
        cp16(d + OFF_AHI + s0, Ahi + gA0); cp16(d + OFF_AHI + s1, Ahi + gA1);
        cp16(d + OFF_ALO + s0, Alo + gA0); cp16(d + OFF_ALO + s1, Alo + gA1);
        cp16(d + OFF_BHI + s0, Bhi + gB0); cp16(d + OFF_BHI + s1, Bhi + gB1);
        cp16(d + OFF_BLO + s0, Blo + gB0); cp16(d + OFF_BLO + s1, Blo + gB1);
        asm volatile("cp.async.commit_group;");
    }

    for (int c = 0; c < nchunks; c++) {
        if (c + 1 < nchunks) {
            const uint32_t d = sb + ((c + 1) & 1) * STG_BYTES;
            const size_t ko = (size_t)(c + 1) * KC;
            cp16(d + OFF_AHI + s0, Ahi + gA0 + ko); cp16(d + OFF_AHI + s1, Ahi + gA1 + ko);
            cp16(d + OFF_ALO + s0, Alo + gA0 + ko); cp16(d + OFF_ALO + s1, Alo + gA1 + ko);
            cp16(d + OFF_BHI + s0, Bhi + gB0 + ko); cp16(d + OFF_BHI + s1, Bhi + gB1 + ko);
            cp16(d + OFF_BLO + s0, Blo + gB0 + ko); cp16(d + OFF_BLO + s1, Blo + gB1 + ko);
            asm volatile("cp.async.commit_group;");
            asm volatile("cp.async.wait_group 1;");
        } else {
            asm volatile("cp.async.wait_group 0;");
        }
        __syncthreads();

        const uint32_t base = sb + (c & 1) * STG_BYTES;
        #pragma unroll
        for (int ks = 0; ks < 2; ks++) {
            const uint32_t kadd = ks * 32;
            uint32_t ahi[2][4], alo[2][4], bhi[8][2], blo[8][2];
            #pragma unroll
            for (int mt = 0; mt < 2; mt++) {
                ldm_x4(ahi[mt][0], ahi[mt][1], ahi[mt][2], ahi[mt][3],
                       base + OFF_AHI + offA + mt * 16 * SPITCH + kadd);
                ldm_x4(alo[mt][0], alo[mt][1], alo[mt][2], alo[mt][3],
                       base + OFF_ALO + offA + mt * 16 * SPITCH + kadd);
            }
            #pragma unroll
            for (int np = 0; np < 4; np++) {
                ldm_x4(bhi[2*np][0], bhi[2*np][1], bhi[2*np+1][0], bhi[2*np+1][1],
                       base + OFF_BHI + offB + np * 16 * SPITCH + kadd);
                ldm_x4(blo[2*np][0], blo[2*np][1], blo[2*np+1][0], blo[2*np+1][1],
                       base + OFF_BLO + offB + np * 16 * SPITCH + kadd);
            }
            #pragma unroll
            for (int mi = 0; mi < 2; mi++)
                #pragma unroll
                for (int ni = 0; ni < 8; ni++) {
                    mma_bf16(acc[mi][ni], ahi[mi], bhi[ni]);
                    mma_bf16(acc[mi][ni], ahi[mi], blo[ni]);
                    mma_bf16(acc[mi][ni], alo[mi], bhi[ni]);
                }
        }
        __syncthreads();
    }

    const int er = lane >> 2, ec = (lane & 3) * 2;
    #pragma unroll
    for (int mi = 0; mi < 2; mi++) {
        const int r_lo = m0 + warp_m * 32 + mi * 16 + er;
        #pragma unroll
        for (int ni = 0; ni < 8; ni++) {
            const int cc = n0 + warp_n * 64 + ni * 8 + ec;
            *(float2*)(C + (size_t)r_lo * Nc + cc)       = make_float2(acc[mi][ni][0], acc[mi][ni][1]);
            *(float2*)(C + (size_t)(r_lo + 8) * Nc + cc) = make_float2(acc[mi][ni][2], acc[mi][ni][3]);
        }
    }
}

// ==================== attention scores ====================
__global__ void s_kernel_vec(const float* __restrict__ h, const float* __restrict__ a_s,
                             const float* __restrict__ a_d, int F) {
    int node = blockIdx.x * (blockDim.x >> 5) + (threadIdx.x >> 5);
    int lane = threadIdx.x & 31;
    if (node >= N_NODES) return;
    const float* hr = h + (size_t)node * F;
    float vs = 0.0f, vd = 0.0f;
    for (int f = lane * 4; f < F; f += 128) {
        float4 x = *(const float4*)(hr + f);
        float4 as4 = *(const float4*)(a_s + f);
        float4 ad4 = *(const float4*)(a_d + f);
        vs += x.x * as4.x + x.y * as4.y + x.z * as4.z + x.w * as4.w;
        vd += x.x * ad4.x + x.y * ad4.y + x.z * ad4.z + x.w * ad4.w;
    }
    #pragma unroll
    for (int o = 16; o > 0; o >>= 1) {
        vs += __shfl_down_sync(0xffffffffu, vs, o);
        vd += __shfl_down_sync(0xffffffffu, vd, o);
    }
    if (lane == 0) {
        g_ss[node] = vs;
        g_sd[node] = vd;
    }
}

__global__ void s_kernel_scalar(const float* __restrict__ h, const float* __restrict__ a_s,
                                const float* __restrict__ a_d, int F) {
    int node = blockIdx.x * (blockDim.x >> 5) + (threadIdx.x >> 5);
    int lane = threadIdx.x & 31;
    if (node >= N_NODES) return;
    const float* hr = h + (size_t)node * F;
    float vs = 0.0f, vd = 0.0f;
    for (int f = lane; f < F; f += 32) {
        float x = hr[f];
        vs += x * a_s[f];
        vd += x * a_d[f];
    }
    #pragma unroll
    for (int o = 16; o > 0; o >>= 1) {
        vs += __shfl_down_sync(0xffffffffu, vs, o);
        vd += __shfl_down_sync(0xffffffffu, vd, o);
    }
    if (lane == 0) {
        g_ss[node] = vs;
        g_sd[node] = vd;
    }
}

// ==================== fused GAT aggregation (warp per node) ====================
template <int F, int OUT_BF16>
__global__ void __launch_bounds__(256)
gat_agg_kernel(const float* __restrict__ h, const float* __restrict__ bias,
               float* __restrict__ outf,
               __nv_bfloat16* __restrict__ ohi, __nv_bfloat16* __restrict__ olo) {
    int node = blockIdx.x * 8 + (threadIdx.x >> 5);
    int lane = threadIdx.x & 31;
    if (node >= N_NODES) return;
    const int beg = g_rowoff[node], end = g_rowoff[node + 1];
    const float sd = g_sd[node];

    float m = -INFINITY;
    for (int i = beg + lane; i < end; i += 32) {
        float e = g_ss[g_csr_src[i]] + sd;
        e = e > 0.0f ? e : 0.2f * e;
        m = fmaxf(m, e);
    }
    #pragma unroll
    for (int o = 16; o > 0; o >>= 1) m = fmaxf(m, __shfl_xor_sync(0xffffffffu, m, o));

    constexpr int R4 = F / 128;
    float4 acc[R4];
    #pragma unroll
    for (int j = 0; j < R4; j++) acc[j] = make_float4(0.f, 0.f, 0.f, 0.f);
    float den = 0.0f;
    const uint32_t c4 = lane * 4;

    int i = beg;
    for (; i + 1 < end; i += 2) {
        int s0 = g_csr_src[i], s1 = g_csr_src[i + 1];
        float e0 = g_ss[s0] + sd; e0 = e0 > 0.0f ? e0 : 0.2f * e0;
        float e1 = g_ss[s1] + sd; e1 = e1 > 0.0f ? e1 : 0.2f * e1;
        float ee0 = __expf(e0 - m), ee1 = __expf(e1 - m);
        den += ee0 + ee1;
        const float* h0 = h + (size_t)s0 * F + c4;
        const float* h1 = h + (size_t)s1 * F + c4;
        #pragma unroll
        for (int j = 0; j < R4; j++) {
            float4 v0 = *(const float4*)(h0 + j * 128);
            float4 v1 = *(const float4*)(h1 + j * 128);
            acc[j].x += ee0 * v0.x + ee1 * v1.x;
            acc[j].y += ee0 * v0.y + ee1 * v1.y;
            acc[j].z += ee0 * v0.z + ee1 * v1.z;
            acc[j].w += ee0 * v0.w + ee1 * v1.w;
        }
    }
    if (i < end) {
        int s0 = g_csr_src[i];
        float e0 = g_ss[s0] + sd; e0 = e0 > 0.0f ? e0 : 0.2f * e0;
        float ee0 = __expf(e0 - m);
        den += ee0;
        const float* h0 = h + (size_t)s0 * F + c4;
        #pragma unroll
        for (int j = 0; j < R4; j++) {
            float4 v0 = *(const float4*)(h0 + j * 128);
            acc[j].x += ee0 * v0.x; acc[j].y += ee0 * v0.y;
            acc[j].z += ee0 * v0.z; acc[j].w += ee0 * v0.w;
        }
    }

    float inv = 1.0f / den;
    #pragma unroll
    for (int j = 0; j < R4; j++) {
        float4 b4 = *(const float4*)(bias + j * 128 + c4);
        float v0 = fmaxf(acc[j].x * inv + b4.x, 0.0f);
        float v1 = fmaxf(acc[j].y * inv + b4.y, 0.0f);
        float v2 = fmaxf(acc[j].z * inv + b4.z, 0.0f);
        float v3 = fmaxf(acc[j].w * inv + b4.w, 0.0f);
        size_t o = (size_t)node * F + j * 128 + c4;
        if (OUT_BF16) {
            __nv_bfloat16 h0 = __float2bfloat16(v0), h1 = __float2bfloat16(v1);
            __nv_bfloat16 h2 = __float2bfloat16(v2), h3 = __float2bfloat16(v3);
            ohi[o + 0] = h0; ohi[o + 1] = h1; ohi[o + 2] = h2; ohi[o + 3] = h3;
            olo[o + 0] = __float2bfloat16(v0 - __bfloat162float(h0));
            olo[o + 1] = __float2bfloat16(v1 - __bfloat162float(h1));
            olo[o + 2] = __float2bfloat16(v2 - __bfloat162float(h2));
            olo[o + 3] = __float2bfloat16(v3 - __bfloat162float(h3));
        } else {
            *(float4*)(outf + o) = make_float4(v0, v1, v2, v3);
        }
    }
}

// ==================== layer 3: skinny GEMM (smem W) + fused agg+logsoftmax ====================
__global__ void __launch_bounds__(256)
gemm3_kernel(const float* __restrict__ A, const float* __restrict__ W,
             float* __restrict__ C) {
    __shared__ float sW[H2 * NC];
    for (int i = threadIdx.x; i < H2 * NC; i += blockDim.x) sW[i] = W[i];
    __syncthreads();
    int node = blockIdx.x * blockDim.x + threadIdx.x;
    if (node >= N_NODES) return;
    const float4* a4 = (const float4*)(A + (size_t)node * H2);
    float acc[NC] = {0,0,0,0,0,0,0};
    #pragma unroll 4
    for (int k4 = 0; k4 < H2 / 4; k4++) {
        float4 a = a4[k4];
        const float* w0 = sW + (k4 * 4) * NC;
        #pragma unroll
        for (int c = 0; c < NC; c++)
            acc[c] += a.x * w0[c] + a.y * w0[NC + c] + a.z * w0[2 * NC + c] + a.w * w0[3 * NC + c];
    }
    #pragma unroll
    for (int c = 0; c < NC; c++) C[(size_t)node * NC + c] = acc[c];
}

__global__ void __launch_bounds__(256)
gat_agg3_final_kernel(const float* __restrict__ h, const float* __restrict__ bias,
                      float* __restrict__ out) {
    int node = blockIdx.x * 8 + (threadIdx.x >> 5);
    int lane = threadIdx.x & 31;
    if (node >= N_NODES) return;
    const int beg = g_rowoff[node], end = g_rowoff[node + 1];
    const float sd = g_sd[node];

    float m = -INFINITY;
    for (int i = beg + lane; i < end; i += 32) {
        float e = g_ss[g_csr_src[i]] + sd;
        e = e > 0.0f ? e : 0.2f * e;
        m = fmaxf(m, e);
    }
    #pragma unroll
    for (int o = 16; o > 0; o >>= 1) m = fmaxf(m, __shfl_xor_sync(0xffffffffu, m, o));

    float acc[NC] = {0,0,0,0,0,0,0};
    float den = 0.0f;
    for (int i = beg + lane; i < end; i += 32) {
        int s = g_csr_src[i];
        float e = g_ss[s] + sd;
        e = e > 0.0f ? e : 0.2f * e;
        float ee = __expf(e - m);
        den += ee;
        const float* hr = h + (size_t)s * NC;
        #pragma unroll
        for (int c = 0; c < NC; c++) acc[c] += ee * hr[c];
    }
    #pragma unroll
    for (int o = 16; o > 0; o >>= 1) {
        den += __shfl_xor_sync(0xffffffffu, den, o);
        #pragma unroll
        for (int c = 0; c < NC; c++) acc[c] += __shfl_xor_sync(0xffffffffu, acc[c], o);
    }
    if (lane == 0) {
        float inv = 1.0f / den;
        float z[NC], mx = -INFINITY;
        #pragma unroll
        for (int c = 0; c < NC; c++) {
            z[c] = acc[c] * inv + bias[c];
            mx = fmaxf(mx, z[c]);
        }
        float ssum = 0.0f;
        #pragma unroll
        for (int c = 0; c < NC; c++) ssum += __expf(z[c] - mx);
        float l = logf(ssum);
        float* o = out + (size_t)node * NC;
        #pragma unroll
        for (int c = 0; c < NC; c++) o[c] = z[c] - mx - l;
    }
}

// ==================== launcher ====================
extern "C" void kernel_launch(void* const* d_in, const int* in_sizes, int n_in,
                              void* d_out, int out_size) {
    const float* x   = (const float*)d_in[0];
    const void*  ei  = d_in[1];
    const float* W1  = (const float*)d_in[2];
    const float* as1 = (const float*)d_in[3];
    const float* ad1 = (const float*)d_in[4];
    const float* b1  = (const float*)d_in[5];
    const float* W2  = (const float*)d_in[6];
    const float* as2 = (const float*)d_in[7];
    const float* ad2 = (const float*)d_in[8];
    const float* b2  = (const float*)d_in[9];
    const float* W3  = (const float*)d_in[10];
    const float* as3 = (const float*)d_in[11];
    const float* ad3 = (const float*)d_in[12];
    const float* b3  = (const float*)d_in[13];
    float* out = (float*)d_out;

    float *buf1, *buf2;
    __nv_bfloat16 *ahi, *alo, *bhi, *blo;
    cudaGetSymbolAddress((void**)&buf1, g_buf1);
    cudaGetSymbolAddress((void**)&buf2, g_buf2);
    cudaGetSymbolAddress((void**)&ahi, g_Ahi);
    cudaGetSymbolAddress((void**)&alo, g_Alo);
    cudaGetSymbolAddress((void**)&bhi, g_Bhi);
    cudaGetSymbolAddress((void**)&blo, g_Blo);

    cudaFuncSetAttribute(gemm1_tc_kernel, cudaFuncAttributeMaxDynamicSharedMemorySize, G1_SMEM);
    cudaFuncSetAttribute(gemm_tc_kernel, cudaFuncAttributeMaxDynamicSharedMemorySize, SMEM_DYN);

    const int BT = 256;
    const int edge_blocks      = (NE + BT - 1) / BT;
    const int node_warp_blocks = (N_NODES + (BT / 32) - 1) / (BT / 32);
    const int node_blocks      = (N_NODES + BT - 1) / BT;

    // ---- CSR build ----
    detect_kernel<<<1, 128>>>((const unsigned int*)ei);
    zero_deg_kernel<<<node_blocks, BT>>>();
    prep_edges_kernel<<<edge_blocks, BT>>>(ei);
    reduce_deg_kernel<<<NB, 256>>>();
    scan_bsums_kernel<<<1, 256>>>();
    scan_write_kernel<<<NB, 256>>>();
    scatter_kernel<<<edge_blocks, BT>>>();

    // ---------------- layer 1: F_IN -> H1 (A split fused into GEMM) ----------------
    split_Wt_kernel<<<2048, BT>>>(W1, F_IN, H1, K1PAD, bhi, blo);
    gemm1_tc_kernel<<<dim3(H1 / 128, MPAD / 128), BT, G1_SMEM>>>(x, bhi, blo, buf1);
    s_kernel_vec<<<node_warp_blocks, BT>>>(buf1, as1, ad1, H1);
    gat_agg_kernel<H1, 1><<<node_warp_blocks, BT>>>(buf1, b1, nullptr, ahi, alo);

    // ---------------- layer 2: H1 -> H2 ----------------
    split_Wt_kernel<<<2048, BT>>>(W2, H1, H2, H1, bhi, blo);
    gemm_tc_kernel<<<dim3(H2 / 128, MPAD / 128), BT, SMEM_DYN>>>(ahi, alo, bhi, blo, buf1, H1, H2);
    s_kernel_vec<<<node_warp_blocks, BT>>>(buf1, as2, ad2, H2);
    gat_agg_kernel<H2, 0><<<node_warp_blocks, BT>>>(buf1, b2, buf2, nullptr, nullptr);

    // ---------------- layer 3: H2 -> NC ----------------
    gemm3_kernel<<<node_blocks, BT>>>(buf2, W3, buf1);
    s_kernel_scalar<<<node_warp_blocks, BT>>>(buf1, as3, ad3, NC);
    gat_agg3_final_kernel<<<node_warp_blocks, BT>>>(buf1, b3, out);
}

// round 11
// speedup vs baseline: 2.9228x; 1.3812x over previous
#include <cuda_runtime.h>
#include <cuda_fp16.h>
#include <math.h>
#include <stdint.h>

#define N_NODES 50000
#define MPAD    50048   // 391 * 128
#define E0      800000
#define NE      850000
#define F_IN    1433
#define K1PAD   1472    // 46 * 32
#define H1      512
#define H2      256
#define NC      7
#define NB      196     // ceil(N_NODES / 256)

// ==================== scratch (device globals) ====================
__device__ __half g_A16[(size_t)MPAD * H1];        // layer-2 GEMM A (fp16)
__device__ __half g_Bhi[(size_t)H1 * K1PAD];
__device__ __half g_Blo[(size_t)H1 * K1PAD];
__device__ float g_buf1[(size_t)MPAD * H1];
__device__ float g_buf2[(size_t)MPAD * H1];
__device__ float g_ss[N_NODES];
__device__ float g_sd[N_NODES];
__device__ int   g_src[NE];
__device__ int   g_dst[NE];
__device__ int   g_csr_src[NE];
__device__ int   g_deg[N_NODES];
__device__ int   g_rowoff[N_NODES + 1];
__device__ int   g_cursor[N_NODES];
__device__ int   g_bsum[NB];
__device__ int   g_boff[NB];
__device__ int   g_is64;

// ==================== PTX helpers (base-arch only) ====================
__device__ __forceinline__ uint32_t smem_u32(const void* p) {
    uint32_t a;
    asm("{ .reg .u64 t; cvta.to.shared.u64 t, %1; cvt.u32.u64 %0, t; }" : "=r"(a) : "l"(p));
    return a;
}
__device__ __forceinline__ void cp16(uint32_t dst, const void* src) {
    asm volatile("cp.async.cg.shared.global [%0], [%1], 16;" :: "r"(dst), "l"(src));
}
__device__ __forceinline__ void ldm_x4(uint32_t& r0, uint32_t& r1, uint32_t& r2, uint32_t& r3,
                                       uint32_t addr) {
    asm volatile("ldmatrix.sync.aligned.m8n8.x4.shared.b16 {%0,%1,%2,%3}, [%4];"
                 : "=r"(r0), "=r"(r1), "=r"(r2), "=r"(r3) : "r"(addr));
}
__device__ __forceinline__ void mma_f16(float* c, const uint32_t* a, const uint32_t* b) {
    asm volatile("mma.sync.aligned.m16n8k16.row.col.f32.f16.f16.f32 "
                 "{%0,%1,%2,%3}, {%4,%5,%6,%7}, {%8,%9}, {%0,%1,%2,%3};"
                 : "+f"(c[0]), "+f"(c[1]), "+f"(c[2]), "+f"(c[3])
                 : "r"(a[0]), "r"(a[1]), "r"(a[2]), "r"(a[3]), "r"(b[0]), "r"(b[1]));
}

// ==================== edge prep + CSR build ====================
__global__ void detect_kernel(const unsigned int* __restrict__ w) {
    __shared__ int nz;
    if (threadIdx.x == 0) nz = 0;
    __syncthreads();
    if (w[threadIdx.x * 2 + 1] != 0u) atomicOr(&nz, 1);
    __syncthreads();
    if (threadIdx.x == 0) g_is64 = (nz == 0);
}

__global__ void zero_deg_kernel() {
    int i = blockIdx.x * blockDim.x + threadIdx.x;
    if (i < N_NODES) g_deg[i] = 0;
}

__global__ void prep_edges_kernel(const void* __restrict__ ei) {
    int i = blockIdx.x * blockDim.x + threadIdx.x;
    if (i >= NE) return;
    int s, d;
    if (i < E0) {
        if (g_is64) {
            const long long* e = (const long long*)ei;
            s = (int)e[i]; d = (int)e[E0 + i];
        } else {
            const int* e = (const int*)ei;
            s = e[i]; d = e[E0 + i];
        }
    } else {
        s = d = i - E0;
    }
    s = min(max(s, 0), N_NODES - 1);
    d = min(max(d, 0), N_NODES - 1);
    g_src[i] = s;
    g_dst[i] = d;
    atomicAdd(&g_deg[d], 1);
}

__global__ void reduce_deg_kernel() {          // grid NB, 256
    __shared__ int sh[256];
    int i = blockIdx.x * 256 + threadIdx.x;
    sh[threadIdx.x] = (i < N_NODES) ? g_deg[i] : 0;
    __syncthreads();
    for (int o = 128; o > 0; o >>= 1) {
        if (threadIdx.x < o) sh[threadIdx.x] += sh[threadIdx.x + o];
        __syncthreads();
    }
    if (threadIdx.x == 0) g_bsum[blockIdx.x] = sh[0];
}

__global__ void scan_bsums_kernel() {          // 1 block, 256
    __shared__ int sh[256];
    int t = threadIdx.x;
    int mine = (t < NB) ? g_bsum[t] : 0;
    sh[t] = mine;
    __syncthreads();
    for (int o = 1; o < 256; o <<= 1) {
        int v = (t >= o) ? sh[t - o] : 0;
        __syncthreads();
        sh[t] += v;
        __syncthreads();
    }
    if (t < NB) g_boff[t] = sh[t] - mine;      // exclusive
    if (t == 0) g_rowoff[N_NODES] = NE;
}

__global__ void scan_write_kernel() {          // grid NB, 256
    __shared__ int sh[256];
    int i = blockIdx.x * 256 + threadIdx.x;
    int v = (i < N_NODES) ? g_deg[i] : 0;
    sh[threadIdx.x] = v;
    __syncthreads();
    for (int o = 1; o < 256; o <<= 1) {
        int u = (threadIdx.x >= o) ? sh[threadIdx.x - o] : 0;
        __syncthreads();
        sh[threadIdx.x] += u;
        __syncthreads();
    }
    if (i < N_NODES) {
        int excl = g_boff[blockIdx.x] + sh[threadIdx.x] - v;
        g_rowoff[i] = excl;
        g_cursor[i] = excl;
    }
}

__global__ void scatter_kernel() {
    int i = blockIdx.x * blockDim.x + threadIdx.x;
    if (i >= NE) return;
    int pos = atomicAdd(&g_cursor[g_dst[i]], 1);
    g_csr_src[pos] = g_src[i];
}

// ==================== weight split (fp16 hi/lo) ====================
__global__ void split_Wt_kernel(const float* __restrict__ W, int K, int N, int Kpad,
                                __half* __restrict__ hi, __half* __restrict__ lo) {
    size_t total = (size_t)N * Kpad;
    size_t i = (size_t)blockIdx.x * blockDim.x + threadIdx.x;
    size_t stride = (size_t)gridDim.x * blockDim.x;
    for (; i < total; i += stride) {
        int n = (int)(i / Kpad), k = (int)(i % Kpad);
        float v = (k < K) ? W[(size_t)k * N + n] : 0.0f;
        __half h = __float2half(v);
        hi[i] = h;
        lo[i] = __float2half(v - __half2float(h));
    }
}

// ==================== GEMM common ====================
#define KC        32
#define SPITCH    80
#define ARR_BYTES (128 * SPITCH)    // 10240

// ---------- layer-1 GEMM: fp32 A loaded + converted to fp16 in-kernel ----------
// smem: A16 [0,10240), B stage s at 10240 + s*20480 (BHI +0, BLO +10240)
#define G1_OFF_A  0
#define G1_B(s)   (ARR_BYTES + (s) * 2 * ARR_BYTES)
#define G1_SMEM   (5 * ARR_BYTES)   // 51200

__global__ void __launch_bounds__(256)
gemm1_tc_kernel(const float* __restrict__ Af,
                const __half* __restrict__ Bhi, const __half* __restrict__ Blo,
                float* __restrict__ C) {
    extern __shared__ char smem[];
    const uint32_t sb = smem_u32(smem);
    const int tid = threadIdx.x;
    const int wid = tid >> 5, lane = tid & 31;
    const int warp_m = wid & 3, warp_n = wid >> 2;
    const int m0 = blockIdx.y * 128;
    const int n0 = blockIdx.x * 128;
    const int nchunks = K1PAD / KC;   // 46

    // B cp.async mapping
    const int row0 = tid >> 2, seg = tid & 3;
    const int row1 = row0 + 64;
    const uint32_t bs0 = (uint32_t)row0 * SPITCH + seg * 16;
    const uint32_t bs1 = (uint32_t)row1 * SPITCH + seg * 16;
    const size_t gB0 = (size_t)(n0 + row0) * K1PAD + seg * 8;
    const size_t gB1 = (size_t)(n0 + row1) * K1PAD + seg * 8;

    // A fp32 load mapping: thread covers one half-row (16 floats) per chunk
    const int arow = tid >> 1;
    const int acol0 = (tid & 1) * 16;
    const bool row_ok = (m0 + arow) < N_NODES;
    const float* arow_ptr = Af + (size_t)(m0 + arow) * F_IN;

    // ldmatrix addressing
    const int lr = lane & 7, g = lane >> 3;
    const uint32_t offA = (uint32_t)(warp_m * 32 + lr + (g & 1) * 8) * SPITCH + (g >> 1) * 16;
    const uint32_t offB = (uint32_t)(warp_n * 64 + lr + (g >> 1) * 8) * SPITCH + (g & 1) * 16;

    float acc[2][8][4];
    #pragma unroll
    for (int mi = 0; mi < 2; mi++)
        #pragma unroll
        for (int ni = 0; ni < 8; ni++)
            #pragma unroll
            for (int q = 0; q < 4; q++) acc[mi][ni][q] = 0.0f;

    float areg[16];
    {
        const uint32_t d = sb + G1_B(0);
        cp16(d + bs0, Bhi + gB0); cp16(d + bs1, Bhi + gB1);
        cp16(d + ARR_BYTES + bs0, Blo + gB0); cp16(d + ARR_BYTES + bs1, Blo + gB1);
        asm volatile("cp.async.commit_group;");
        if (row_ok) {
            #pragma unroll
            for (int j = 0; j < 16; j++) areg[j] = arow_ptr[acol0 + j];
        } else {
            #pragma unroll
            for (int j = 0; j < 16; j++) areg[j] = 0.0f;
        }
    }

    char* const aDst = smem + G1_OFF_A + (size_t)arow * SPITCH + acol0 * 2;

    for (int c = 0; c < nchunks; c++) {
        // convert + store A chunk c (fp16)
        #pragma unroll
        for (int j = 0; j < 8; j++) {
            __half2 hh;
            hh.x = __float2half(areg[2 * j]);
            hh.y = __float2half(areg[2 * j + 1]);
            *(__half2*)(aDst + j * 4) = hh;
        }
        if (c + 1 < nchunks) {
            const uint32_t d = sb + G1_B((c + 1) & 1);
            const size_t ko = (size_t)(c + 1) * KC;
            cp16(d + bs0, Bhi + gB0 + ko); cp16(d + bs1, Bhi + gB1 + ko);
            cp16(d + ARR_BYTES + bs0, Blo + gB0 + ko); cp16(d + ARR_BYTES + bs1, Blo + gB1 + ko);
            asm volatile("cp.async.commit_group;");
            const int cb = (c + 1) * KC + acol0;
            if (row_ok && cb + 16 <= F_IN) {
                #pragma unroll
                for (int j = 0; j < 16; j++) areg[j] = arow_ptr[cb + j];
            } else if (row_ok) {
                #pragma unroll
                for (int j = 0; j < 16; j++) areg[j] = (cb + j < F_IN) ? arow_ptr[cb + j] : 0.0f;
            } else {
                #pragma unroll
                for (int j = 0; j < 16; j++) areg[j] = 0.0f;
            }
            asm volatile("cp.async.wait_group 1;");
        } else {
            asm volatile("cp.async.wait_group 0;");
        }
        __syncthreads();

        const uint32_t bbase = sb + G1_B(c & 1);
        #pragma unroll
        for (int ks = 0; ks < 2; ks++) {
            const uint32_t kadd = ks * 32;
            uint32_t a16[2][4], bhi[8][2], blo[8][2];
            #pragma unroll
            for (int mt = 0; mt < 2; mt++)
                ldm_x4(a16[mt][0], a16[mt][1], a16[mt][2], a16[mt][3],
                       sb + G1_OFF_A + offA + mt * 16 * SPITCH + kadd);
            #pragma unroll
            for (int np = 0; np < 4; np++) {
                ldm_x4(bhi[2*np][0], bhi[2*np][1], bhi[2*np+1][0], bhi[2*np+1][1],
                       bbase + offB + np * 16 * SPITCH + kadd);
                ldm_x4(blo[2*np][0], blo[2*np][1], blo[2*np+1][0], blo[2*np+1][1],
                       bbase + ARR_BYTES + offB + np * 16 * SPITCH + kadd);
            }
            #pragma unroll
            for (int mi = 0; mi < 2; mi++)
                #pragma unroll
                for (int ni = 0; ni < 8; ni++) {
                    mma_f16(acc[mi][ni], a16[mi], bhi[ni]);
                    mma_f16(acc[mi][ni], a16[mi], blo[ni]);
                }
        }
        __syncthreads();
    }

    const int er = lane >> 2, ec = (lane & 3) * 2;
    #pragma unroll
    for (int mi = 0; mi < 2; mi++) {
        const int r_lo = m0 + warp_m * 32 + mi * 16 + er;
        #pragma unroll
        for (int ni = 0; ni < 8; ni++) {
            const int cc = n0 + warp_n * 64 + ni * 8 + ec;
            *(float2*)(C + (size_t)r_lo * H1 + cc)       = make_float2(acc[mi][ni][0], acc[mi][ni][1]);
            *(float2*)(C + (size_t)(r_lo + 8) * H1 + cc) = make_float2(acc[mi][ni][2], acc[mi][ni][3]);
        }
    }
}

// ---------- layer-2 GEMM: fp16 A (cp.async), fp16 B hi/lo ----------
#define STG_BYTES (3 * ARR_BYTES)   // 30720
#define OFF_A16   0
#define OFF_BHI   ARR_BYTES
#define OFF_BLO   (2 * ARR_BYTES)
#define SMEM_DYN  (2 * STG_BYTES)   // 61440

__global__ void __launch_bounds__(256)
gemm_tc_kernel(const __half* __restrict__ A16,
               const __half* __restrict__ Bhi, const __half* __restrict__ Blo,
               float* __restrict__ C, int Kpad, int Nc) {
    extern __shared__ char smem[];
    const uint32_t sb = smem_u32(smem);
    const int tid = threadIdx.x;
    const int wid = tid >> 5, lane = tid & 31;
    const int warp_m = wid & 3, warp_n = wid >> 2;
    const int m0 = blockIdx.y * 128;
    const int n0 = blockIdx.x * 128;
    const int nchunks = Kpad / KC;

    const int row0 = tid >> 2, seg = tid & 3;
    const int row1 = row0 + 64;
    const uint32_t s0 = (uint32_t)row0 * SPITCH + seg * 16;
    const uint32_t s1 = (uint32_t)row1 * SPITCH + seg * 16;
    const size_t gA0 = (size_t)(m0 + row0) * Kpad + seg * 8;
    const size_t gA1 = (size_t)(m0 + row1) * Kpad + seg * 8;
    const size_t gB0 = (size_t)(n0 + row0) * Kpad + seg * 8;
    const size_t gB1 = (size_t)(n0 + row1) * Kpad + seg * 8;

    const int lr = lane & 7, g = lane >> 3;
    const uint32_t offA = (uint32_t)(warp_m * 32 + lr + (g & 1) * 8) * SPITCH + (g >> 1) * 16;
    const uint32_t offB = (uint32_t)(warp_n * 64 + lr + (g >> 1) * 8) * SPITCH + (g & 1) * 16;

    float acc[2][8][4];
    #pragma unroll
    for (int mi = 0; mi < 2; mi++)
        #pragma unroll
        for (int ni = 0; ni < 8; ni++)
            #pragma unroll
            for (int q = 0; q < 4; q++) acc[mi][ni][q] = 0.0f;

    {
        const uint32_t d = sb;
        cp16(d + OFF_A16 + s0, A16 + gA0); cp16(d + OFF_A16 + s1, A16 + gA1);
        cp16(d + OFF_BHI + s0, Bhi + gB0); cp16(d + OFF_BHI + s1, Bhi + gB1);
        cp16(d + OFF_BLO + s0, Blo + gB0); cp16(d + OFF_BLO + s1, Blo + gB1);
        asm volatile("cp.async.commit_group;");
    }

    for (int c = 0; c < nchunks; c++) {
        if (c + 1 < nchunks) {
            const uint32_t d = sb + ((c + 1) & 1) * STG_BYTES;
            const size_t ko = (size_t)(c + 1) * KC;
            cp16(d + OFF_A16 + s0, A16 + gA0 + ko); cp16(d + OFF_A16 + s1, A16 + gA1 + ko);
            cp16(d + OFF_BHI + s0, Bhi + gB0 + ko); cp16(d + OFF_BHI + s1, Bhi + gB1 + ko);
            cp16(d + OFF_BLO + s0, Blo + gB0 + ko); cp16(d + OFF_BLO + s1, Blo + gB1 + ko);
            asm volatile("cp.async.commit_group;");
            asm volatile("cp.async.wait_group 1;");
        } else {
            asm volatile("cp.async.wait_group 0;");
        }
        __syncthreads();

        const uint32_t base = sb + (c & 1) * STG_BYTES;
        #pragma unroll
        for (int ks = 0; ks < 2; ks++) {
            const uint32_t kadd = ks * 32;
            uint32_t a16[2][4], bhi[8][2], blo[8][2];
            #pragma unroll
            for (int mt = 0; mt < 2; mt++)
                ldm_x4(a16[mt][0], a16[mt][1], a16[mt][2], a16[mt][3],
                       base + OFF_A16 + offA + mt * 16 * SPITCH + kadd);
            #pragma unroll
            for (int np = 0; np < 4; np++) {
                ldm_x4(bhi[2*np][0], bhi[2*np][1], bhi[2*np+1][0], bhi[2*np+1][1],
                       base + OFF_BHI + offB + np * 16 * SPITCH + kadd);
                ldm_x4(blo[2*np][0], blo[2*np][1], blo[2*np+1][0], blo[2*np+1][1],
                       base + OFF_BLO + offB + np * 16 * SPITCH + kadd);
            }
            #pragma unroll
            for (int mi = 0; mi < 2; mi++)
                #pragma unroll
                for (int ni = 0; ni < 8; ni++) {
                    mma_f16(acc[mi][ni], a16[mi], bhi[ni]);
                    mma_f16(acc[mi][ni], a16[mi], blo[ni]);
                }
        }
        __syncthreads();
    }

    const int er = lane >> 2, ec = (lane & 3) * 2;
    #pragma unroll
    for (int mi = 0; mi < 2; mi++) {
        const int r_lo = m0 + warp_m * 32 + mi * 16 + er;
        #pragma unroll
        for (int ni = 0; ni < 8; ni++) {
            const int cc = n0 + warp_n * 64 + ni * 8 + ec;
            *(float2*)(C + (size_t)r_lo * Nc + cc)       = make_float2(acc[mi][ni][0], acc[mi][ni][1]);
            *(float2*)(C + (size_t)(r_lo + 8) * Nc + cc) = make_float2(acc[mi][ni][2], acc[mi][ni][3]);
        }
    }
}

// ==================== attention scores ====================
__global__ void s_kernel_vec(const float* __restrict__ h, const float* __restrict__ a_s,
                             const float* __restrict__ a_d, int F) {
    int node = blockIdx.x * (blockDim.x >> 5) + (threadIdx.x >> 5);
    int lane = threadIdx.x & 31;
    if (node >= N_NODES) return;
    const float* hr = h + (size_t)node * F;
    float vs = 0.0f, vd = 0.0f;
    for (int f = lane * 4; f < F; f += 128) {
        float4 x = *(const float4*)(hr + f);
        float4 as4 = *(const float4*)(a_s + f);
        float4 ad4 = *(const float4*)(a_d + f);
        vs += x.x * as4.x + x.y * as4.y + x.z * as4.z + x.w * as4.w;
        vd += x.x * ad4.x + x.y * ad4.y + x.z * ad4.z + x.w * ad4.w;
    }
    #pragma unroll
    for (int o = 16; o > 0; o >>= 1) {
        vs += __shfl_down_sync(0xffffffffu, vs, o);
        vd += __shfl_down_sync(0xffffffffu, vd, o);
    }
    if (lane == 0) {
        g_ss[node] = vs;
        g_sd[node] = vd;
    }
}

__global__ void s_kernel_scalar(const float* __restrict__ h, const float* __restrict__ a_s,
                                const float* __restrict__ a_d, int F) {
    int node = blockIdx.x * (blockDim.x >> 5) + (threadIdx.x >> 5);
    int lane = threadIdx.x & 31;
    if (node >= N_NODES) return;
    const float* hr = h + (size_t)node * F;
    float vs = 0.0f, vd = 0.0f;
    for (int f = lane; f < F; f += 32) {
        float x = hr[f];
        vs += x * a_s[f];
        vd += x * a_d[f];
    }
    #pragma unroll
    for (int o = 16; o > 0; o >>= 1) {
        vs += __shfl_down_sync(0xffffffffu, vs, o);
        vd += __shfl_down_sync(0xffffffffu, vd, o);
    }
    if (lane == 0) {
        g_ss[node] = vs;
        g_sd[node] = vd;
    }
}

// ==================== fused GAT aggregation (warp per node) ====================
// OUT_F16=1: write fp16 (next GEMM's A operand) instead of fp32.
template <int F, int OUT_F16>
__global__ void __launch_bounds__(256)
gat_agg_kernel(const float* __restrict__ h, const float* __restrict__ bias,
               float* __restrict__ outf, __half* __restrict__ oh) {
    int node = blockIdx.x * 8 + (threadIdx.x >> 5);
    int lane = threadIdx.x & 31;
    if (node >= N_NODES) return;
    const int beg = g_rowoff[node], end = g_rowoff[node + 1];
    const float sd = g_sd[node];

    float m = -INFINITY;
    for (int i = beg + lane; i < end; i += 32) {
        float e = g_ss[g_csr_src[i]] + sd;
        e = e > 0.0f ? e : 0.2f * e;
        m = fmaxf(m, e);
    }
    #pragma unroll
    for (int o = 16; o > 0; o >>= 1) m = fmaxf(m, __shfl_xor_sync(0xffffffffu, m, o));

    constexpr int R4 = F / 128;
    float4 acc[R4];
    #pragma unroll
    for (int j = 0; j < R4; j++) acc[j] = make_float4(0.f, 0.f, 0.f, 0.f);
    float den = 0.0f;
    const uint32_t c4 = lane * 4;

    int i = beg;
    for (; i + 1 < end; i += 2) {
        int s0 = g_csr_src[i], s1 = g_csr_src[i + 1];
        float e0 = g_ss[s0] + sd; e0 = e0 > 0.0f ? e0 : 0.2f * e0;
        float e1 = g_ss[s1] + sd; e1 = e1 > 0.0f ? e1 : 0.2f * e1;
        float ee0 = __expf(e0 - m), ee1 = __expf(e1 - m);
        den += ee0 + ee1;
        const float* h0 = h + (size_t)s0 * F + c4;
        const float* h1 = h + (size_t)s1 * F + c4;
        #pragma unroll
        for (int j = 0; j < R4; j++) {
            float4 v0 = *(const float4*)(h0 + j * 128);
            float4 v1 = *(const float4*)(h1 + j * 128);
            acc[j].x += ee0 * v0.x + ee1 * v1.x;
            acc[j].y += ee0 * v0.y + ee1 * v1.y;
            acc[j].z += ee0 * v0.z + ee1 * v1.z;
            acc[j].w += ee0 * v0.w + ee1 * v1.w;
        }
    }
    if (i < end) {
        int s0 = g_csr_src[i];
        float e0 = g_ss[s0] + sd; e0 = e0 > 0.0f ? e0 : 0.2f * e0;
        float ee0 = __expf(e0 - m);
        den += ee0;
        const float* h0 = h + (size_t)s0 * F + c4;
        #pragma unroll
        for (int j = 0; j < R4; j++) {
            float4 v0 = *(const float4*)(h0 + j * 128);
            acc[j].x += ee0 * v0.x; acc[j].y += ee0 * v0.y;
            acc[j].z += ee0 * v0.z; acc[j].w += ee0 * v0.w;
        }
    }

    float inv = 1.0f / den;
    #pragma unroll
    for (int j = 0; j < R4; j++) {
        float4 b4 = *(const float4*)(bias + j * 128 + c4);
        float v0 = fmaxf(acc[j].x * inv + b4.x, 0.0f);
        float v1 = fmaxf(acc[j].y * inv + b4.y, 0.0f);
        float v2 = fmaxf(acc[j].z * inv + b4.z, 0.0f);
        float v3 = fmaxf(acc[j].w * inv + b4.w, 0.0f);
        size_t o = (size_t)node * F + j * 128 + c4;
        if (OUT_F16) {
            __half2 p0, p1;
            p0.x = __float2half(v0); p0.y = __float2half(v1);
            p1.x = __float2half(v2); p1.y = __float2half(v3);
            *(__half2*)(oh + o)     = p0;
            *(__half2*)(oh + o + 2) = p1;
        } else {
            *(float4*)(outf + o) = make_float4(v0, v1, v2, v3);
        }
    }
}

// ==================== layer 3: skinny GEMM (smem W) + fused agg+logsoftmax ====================
__global__ void __launch_bounds__(256)
gemm3_kernel(const float* __restrict__ A, const float* __restrict__ W,
             float* __restrict__ C) {
    __shared__ float sW[H2 * NC];
    for (int i = threadIdx.x; i < H2 * NC; i += blockDim.x) sW[i] = W[i];
    __syncthreads();
    int node = blockIdx.x * blockDim.x + threadIdx.x;
    if (node >= N_NODES) return;
    const float4* a4 = (const float4*)(A + (size_t)node * H2);
    float acc[NC] = {0,0,0,0,0,0,0};
    #pragma unroll 4
    for (int k4 = 0; k4 < H2 / 4; k4++) {
        float4 a = a4[k4];
        const float* w0 = sW + (k4 * 4) * NC;
        #pragma unroll
        for (int c = 0; c < NC; c++)
            acc[c] += a.x * w0[c] + a.y * w0[NC + c] + a.z * w0[2 * NC + c] + a.w * w0[3 * NC + c];
    }
    #pragma unroll
    for (int c = 0; c < NC; c++) C[(size_t)node * NC + c] = acc[c];
}

__global__ void __launch_bounds__(256)
gat_agg3_final_kernel(const float* __restrict__ h, const float* __restrict__ bias,
                      float* __restrict__ out) {
    int node = blockIdx.x * 8 + (threadIdx.x >> 5);
    int lane = threadIdx.x & 31;
    if (node >= N_NODES) return;
    const int beg = g_rowoff[node], end = g_rowoff[node + 1];
    const float sd = g_sd[node];

    float m = -INFINITY;
    for (int i = beg + lane; i < end; i += 32) {
        float e = g_ss[g_csr_src[i]] + sd;
        e = e > 0.0f ? e : 0.2f * e;
        m = fmaxf(m, e);
    }
    #pragma unroll
    for (int o = 16; o > 0; o >>= 1) m = fmaxf(m, __shfl_xor_sync(0xffffffffu, m, o));

    float acc[NC] = {0,0,0,0,0,0,0};
    float den = 0.0f;
    for (int i = beg + lane; i < end; i += 32) {
        int s = g_csr_src[i];
        float e = g_ss[s] + sd;
        e = e > 0.0f ? e : 0.2f * e;
        float ee = __expf(e - m);
        den += ee;
        const float* hr = h + (size_t)s * NC;
        #pragma unroll
        for (int c = 0; c < NC; c++) acc[c] += ee * hr[c];
    }
    #pragma unroll
    for (int o = 16; o > 0; o >>= 1) {
        den += __shfl_xor_sync(0xffffffffu, den, o);
        #pragma unroll
        for (int c = 0; c < NC; c++) acc[c] += __shfl_xor_sync(0xffffffffu, acc[c], o);
    }
    if (lane == 0) {
        float inv = 1.0f / den;
        float z[NC], mx = -INFINITY;
        #pragma unroll
        for (int c = 0; c < NC; c++) {
            z[c] = acc[c] * inv + bias[c];
            mx = fmaxf(mx, z[c]);
        }
        float ssum = 0.0f;
        #pragma unroll
        for (int c = 0; c < NC; c++) ssum += __expf(z[c] - mx);
        float l = logf(ssum);
        float* o = out + (size_t)node * NC;
        #pragma unroll
        for (int c = 0; c < NC; c++) o[c] = z[c] - mx - l;
    }
}

// ==================== launcher ====================
extern "C" void kernel_launch(void* const* d_in, const int* in_sizes, int n_in,
                              void* d_out, int out_size) {
    const float* x   = (const float*)d_in[0];
    const void*  ei  = d_in[1];
    const float* W1  = (const float*)d_in[2];
    const float* as1 = (const float*)d_in[3];
    const float* ad1 = (const float*)d_in[4];
    const float* b1  = (const float*)d_in[5];
    const float* W2  = (const float*)d_in[6];
    const float* as2 = (const float*)d_in[7];
    const float* ad2 = (const float*)d_in[8];
    const float* b2  = (const float*)d_in[9];
    const float* W3  = (const float*)d_in[10];
    const float* as3 = (const float*)d_in[11];
    const float* ad3 = (const float*)d_in[12];
    const float* b3  = (const float*)d_in[13];
    float* out = (float*)d_out;

    float *buf1, *buf2;
    __half *a16, *bhi, *blo;
    cudaGetSymbolAddress((void**)&buf1, g_buf1);
    cudaGetSymbolAddress((void**)&buf2, g_buf2);
    cudaGetSymbolAddress((void**)&a16, g_A16);
    cudaGetSymbolAddress((void**)&bhi, g_Bhi);
    cudaGetSymbolAddress((void**)&blo, g_Blo);

    cudaFuncSetAttribute(gemm1_tc_kernel, cudaFuncAttributeMaxDynamicSharedMemorySize, G1_SMEM);
    cudaFuncSetAttribute(gemm_tc_kernel, cudaFuncAttributeMaxDynamicSharedMemorySize, SMEM_DYN);

    const int BT = 256;
    const int edge_blocks      = (NE + BT - 1) / BT;
    const int node_warp_blocks = (N_NODES + (BT / 32) - 1) / (BT / 32);
    const int node_blocks      = (N_NODES + BT - 1) / BT;

    // ---- CSR build ----
    detect_kernel<<<1, 128>>>((const unsigned int*)ei);
    zero_deg_kernel<<<node_blocks, BT>>>();
    prep_edges_kernel<<<edge_blocks, BT>>>(ei);
    reduce_deg_kernel<<<NB, 256>>>();
    scan_bsums_kernel<<<1, 256>>>();
    scan_write_kernel<<<NB, 256>>>();
    scatter_kernel<<<edge_blocks, BT>>>();

    // ---------------- layer 1: F_IN -> H1 ----------------
    split_Wt_kernel<<<2048, BT>>>(W1, F_IN, H1, K1PAD, bhi, blo);
    gemm1_tc_kernel<<<dim3(H1 / 128, MPAD / 128), BT, G1_SMEM>>>(x, bhi, blo, buf1);
    s_kernel_vec<<<node_warp_blocks, BT>>>(buf1, as1, ad1, H1);
    gat_agg_kernel<H1, 1><<<node_warp_blocks, BT>>>(buf1, b1, nullptr, a16);

    // ---------------- layer 2: H1 -> H2 ----------------
    split_Wt_kernel<<<2048, BT>>>(W2, H1, H2, H1, bhi, blo);
    gemm_tc_kernel<<<dim3(H2 / 128, MPAD / 128), BT, SMEM_DYN>>>(a16, bhi, blo, buf1, H1, H2);
    s_kernel_vec<<<node_warp_blocks, BT>>>(buf1, as2, ad2, H2);
    gat_agg_kernel<H2, 0><<<node_warp_blocks, BT>>>(buf1, b2, buf2, nullptr);

    // ---------------- layer 3: H2 -> NC ----------------
    gemm3_kernel<<<node_blocks, BT>>>(buf2, W3, buf1);
    s_kernel_scalar<<<node_warp_blocks, BT>>>(buf1, as3, ad3, NC);
    gat_agg3_final_kernel<<<node_warp_blocks, BT>>>(buf1, b3, out);
}

// round 12
// speedup vs baseline: 3.0612x; 1.0474x over previous
#include <cuda_runtime.h>
#include <cuda_fp16.h>
#include <math.h>
#include <stdint.h>

#define N_NODES 50000
#define MPAD    50048   // 391 * 128
#define E0      800000
#define NE      850000
#define F_IN    1433
#define K1PAD   1472    // 46 * 32
#define H1      512
#define H2      256
#define NC      7
#define NB      196     // ceil(N_NODES / 256)

// ==================== scratch (device globals) ====================
__device__ __half g_h16[(size_t)MPAD * H1];        // GEMM outputs (fp16)
__device__ __half g_A16[(size_t)MPAD * H1];        // aggregated activations (fp16, GEMM A)
__device__ __half g_Bhi[(size_t)H1 * K1PAD];
__device__ __half g_Blo[(size_t)H1 * K1PAD];
__device__ float g_buf1[(size_t)MPAD * NC];        // gemm3 out
__device__ float g_buf2[(size_t)MPAD * H2];        // agg2 out (gemm3 in)
__device__ float g_ss[N_NODES];
__device__ float g_sd[N_NODES];
__device__ int   g_src[NE];
__device__ int   g_dst[NE];
__device__ int   g_csr_src[NE];
__device__ int   g_deg[N_NODES];
__device__ int   g_rowoff[N_NODES + 1];
__device__ int   g_cursor[N_NODES];
__device__ int   g_bsum[NB];
__device__ int   g_boff[NB];
__device__ int   g_is64;

// ==================== PTX helpers (base-arch only) ====================
__device__ __forceinline__ uint32_t smem_u32(const void* p) {
    uint32_t a;
    asm("{ .reg .u64 t; cvta.to.shared.u64 t, %1; cvt.u32.u64 %0, t; }" : "=r"(a) : "l"(p));
    return a;
}
__device__ __forceinline__ void cp16(uint32_t dst, const void* src) {
    asm volatile("cp.async.cg.shared.global [%0], [%1], 16;" :: "r"(dst), "l"(src));
}
__device__ __forceinline__ void ldm_x4(uint32_t& r0, uint32_t& r1, uint32_t& r2, uint32_t& r3,
                                       uint32_t addr) {
    asm volatile("ldmatrix.sync.aligned.m8n8.x4.shared.b16 {%0,%1,%2,%3}, [%4];"
                 : "=r"(r0), "=r"(r1), "=r"(r2), "=r"(r3) : "r"(addr));
}
__device__ __forceinline__ void mma_f16(float* c, const uint32_t* a, const uint32_t* b) {
    asm volatile("mma.sync.aligned.m16n8k16.row.col.f32.f16.f16.f32 "
                 "{%0,%1,%2,%3}, {%4,%5,%6,%7}, {%8,%9}, {%0,%1,%2,%3};"
                 : "+f"(c[0]), "+f"(c[1]), "+f"(c[2]), "+f"(c[3])
                 : "r"(a[0]), "r"(a[1]), "r"(a[2]), "r"(a[3]), "r"(b[0]), "r"(b[1]));
}

// ==================== edge prep + CSR build ====================
__global__ void detect_kernel(const unsigned int* __restrict__ w) {
    __shared__ int nz;
    if (threadIdx.x == 0) nz = 0;
    __syncthreads();
    if (w[threadIdx.x * 2 + 1] != 0u) atomicOr(&nz, 1);
    __syncthreads();
    if (threadIdx.x == 0) g_is64 = (nz == 0);
}

__global__ void zero_deg_kernel() {
    int i = blockIdx.x * blockDim.x + threadIdx.x;
    if (i < N_NODES) g_deg[i] = 0;
}

__global__ void prep_edges_kernel(const void* __restrict__ ei) {
    int i = blockIdx.x * blockDim.x + threadIdx.x;
    if (i >= NE) return;
    int s, d;
    if (i < E0) {
        if (g_is64) {
            const long long* e = (const long long*)ei;
            s = (int)e[i]; d = (int)e[E0 + i];
        } else {
            const int* e = (const int*)ei;
            s = e[i]; d = e[E0 + i];
        }
    } else {
        s = d = i - E0;
    }
    s = min(max(s, 0), N_NODES - 1);
    d = min(max(d, 0), N_NODES - 1);
    g_src[i] = s;
    g_dst[i] = d;
    atomicAdd(&g_deg[d], 1);
}

__global__ void reduce_deg_kernel() {          // grid NB, 256
    __shared__ int sh[256];
    int i = blockIdx.x * 256 + threadIdx.x;
    sh[threadIdx.x] = (i < N_NODES) ? g_deg[i] : 0;
    __syncthreads();
    for (int o = 128; o > 0; o >>= 1) {
        if (threadIdx.x < o) sh[threadIdx.x] += sh[threadIdx.x + o];
        __syncthreads();
    }
    if (threadIdx.x == 0) g_bsum[blockIdx.x] = sh[0];
}

__global__ void scan_bsums_kernel() {          // 1 block, 256
    __shared__ int sh[256];
    int t = threadIdx.x;
    int mine = (t < NB) ? g_bsum[t] : 0;
    sh[t] = mine;
    __syncthreads();
    for (int o = 1; o < 256; o <<= 1) {
        int v = (t >= o) ? sh[t - o] : 0;
        __syncthreads();
        sh[t] += v;
        __syncthreads();
    }
    if (t < NB) g_boff[t] = sh[t] - mine;      // exclusive
    if (t == 0) g_rowoff[N_NODES] = NE;
}

__global__ void scan_write_kernel() {          // grid NB, 256
    __shared__ int sh[256];
    int i = blockIdx.x * 256 + threadIdx.x;
    int v = (i < N_NODES) ? g_deg[i] : 0;
    sh[threadIdx.x] = v;
    __syncthreads();
    for (int o = 1; o < 256; o <<= 1) {
        int u = (threadIdx.x >= o) ? sh[threadIdx.x - o] : 0;
        __syncthreads();
        sh[threadIdx.x] += u;
        __syncthreads();
    }
    if (i < N_NODES) {
        int excl = g_boff[blockIdx.x] + sh[threadIdx.x] - v;
        g_rowoff[i] = excl;
        g_cursor[i] = excl;
    }
}

__global__ void scatter_kernel() {
    int i = blockIdx.x * blockDim.x + threadIdx.x;
    if (i >= NE) return;
    int pos = atomicAdd(&g_cursor[g_dst[i]], 1);
    g_csr_src[pos] = g_src[i];
}

// ==================== weight split (fp16 hi/lo) ====================
__global__ void split_Wt_kernel(const float* __restrict__ W, int K, int N, int Kpad,
                                __half* __restrict__ hi, __half* __restrict__ lo) {
    size_t total = (size_t)N * Kpad;
    size_t i = (size_t)blockIdx.x * blockDim.x + threadIdx.x;
    size_t stride = (size_t)gridDim.x * blockDim.x;
    for (; i < total; i += stride) {
        int n = (int)(i / Kpad), k = (int)(i % Kpad);
        float v = (k < K) ? W[(size_t)k * N + n] : 0.0f;
        __half h = __float2half(v);
        hi[i] = h;
        lo[i] = __float2half(v - __half2float(h));
    }
}

// ==================== GEMM common ====================
#define KC        32
#define SPITCH    80
#define ARR_BYTES (128 * SPITCH)    // 10240

// ---------- layer-1 GEMM: fp32 A loaded + converted to fp16 in-kernel, fp16 out ----------
#define G1_OFF_A  0
#define G1_B(s)   (ARR_BYTES + (s) * 2 * ARR_BYTES)
#define G1_SMEM   (5 * ARR_BYTES)   // 51200

__global__ void __launch_bounds__(256)
gemm1_tc_kernel(const float* __restrict__ Af,
                const __half* __restrict__ Bhi, const __half* __restrict__ Blo,
                __half* __restrict__ C16) {
    extern __shared__ char smem[];
    const uint32_t sb = smem_u32(smem);
    const int tid = threadIdx.x;
    const int wid = tid >> 5, lane = tid & 31;
    const int warp_m = wid & 3, warp_n = wid >> 2;
    const int m0 = blockIdx.y * 128;
    const int n0 = blockIdx.x * 128;
    const int nchunks = K1PAD / KC;   // 46

    const int row0 = tid >> 2, seg = tid & 3;
    const int row1 = row0 + 64;
    const uint32_t bs0 = (uint32_t)row0 * SPITCH + seg * 16;
    const uint32_t bs1 = (uint32_t)row1 * SPITCH + seg * 16;
    const size_t gB0 = (size_t)(n0 + row0) * K1PAD + seg * 8;
    const size_t gB1 = (size_t)(n0 + row1) * K1PAD + seg * 8;

    const int arow = tid >> 1;
    const int acol0 = (tid & 1) * 16;
    const bool row_ok = (m0 + arow) < N_NODES;
    const float* arow_ptr = Af + (size_t)(m0 + arow) * F_IN;

    const int lr = lane & 7, g = lane >> 3;
    const uint32_t offA = (uint32_t)(warp_m * 32 + lr + (g & 1) * 8) * SPITCH + (g >> 1) * 16;
    const uint32_t offB = (uint32_t)(warp_n * 64 + lr + (g >> 1) * 8) * SPITCH + (g & 1) * 16;

    float acc[2][8][4];
    #pragma unroll
    for (int mi = 0; mi < 2; mi++)
        #pragma unroll
        for (int ni = 0; ni < 8; ni++)
            #pragma unroll
            for (int q = 0; q < 4; q++) acc[mi][ni][q] = 0.0f;

    float areg[16];
    {
        const uint32_t d = sb + G1_B(0);
        cp16(d + bs0, Bhi + gB0); cp16(d + bs1, Bhi + gB1);
        cp16(d + ARR_BYTES + bs0, Blo + gB0); cp16(d + ARR_BYTES + bs1, Blo + gB1);
        asm volatile("cp.async.commit_group;");
        if (row_ok) {
            #pragma unroll
            for (int j = 0; j < 16; j++) areg[j] = arow_ptr[acol0 + j];
        } else {
            #pragma unroll
            for (int j = 0; j < 16; j++) areg[j] = 0.0f;
        }
    }

    char* const aDst = smem + G1_OFF_A + (size_t)arow * SPITCH + acol0 * 2;

    for (int c = 0; c < nchunks; c++) {
        #pragma unroll
        for (int j = 0; j < 8; j++) {
            __half2 hh;
            hh.x = __float2half(areg[2 * j]);
            hh.y = __float2half(areg[2 * j + 1]);
            *(__half2*)(aDst + j * 4) = hh;
        }
        if (c + 1 < nchunks) {
            const uint32_t d = sb + G1_B((c + 1) & 1);
            const size_t ko = (size_t)(c + 1) * KC;
            cp16(d + bs0, Bhi + gB0 + ko); cp16(d + bs1, Bhi + gB1 + ko);
            cp16(d + ARR_BYTES + bs0, Blo + gB0 + ko); cp16(d + ARR_BYTES + bs1, Blo + gB1 + ko);
            asm volatile("cp.async.commit_group;");
            const int cb = (c + 1) * KC + acol0;
            if (row_ok && cb + 16 <= F_IN) {
                #pragma unroll
                for (int j = 0; j < 16; j++) areg[j] = arow_ptr[cb + j];
            } else if (row_ok) {
                #pragma unroll
                for (int j = 0; j < 16; j++) areg[j] = (cb + j < F_IN) ? arow_ptr[cb + j] : 0.0f;
            } else {
                #pragma unroll
                for (int j = 0; j < 16; j++) areg[j] = 0.0f;
            }
            asm volatile("cp.async.wait_group 1;");
        } else {
            asm volatile("cp.async.wait_group 0;");
        }
        __syncthreads();

        const uint32_t bbase = sb + G1_B(c & 1);
        #pragma unroll
        for (int ks = 0; ks < 2; ks++) {
            const uint32_t kadd = ks * 32;
            uint32_t a16[2][4], bhi[8][2], blo[8][2];
            #pragma unroll
            for (int mt = 0; mt < 2; mt++)
                ldm_x4(a16[mt][0], a16[mt][1], a16[mt][2], a16[mt][3],
                       sb + G1_OFF_A + offA + mt * 16 * SPITCH + kadd);
            #pragma unroll
            for (int np = 0; np < 4; np++) {
                ldm_x4(bhi[2*np][0], bhi[2*np][1], bhi[2*np+1][0], bhi[2*np+1][1],
                       bbase + offB + np * 16 * SPITCH + kadd);
                ldm_x4(blo[2*np][0], blo[2*np][1], blo[2*np+1][0], blo[2*np+1][1],
                       bbase + ARR_BYTES + offB + np * 16 * SPITCH + kadd);
            }
            #pragma unroll
            for (int mi = 0; mi < 2; mi++)
                #pragma unroll
                for (int ni = 0; ni < 8; ni++) {
                    mma_f16(acc[mi][ni], a16[mi], bhi[ni]);
                    mma_f16(acc[mi][ni], a16[mi], blo[ni]);
                }
        }
        __syncthreads();
    }

    const int er = lane >> 2, ec = (lane & 3) * 2;
    #pragma unroll
    for (int mi = 0; mi < 2; mi++) {
        const int r_lo = m0 + warp_m * 32 + mi * 16 + er;
        #pragma unroll
        for (int ni = 0; ni < 8; ni++) {
            const int cc = n0 + warp_n * 64 + ni * 8 + ec;
            __half2 p0, p1;
            p0.x = __float2half(acc[mi][ni][0]); p0.y = __float2half(acc[mi][ni][1]);
            p1.x = __float2half(acc[mi][ni][2]); p1.y = __float2half(acc[mi][ni][3]);
            *(__half2*)(C16 + (size_t)r_lo * H1 + cc)       = p0;
            *(__half2*)(C16 + (size_t)(r_lo + 8) * H1 + cc) = p1;
        }
    }
}

// ---------- layer-2 GEMM: fp16 A (cp.async), fp16 B hi/lo, fp16 out ----------
#define STG_BYTES (3 * ARR_BYTES)   // 30720
#define OFF_A16   0
#define OFF_BHI   ARR_BYTES
#define OFF_BLO   (2 * ARR_BYTES)
#define SMEM_DYN  (2 * STG_BYTES)   // 61440

__global__ void __launch_bounds__(256)
gemm_tc_kernel(const __half* __restrict__ A16,
               const __half* __restrict__ Bhi, const __half* __restrict__ Blo,
               __half* __restrict__ C16, int Kpad, int Nc) {
    extern __shared__ char smem[];
    const uint32_t sb = smem_u32(smem);
    const int tid = threadIdx.x;
    const int wid = tid >> 5, lane = tid & 31;
    const int warp_m = wid & 3, warp_n = wid >> 2;
    const int m0 = blockIdx.y * 128;
    const int n0 = blockIdx.x * 128;
    const int nchunks = Kpad / KC;

    const int row0 = tid >> 2, seg = tid & 3;
    const int row1 = row0 + 64;
    const uint32_t s0 = (uint32_t)row0 * SPITCH + seg * 16;
    const uint32_t s1 = (uint32_t)row1 * SPITCH + seg * 16;
    const size_t gA0 = (size_t)(m0 + row0) * Kpad + seg * 8;
    const size_t gA1 = (size_t)(m0 + row1) * Kpad + seg * 8;
    const size_t gB0 = (size_t)(n0 + row0) * Kpad + seg * 8;
    const size_t gB1 = (size_t)(n0 + row1) * Kpad + seg * 8;

    const int lr = lane & 7, g = lane >> 3;
    const uint32_t offA = (uint32_t)(warp_m * 32 + lr + (g & 1) * 8) * SPITCH + (g >> 1) * 16;
    const uint32_t offB = (uint32_t)(warp_n * 64 + lr + (g >> 1) * 8) * SPITCH + (g & 1) * 16;

    float acc[2][8][4];
    #pragma unroll
    for (int mi = 0; mi < 2; mi++)
        #pragma unroll
        for (int ni = 0; ni < 8; ni++)
            #pragma unroll
            for (int q = 0; q < 4; q++) acc[mi][ni][q] = 0.0f;

    {
        const uint32_t d = sb;
        cp16(d + OFF_A16 + s0, A16 + gA0); cp16(d + OFF_A16 + s1, A16 + gA1);
        cp16(d + OFF_BHI + s0, Bhi + gB0); cp16(d + OFF_BHI + s1, Bhi + gB1);
        cp16(d + OFF_BLO + s0, Blo + gB0); cp16(d + OFF_BLO + s1, Blo + gB1);
        asm volatile("cp.async.commit_group;");
    }

    for (int c = 0; c < nchunks; c++) {
        if (c + 1 < nchunks) {
            const uint32_t d = sb + ((c + 1) & 1) * STG_BYTES;
            const size_t ko = (size_t)(c + 1) * KC;
            cp16(d + OFF_A16 + s0, A16 + gA0 + ko); cp16(d + OFF_A16 + s1, A16 + gA1 + ko);
            cp16(d + OFF_BHI + s0, Bhi + gB0 + ko); cp16(d + OFF_BHI + s1, Bhi + gB1 + ko);
            cp16(d + OFF_BLO + s0, Blo + gB0 + ko); cp16(d + OFF_BLO + s1, Blo + gB1 + ko);
            asm volatile("cp.async.commit_group;");
            asm volatile("cp.async.wait_group 1;");
        } else {
            asm volatile("cp.async.wait_group 0;");
        }
        __syncthreads();

        const uint32_t base = sb + (c & 1) * STG_BYTES;
        #pragma unroll
        for (int ks = 0; ks < 2; ks++) {
            const uint32_t kadd = ks * 32;
            uint32_t a16[2][4], bhi[8][2], blo[8][2];
            #pragma unroll
            for (int mt = 0; mt < 2; mt++)
                ldm_x4(a16[mt][0], a16[mt][1], a16[mt][2], a16[mt][3],
                       base + OFF_A16 + offA + mt * 16 * SPITCH + kadd);
            #pragma unroll
            for (int np = 0; np < 4; np++) {
                ldm_x4(bhi[2*np][0], bhi[2*np][1], bhi[2*np+1][0], bhi[2*np+1][1],
                       base + OFF_BHI + offB + np * 16 * SPITCH + kadd);
                ldm_x4(blo[2*np][0], blo[2*np][1], blo[2*np+1][0], blo[2*np+1][1],
                       base + OFF_BLO + offB + np * 16 * SPITCH + kadd);
            }
            #pragma unroll
            for (int mi = 0; mi < 2; mi++)
                #pragma unroll
                for (int ni = 0; ni < 8; ni++) {
                    mma_f16(acc[mi][ni], a16[mi], bhi[ni]);
                    mma_f16(acc[mi][ni], a16[mi], blo[ni]);
                }
        }
        __syncthreads();
    }

    const int er = lane >> 2, ec = (lane & 3) * 2;
    #pragma unroll
    for (int mi = 0; mi < 2; mi++) {
        const int r_lo = m0 + warp_m * 32 + mi * 16 + er;
        #pragma unroll
        for (int ni = 0; ni < 8; ni++) {
            const int cc = n0 + warp_n * 64 + ni * 8 + ec;
            __half2 p0, p1;
            p0.x = __float2half(acc[mi][ni][0]); p0.y = __float2half(acc[mi][ni][1]);
            p1.x = __float2half(acc[mi][ni][2]); p1.y = __float2half(acc[mi][ni][3]);
            *(__half2*)(C16 + (size_t)r_lo * Nc + cc)       = p0;
            *(__half2*)(C16 + (size_t)(r_lo + 8) * Nc + cc) = p1;
        }
    }
}

// ==================== attention scores (fp16 h) ====================
__global__ void s_kernel_h16(const __half* __restrict__ h, const float* __restrict__ a_s,
                             const float* __restrict__ a_d, int F) {
    int node = blockIdx.x * (blockDim.x >> 5) + (threadIdx.x >> 5);
    int lane = threadIdx.x & 31;
    if (node >= N_NODES) return;
    const __half* hr = h + (size_t)node * F;
    float vs = 0.0f, vd = 0.0f;
    for (int f = lane * 8; f < F; f += 256) {
        uint4 raw = *(const uint4*)(hr + f);
        const __half2* hp = (const __half2*)&raw;
        #pragma unroll
        for (int q = 0; q < 4; q++) {
            float2 v = __half22float2(hp[q]);
            float2 as2 = *(const float2*)(a_s + f + q * 2);
            float2 ad2 = *(const float2*)(a_d + f + q * 2);
            vs += v.x * as2.x + v.y * as2.y;
            vd += v.x * ad2.x + v.y * ad2.y;
        }
    }
    #pragma unroll
    for (int o = 16; o > 0; o >>= 1) {
        vs += __shfl_down_sync(0xffffffffu, vs, o);
        vd += __shfl_down_sync(0xffffffffu, vd, o);
    }
    if (lane == 0) {
        g_ss[node] = vs;
        g_sd[node] = vd;
    }
}

__global__ void s_kernel_scalar(const float* __restrict__ h, const float* __restrict__ a_s,
                                const float* __restrict__ a_d, int F) {
    int node = blockIdx.x * (blockDim.x >> 5) + (threadIdx.x >> 5);
    int lane = threadIdx.x & 31;
    if (node >= N_NODES) return;
    const float* hr = h + (size_t)node * F;
    float vs = 0.0f, vd = 0.0f;
    for (int f = lane; f < F; f += 32) {
        float x = hr[f];
        vs += x * a_s[f];
        vd += x * a_d[f];
    }
    #pragma unroll
    for (int o = 16; o > 0; o >>= 1) {
        vs += __shfl_down_sync(0xffffffffu, vs, o);
        vd += __shfl_down_sync(0xffffffffu, vd, o);
    }
    if (lane == 0) {
        g_ss[node] = vs;
        g_sd[node] = vd;
    }
}

// ==================== fused GAT aggregation (warp per node, fp16 h) ====================
// OUT_F16=1: write fp16 (next GEMM's A). OUT_F16=0: write fp32.
template <int F, int OUT_F16>
__global__ void __launch_bounds__(256)
gat_agg_kernel(const __half* __restrict__ h, const float* __restrict__ bias,
               float* __restrict__ outf, __half* __restrict__ oh) {
    int node = blockIdx.x * 8 + (threadIdx.x >> 5);
    int lane = threadIdx.x & 31;
    if (node >= N_NODES) return;
    const int beg = g_rowoff[node], end = g_rowoff[node + 1];
    const float sd = g_sd[node];

    float m = -INFINITY;
    for (int i = beg + lane; i < end; i += 32) {
        float e = g_ss[g_csr_src[i]] + sd;
        e = e > 0.0f ? e : 0.2f * e;
        m = fmaxf(m, e);
    }
    #pragma unroll
    for (int o = 16; o > 0; o >>= 1) m = fmaxf(m, __shfl_xor_sync(0xffffffffu, m, o));

    constexpr int R8 = F / 256;     // 16B (8 halves) per lane per iter
    float acc[R8][8];
    #pragma unroll
    for (int j = 0; j < R8; j++)
        #pragma unroll
        for (int q = 0; q < 8; q++) acc[j][q] = 0.0f;
    float den = 0.0f;
    const uint32_t c8 = lane * 8;

    int i = beg;
    for (; i + 1 < end; i += 2) {
        int s0 = g_csr_src[i], s1 = g_csr_src[i + 1];
        float e0 = g_ss[s0] + sd; e0 = e0 > 0.0f ? e0 : 0.2f * e0;
        float e1 = g_ss[s1] + sd; e1 = e1 > 0.0f ? e1 : 0.2f * e1;
        float ee0 = __expf(e0 - m), ee1 = __expf(e1 - m);
        den += ee0 + ee1;
        const __half* h0 = h + (size_t)s0 * F + c8;
        const __half* h1 = h + (size_t)s1 * F + c8;
        #pragma unroll
        for (int j = 0; j < R8; j++) {
            uint4 r0 = *(const uint4*)(h0 + j * 256);
            uint4 r1 = *(const uint4*)(h1 + j * 256);
            const __half2* p0 = (const __half2*)&r0;
            const __half2* p1 = (const __half2*)&r1;
            #pragma unroll
            for (int q = 0; q < 4; q++) {
                float2 v0 = __half22float2(p0[q]);
                float2 v1 = __half22float2(p1[q]);
                acc[j][2*q+0] += ee0 * v0.x + ee1 * v1.x;
                acc[j][2*q+1] += ee0 * v0.y + ee1 * v1.y;
            }
        }
    }
    if (i < end) {
        int s0 = g_csr_src[i];
        float e0 = g_ss[s0] + sd; e0 = e0 > 0.0f ? e0 : 0.2f * e0;
        float ee0 = __expf(e0 - m);
        den += ee0;
        const __half* h0 = h + (size_t)s0 * F + c8;
        #pragma unroll
        for (int j = 0; j < R8; j++) {
            uint4 r0 = *(const uint4*)(h0 + j * 256);
            const __half2* p0 = (const __half2*)&r0;
            #pragma unroll
            for (int q = 0; q < 4; q++) {
                float2 v0 = __half22float2(p0[q]);
                acc[j][2*q+0] += ee0 * v0.x;
                acc[j][2*q+1] += ee0 * v0.y;
            }
        }
    }

    float inv = 1.0f / den;
    #pragma unroll
    for (int j = 0; j < R8; j++) {
        float v[8];
        #pragma unroll
        for (int q = 0; q < 8; q++) {
            v[q] = fmaxf(acc[j][q] * inv + bias[j * 256 + c8 + q], 0.0f);
        }
        size_t o = (size_t)node * F + j * 256 + c8;
        if (OUT_F16) {
            uint4 packed;
            __half2* hp = (__half2*)&packed;
            #pragma unroll
            for (int q = 0; q < 4; q++) {
                __half2 p;
                p.x = __float2half(v[2*q]); p.y = __float2half(v[2*q+1]);
                hp[q] = p;
            }
            *(uint4*)(oh + o) = packed;
        } else {
            *(float4*)(outf + o)     = make_float4(v[0], v[1], v[2], v[3]);
            *(float4*)(outf + o + 4) = make_float4(v[4], v[5], v[6], v[7]);
        }
    }
}

// ==================== layer 3: skinny GEMM (smem W) + fused agg+logsoftmax ====================
__global__ void __launch_bounds__(256)
gemm3_kernel(const float* __restrict__ A, const float* __restrict__ W,
             float* __restrict__ C) {
    __shared__ float sW[H2 * NC];
    for (int i = threadIdx.x; i < H2 * NC; i += blockDim.x) sW[i] = W[i];
    __syncthreads();
    int node = blockIdx.x * blockDim.x + threadIdx.x;
    if (node >= N_NODES) return;
    const float4* a4 = (const float4*)(A + (size_t)node * H2);
    float acc[NC] = {0,0,0,0,0,0,0};
    #pragma unroll 4
    for (int k4 = 0; k4 < H2 / 4; k4++) {
        float4 a = a4[k4];
        const float* w0 = sW + (k4 * 4) * NC;
        #pragma unroll
        for (int c = 0; c < NC; c++)
            acc[c] += a.x * w0[c] + a.y * w0[NC + c] + a.z * w0[2 * NC + c] + a.w * w0[3 * NC + c];
    }
    #pragma unroll
    for (int c = 0; c < NC; c++) C[(size_t)node * NC + c] = acc[c];
}

__global__ void __launch_bounds__(256)
gat_agg3_final_kernel(const float* __restrict__ h, const float* __restrict__ bias,
                      float* __restrict__ out) {
    int node = blockIdx.x * 8 + (threadIdx.x >> 5);
    int lane = threadIdx.x & 31;
    if (node >= N_NODES) return;
    const int beg = g_rowoff[node], end = g_rowoff[node + 1];
    const float sd = g_sd[node];

    float m = -INFINITY;
    for (int i = beg + lane; i < end; i += 32) {
        float e = g_ss[g_csr_src[i]] + sd;
        e = e > 0.0f ? e : 0.2f * e;
        m = fmaxf(m, e);
    }
    #pragma unroll
    for (int o = 16; o > 0; o >>= 1) m = fmaxf(m, __shfl_xor_sync(0xffffffffu, m, o));

    float acc[NC] = {0,0,0,0,0,0,0};
    float den = 0.0f;
    for (int i = beg + lane; i < end; i += 32) {
        int s = g_csr_src[i];
        float e = g_ss[s] + sd;
        e = e > 0.0f ? e : 0.2f * e;
        float ee = __expf(e - m);
        den += ee;
        const float* hr = h + (size_t)s * NC;
        #pragma unroll
        for (int c = 0; c < NC; c++) acc[c] += ee * hr[c];
    }
    #pragma unroll
    for (int o = 16; o > 0; o >>= 1) {
        den += __shfl_xor_sync(0xffffffffu, den, o);
        #pragma unroll
        for (int c = 0; c < NC; c++) acc[c] += __shfl_xor_sync(0xffffffffu, acc[c], o);
    }
    if (lane == 0) {
        float inv = 1.0f / den;
        float z[NC], mx = -INFINITY;
        #pragma unroll
        for (int c = 0; c < NC; c++) {
            z[c] = acc[c] * inv + bias[c];
            mx = fmaxf(mx, z[c]);
        }
        float ssum = 0.0f;
        #pragma unroll
        for (int c = 0; c < NC; c++) ssum += __expf(z[c] - mx);
        float l = logf(ssum);
        float* o = out + (size_t)node * NC;
        #pragma unroll
        for (int c = 0; c < NC; c++) o[c] = z[c] - mx - l;
    }
}

// ==================== launcher ====================
extern "C" void kernel_launch(void* const* d_in, const int* in_sizes, int n_in,
                              void* d_out, int out_size) {
    const float* x   = (const float*)d_in[0];
    const void*  ei  = d_in[1];
    const float* W1  = (const float*)d_in[2];
    const float* as1 = (const float*)d_in[3];
    const float* ad1 = (const float*)d_in[4];
    const float* b1  = (const float*)d_in[5];
    const float* W2  = (const float*)d_in[6];
    const float* as2 = (const float*)d_in[7];
    const float* ad2 = (const float*)d_in[8];
    const float* b2  = (const float*)d_in[9];
    const float* W3  = (const float*)d_in[10];
    const float* as3 = (const float*)d_in[11];
    const float* ad3 = (const float*)d_in[12];
    const float* b3  = (const float*)d_in[13];
    float* out = (float*)d_out;

    float *buf1, *buf2;
    __half *h16, *a16, *bhi, *blo;
    cudaGetSymbolAddress((void**)&buf1, g_buf1);
    cudaGetSymbolAddress((void**)&buf2, g_buf2);
    cudaGetSymbolAddress((void**)&h16, g_h16);
    cudaGetSymbolAddress((void**)&a16, g_A16);
    cudaGetSymbolAddress((void**)&bhi, g_Bhi);
    cudaGetSymbolAddress((void**)&blo, g_Blo);

    cudaFuncSetAttribute(gemm1_tc_kernel, cudaFuncAttributeMaxDynamicSharedMemorySize, G1_SMEM);
    cudaFuncSetAttribute(gemm_tc_kernel, cudaFuncAttributeMaxDynamicSharedMemorySize, SMEM_DYN);

    const int BT = 256;
    const int edge_blocks      = (NE + BT - 1) / BT;
    const int node_warp_blocks = (N_NODES + (BT / 32) - 1) / (BT / 32);
    const int node_blocks      = (N_NODES + BT - 1) / BT;

    // ---- CSR build ----
    detect_kernel<<<1, 128>>>((const unsigned int*)ei);
    zero_deg_kernel<<<node_blocks, BT>>>();
    prep_edges_kernel<<<edge_blocks, BT>>>(ei);
    reduce_deg_kernel<<<NB, 256>>>();
    scan_bsums_kernel<<<1, 256>>>();
    scan_write_kernel<<<NB, 256>>>();
    scatter_kernel<<<edge_blocks, BT>>>();

    // ---------------- layer 1: F_IN -> H1 ----------------
    split_Wt_kernel<<<2048, BT>>>(W1, F_IN, H1, K1PAD, bhi, blo);
    gemm1_tc_kernel<<<dim3(H1 / 128, MPAD / 128), BT, G1_SMEM>>>(x, bhi, blo, h16);
    s_kernel_h16<<<node_warp_blocks, BT>>>(h16, as1, ad1, H1);
    gat_agg_kernel<H1, 1><<<node_warp_blocks, BT>>>(h16, b1, nullptr, a16);

    // ---------------- layer 2: H1 -> H2 ----------------
    split_Wt_kernel<<<2048, BT>>>(W2, H1, H2, H1, bhi, blo);
    gemm_tc_kernel<<<dim3(H2 / 128, MPAD / 128), BT, SMEM_DYN>>>(a16, bhi, blo, h16, H1, H2);
    s_kernel_h16<<<node_warp_blocks, BT>>>(h16, as2, ad2, H2);
    gat_agg_kernel<H2, 0><<<node_warp_blocks, BT>>>(h16, b2, buf2, nullptr);

    // ---------------- layer 3: H2 -> NC ----------------
    gemm3_kernel<<<node_blocks, BT>>>(buf2, W3, buf1);
    s_kernel_scalar<<<node_warp_blocks, BT>>>(buf1, as3, ad3, NC);
    gat_agg3_final_kernel<<<node_warp_blocks, BT>>>(buf1, b3, out);
}

// round 13
// speedup vs baseline: 3.1055x; 1.0144x over previous
#include <cuda_runtime.h>
#include <cuda_fp16.h>
#include <math.h>
#include <stdint.h>

#define N_NODES 50000
#define MPAD    50048   // 391 * 128
#define E0      800000
#define NE      850000
#define F_IN    1433
#define K1PAD   1472    // 46 * 32
#define H1      512
#define H2      256
#define NC      7
#define NB      196     // ceil(N_NODES / 256)

// ==================== scratch (device globals) ====================
__device__ __half g_h16[(size_t)MPAD * H1];
__device__ __half g_A16[(size_t)MPAD * H1];
__device__ __half g_Bhi[(size_t)H1 * K1PAD];
__device__ __half g_Blo[(size_t)H1 * K1PAD];
__device__ float g_buf1[(size_t)MPAD * NC];
__device__ float g_buf2[(size_t)MPAD * H2];
__device__ float g_ss[N_NODES];
__device__ float g_sd[N_NODES];
__device__ float g_alpha[NE];
__device__ int   g_src[NE];
__device__ int   g_dst[NE];
__device__ int   g_csr_src[NE];
__device__ int   g_deg[N_NODES];
__device__ int   g_rowoff[N_NODES + 1];
__device__ int   g_cursor[N_NODES];
__device__ int   g_bsum[NB];
__device__ int   g_boff[NB];
__device__ int   g_is64;

// ==================== PTX helpers (base-arch only) ====================
__device__ __forceinline__ uint32_t smem_u32(const void* p) {
    uint32_t a;
    asm("{ .reg .u64 t; cvta.to.shared.u64 t, %1; cvt.u32.u64 %0, t; }" : "=r"(a) : "l"(p));
    return a;
}
__device__ __forceinline__ void cp16(uint32_t dst, const void* src) {
    asm volatile("cp.async.cg.shared.global [%0], [%1], 16;" :: "r"(dst), "l"(src));
}
__device__ __forceinline__ void ldm_x4(uint32_t& r0, uint32_t& r1, uint32_t& r2, uint32_t& r3,
                                       uint32_t addr) {
    asm volatile("ldmatrix.sync.aligned.m8n8.x4.shared.b16 {%0,%1,%2,%3}, [%4];"
                 : "=r"(r0), "=r"(r1), "=r"(r2), "=r"(r3) : "r"(addr));
}
__device__ __forceinline__ void mma_f16(float* c, const uint32_t* a, const uint32_t* b) {
    asm volatile("mma.sync.aligned.m16n8k16.row.col.f32.f16.f16.f32 "
                 "{%0,%1,%2,%3}, {%4,%5,%6,%7}, {%8,%9}, {%0,%1,%2,%3};"
                 : "+f"(c[0]), "+f"(c[1]), "+f"(c[2]), "+f"(c[3])
                 : "r"(a[0]), "r"(a[1]), "r"(a[2]), "r"(a[3]), "r"(b[0]), "r"(b[1]));
}

// ==================== edge prep + CSR build ====================
__global__ void detect_kernel(const unsigned int* __restrict__ w) {
    __shared__ int nz;
    if (threadIdx.x == 0) nz = 0;
    __syncthreads();
    if (w[threadIdx.x * 2 + 1] != 0u) atomicOr(&nz, 1);
    __syncthreads();
    if (threadIdx.x == 0) g_is64 = (nz == 0);
}

__global__ void zero_deg_kernel() {
    int i = blockIdx.x * blockDim.x + threadIdx.x;
    if (i < N_NODES) g_deg[i] = 0;
}

__global__ void prep_edges_kernel(const void* __restrict__ ei) {
    int i = blockIdx.x * blockDim.x + threadIdx.x;
    if (i >= NE) return;
    int s, d;
    if (i < E0) {
        if (g_is64) {
            const long long* e = (const long long*)ei;
            s = (int)e[i]; d = (int)e[E0 + i];
        } else {
            const int* e = (const int*)ei;
            s = e[i]; d = e[E0 + i];
        }
    } else {
        s = d = i - E0;
    }
    s = min(max(s, 0), N_NODES - 1);
    d = min(max(d, 0), N_NODES - 1);
    g_src[i] = s;
    g_dst[i] = d;
    atomicAdd(&g_deg[d], 1);
}

__global__ void reduce_deg_kernel() {          // grid NB, 256
    __shared__ int sh[256];
    int i = blockIdx.x * 256 + threadIdx.x;
    sh[threadIdx.x] = (i < N_NODES) ? g_deg[i] : 0;
    __syncthreads();
    for (int o = 128; o > 0; o >>= 1) {
        if (threadIdx.x < o) sh[threadIdx.x] += sh[threadIdx.x + o];
        __syncthreads();
    }
    if (threadIdx.x == 0) g_bsum[blockIdx.x] = sh[0];
}

__global__ void scan_bsums_kernel() {          // 1 block, 256
    __shared__ int sh[256];
    int t = threadIdx.x;
    int mine = (t < NB) ? g_bsum[t] : 0;
    sh[t] = mine;
    __syncthreads();
    for (int o = 1; o < 256; o <<= 1) {
        int v = (t >= o) ? sh[t - o] : 0;
        __syncthreads();
        sh[t] += v;
        __syncthreads();
    }
    if (t < NB) g_boff[t] = sh[t] - mine;
    if (t == 0) g_rowoff[N_NODES] = NE;
}

__global__ void scan_write_kernel() {          // grid NB, 256
    __shared__ int sh[256];
    int i = blockIdx.x * 256 + threadIdx.x;
    int v = (i < N_NODES) ? g_deg[i] : 0;
    sh[threadIdx.x] = v;
    __syncthreads();
    for (int o = 1; o < 256; o <<= 1) {
        int u = (threadIdx.x >= o) ? sh[threadIdx.x - o] : 0;
        __syncthreads();
        sh[threadIdx.x] += u;
        __syncthreads();
    }
    if (i < N_NODES) {
        int excl = g_boff[blockIdx.x] + sh[threadIdx.x] - v;
        g_rowoff[i] = excl;
        g_cursor[i] = excl;
    }
}

__global__ void scatter_kernel() {
    int i = blockIdx.x * blockDim.x + threadIdx.x;
    if (i >= NE) return;
    int pos = atomicAdd(&g_cursor[g_dst[i]], 1);
    g_csr_src[pos] = g_src[i];
}

// ==================== weight split (fp16 hi/lo) ====================
__global__ void split_Wt_kernel(const float* __restrict__ W, int K, int N, int Kpad,
                                __half* __restrict__ hi, __half* __restrict__ lo) {
    size_t total = (size_t)N * Kpad;
    size_t i = (size_t)blockIdx.x * blockDim.x + threadIdx.x;
    size_t stride = (size_t)gridDim.x * blockDim.x;
    for (; i < total; i += stride) {
        int n = (int)(i / Kpad), k = (int)(i % Kpad);
        float v = (k < K) ? W[(size_t)k * N + n] : 0.0f;
        __half h = __float2half(v);
        hi[i] = h;
        lo[i] = __float2half(v - __half2float(h));
    }
}

// ==================== GEMM common ====================
#define KC        32
#define SPITCH    80
#define ARR_BYTES (128 * SPITCH)     // 10240 (128-row arrays)
#define B1_BYTES  (256 * SPITCH)     // 20480 (256-row B arrays for gemm1)

// ---------- layer-1 GEMM: CTA tile 128x256, 512 threads, fp32 A converted in-kernel ----------
// smem: A16 [0,10240), B stage s at 10240 + s*40960 (BHI +0, BLO +20480)
#define G1_OFF_A  0
#define G1_B(s)   (ARR_BYTES + (s) * 2 * B1_BYTES)
#define G1_SMEM   (ARR_BYTES + 4 * B1_BYTES)   // 92160

__global__ void __launch_bounds__(512)
gemm1_tc_kernel(const float* __restrict__ Af,
                const __half* __restrict__ Bhi, const __half* __restrict__ Blo,
                __half* __restrict__ C16) {
    extern __shared__ char smem[];
    const uint32_t sb = smem_u32(smem);
    const int tid = threadIdx.x;
    const int wid = tid >> 5, lane = tid & 31;
    const int warp_m = wid & 3, warp_n = wid >> 2;   // 4 x 4 warps
    const int m0 = blockIdx.y * 128;
    const int n0 = blockIdx.x * 256;
    const int nchunks = K1PAD / KC;   // 46

    // B cp.async mapping: 256 rows x 4 segs = 1024 tasks, 2 per thread per array
    uint32_t bs[2]; size_t gB[2];
    #pragma unroll
    for (int t = 0; t < 2; t++) {
        int idx = tid + t * 512;
        int row = idx >> 2, seg = idx & 3;
        bs[t] = (uint32_t)row * SPITCH + seg * 16;
        gB[t] = (size_t)(n0 + row) * K1PAD + seg * 8;
    }

    // A fp32 load mapping: 128 rows x 32 floats = 4096; 512 threads x 8 floats
    const int arow = tid >> 2;
    const int acol0 = (tid & 3) * 8;
    const bool row_ok = (m0 + arow) < N_NODES;
    const float* arow_ptr = Af + (size_t)(m0 + arow) * F_IN;

    const int lr = lane & 7, g = lane >> 3;
    const uint32_t offA = (uint32_t)(warp_m * 32 + lr + (g & 1) * 8) * SPITCH + (g >> 1) * 16;
    const uint32_t offB = (uint32_t)(warp_n * 64 + lr + (g >> 1) * 8) * SPITCH + (g & 1) * 16;

    float acc[2][8][4];
    #pragma unroll
    for (int mi = 0; mi < 2; mi++)
        #pragma unroll
        for (int ni = 0; ni < 8; ni++)
            #pragma unroll
            for (int q = 0; q < 4; q++) acc[mi][ni][q] = 0.0f;

    float areg[8];
    {
        const uint32_t d = sb + G1_B(0);
        #pragma unroll
        for (int t = 0; t < 2; t++) {
            cp16(d + bs[t], Bhi + gB[t]);
            cp16(d + B1_BYTES + bs[t], Blo + gB[t]);
        }
        asm volatile("cp.async.commit_group;");
        if (row_ok) {
            #pragma unroll
            for (int j = 0; j < 8; j++) areg[j] = arow_ptr[acol0 + j];
        } else {
            #pragma unroll
            for (int j = 0; j < 8; j++) areg[j] = 0.0f;
        }
    }

    char* const aDst = smem + G1_OFF_A + (size_t)arow * SPITCH + acol0 * 2;

    for (int c = 0; c < nchunks; c++) {
        #pragma unroll
        for (int j = 0; j < 4; j++) {
            __half2 hh;
            hh.x = __float2half(areg[2 * j]);
            hh.y = __float2half(areg[2 * j + 1]);
            *(__half2*)(aDst + j * 4) = hh;
        }
        if (c + 1 < nchunks) {
            const uint32_t d = sb + G1_B((c + 1) & 1);
            const size_t ko = (size_t)(c + 1) * KC;
            #pragma unroll
            for (int t = 0; t < 2; t++) {
                cp16(d + bs[t], Bhi + gB[t] + ko);
                cp16(d + B1_BYTES + bs[t], Blo + gB[t] + ko);
            }
            asm volatile("cp.async.commit_group;");
            const int cb = (c + 1) * KC + acol0;
            if (row_ok && cb + 8 <= F_IN) {
                #pragma unroll
                for (int j = 0; j < 8; j++) areg[j] = arow_ptr[cb + j];
            } else if (row_ok) {
                #pragma unroll
                for (int j = 0; j < 8; j++) areg[j] = (cb + j < F_IN) ? arow_ptr[cb + j] : 0.0f;
            } else {
                #pragma unroll
                for (int j = 0; j < 8; j++) areg[j] = 0.0f;
            }
            asm volatile("cp.async.wait_group 1;");
        } else {
            asm volatile("cp.async.wait_group 0;");
        }
        __syncthreads();

        const uint32_t bbase = sb + G1_B(c & 1);
        #pragma unroll
        for (int ks = 0; ks < 2; ks++) {
            const uint32_t kadd = ks * 32;
            uint32_t a16[2][4], bhi[8][2], blo[8][2];
            #pragma unroll
            for (int mt = 0; mt < 2; mt++)
                ldm_x4(a16[mt][0], a16[mt][1], a16[mt][2], a16[mt][3],
                       sb + G1_OFF_A + offA + mt * 16 * SPITCH + kadd);
            #pragma unroll
            for (int np = 0; np < 4; np++) {
                ldm_x4(bhi[2*np][0], bhi[2*np][1], bhi[2*np+1][0], bhi[2*np+1][1],
                       bbase + offB + np * 16 * SPITCH + kadd);
                ldm_x4(blo[2*np][0], blo[2*np][1], blo[2*np+1][0], blo[2*np+1][1],
                       bbase + B1_BYTES + offB + np * 16 * SPITCH + kadd);
            }
            #pragma unroll
            for (int mi = 0; mi < 2; mi++)
                #pragma unroll
                for (int ni = 0; ni < 8; ni++) {
                    mma_f16(acc[mi][ni], a16[mi], bhi[ni]);
                    mma_f16(acc[mi][ni], a16[mi], blo[ni]);
                }
        }
        __syncthreads();
    }

    const int er = lane >> 2, ec = (lane & 3) * 2;
    #pragma unroll
    for (int mi = 0; mi < 2; mi++) {
        const int r_lo = m0 + warp_m * 32 + mi * 16 + er;
        #pragma unroll
        for (int ni = 0; ni < 8; ni++) {
            const int cc = n0 + warp_n * 64 + ni * 8 + ec;
            __half2 p0, p1;
            p0.x = __float2half(acc[mi][ni][0]); p0.y = __float2half(acc[mi][ni][1]);
            p1.x = __float2half(acc[mi][ni][2]); p1.y = __float2half(acc[mi][ni][3]);
            *(__half2*)(C16 + (size_t)r_lo * H1 + cc)       = p0;
            *(__half2*)(C16 + (size_t)(r_lo + 8) * H1 + cc) = p1;
        }
    }
}

// ---------- layer-2 GEMM: fp16 A (cp.async), fp16 B hi/lo, fp16 out ----------
#define STG_BYTES (3 * ARR_BYTES)
#define OFF_A16   0
#define OFF_BHI   ARR_BYTES
#define OFF_BLO   (2 * ARR_BYTES)
#define SMEM_DYN  (2 * STG_BYTES)

__global__ void __launch_bounds__(256)
gemm_tc_kernel(const __half* __restrict__ A16,
               const __half* __restrict__ Bhi, const __half* __restrict__ Blo,
               __half* __restrict__ C16, int Kpad, int Nc) {
    extern __shared__ char smem[];
    const uint32_t sb = smem_u32(smem);
    const int tid = threadIdx.x;
    const int wid = tid >> 5, lane = tid & 31;
    const int warp_m = wid & 3, warp_n = wid >> 2;
    const int m0 = blockIdx.y * 128;
    const int n0 = blockIdx.x * 128;
    const int nchunks = Kpad / KC;

    const int row0 = tid >> 2, seg = tid & 3;
    const int row1 = row0 + 64;
    const uint32_t s0 = (uint32_t)row0 * SPITCH + seg * 16;
    const uint32_t s1 = (uint32_t)row1 * SPITCH + seg * 16;
    const size_t gA0 = (size_t)(m0 + row0) * Kpad + seg * 8;
    const size_t gA1 = (size_t)(m0 + row1) * Kpad + seg * 8;
    const size_t gB0 = (size_t)(n0 + row0) * Kpad + seg * 8;
    const size_t gB1 = (size_t)(n0 + row1) * Kpad + seg * 8;

    const int lr = lane & 7, g = lane >> 3;
    const uint32_t offA = (uint32_t)(warp_m * 32 + lr + (g & 1) * 8) * SPITCH + (g >> 1) * 16;
    const uint32_t offB = (uint32_t)(warp_n * 64 + lr + (g >> 1) * 8) * SPITCH + (g & 1) * 16;

    float acc[2][8][4];
    #pragma unroll
    for (int mi = 0; mi < 2; mi++)
        #pragma unroll
        for (int ni = 0; ni < 8; ni++)
            #pragma unroll
            for (int q = 0; q < 4; q++) acc[mi][ni][q] = 0.0f;

    {
        const uint32_t d = sb;
        cp16(d + OFF_A16 + s0, A16 + gA0); cp16(d + OFF_A16 + s1, A16 + gA1);
        cp16(d + OFF_BHI + s0, Bhi + gB0); cp16(d + OFF_BHI + s1, Bhi + gB1);
        cp16(d + OFF_BLO + s0, Blo + gB0); cp16(d + OFF_BLO + s1, Blo + gB1);
        asm volatile("cp.async.commit_group;");
    }

    for (int c = 0; c < nchunks; c++) {
        if (c + 1 < nchunks) {
            const uint32_t d = sb + ((c + 1) & 1) * STG_BYTES;
            const size_t ko = (size_t)(c + 1) * KC;
            cp16(d + OFF_A16 + s0, A16 + gA0 + ko); cp16(d + OFF_A16 + s1, A16 + gA1 + ko);
            cp16(d + OFF_BHI + s0, Bhi + gB0 + ko); cp16(d + OFF_BHI + s1, Bhi + gB1 + ko);
            cp16(d + OFF_BLO + s0, Blo + gB0 + ko); cp16(d + OFF_BLO + s1, Blo + gB1 + ko);
            asm volatile("cp.async.commit_group;");
            asm volatile("cp.async.wait_group 1;");
        } else {
            asm volatile("cp.async.wait_group 0;");
        }
        __syncthreads();

        const uint32_t base = sb + (c & 1) * STG_BYTES;
        #pragma unroll
        for (int ks = 0; ks < 2; ks++) {
            const uint32_t kadd = ks * 32;
            uint32_t a16[2][4], bhi[8][2], blo[8][2];
            #pragma unroll
            for (int mt = 0; mt < 2; mt++)
                ldm_x4(a16[mt][0], a16[mt][1], a16[mt][2], a16[mt][3],
                       base + OFF_A16 + offA + mt * 16 * SPITCH + kadd);
            #pragma unroll
            for (int np = 0; np < 4; np++) {
                ldm_x4(bhi[2*np][0], bhi[2*np][1], bhi[2*np+1][0], bhi[2*np+1][1],
                       base + OFF_BHI + offB + np * 16 * SPITCH + kadd);
                ldm_x4(blo[2*np][0], blo[2*np][1], blo[2*np+1][0], blo[2*np+1][1],
                       base + OFF_BLO + offB + np * 16 * SPITCH + kadd);
            }
            #pragma unroll
            for (int mi = 0; mi < 2; mi++)
                #pragma unroll
                for (int ni = 0; ni < 8; ni++) {
                    mma_f16(acc[mi][ni], a16[mi], bhi[ni]);
                    mma_f16(acc[mi][ni], a16[mi], blo[ni]);
                }
        }
        __syncthreads();
    }

    const int er = lane >> 2, ec = (lane & 3) * 2;
    #pragma unroll
    for (int mi = 0; mi < 2; mi++) {
        const int r_lo = m0 + warp_m * 32 + mi * 16 + er;
        #pragma unroll
        for (int ni = 0; ni < 8; ni++) {
            const int cc = n0 + warp_n * 64 + ni * 8 + ec;
            __half2 p0, p1;
            p0.x = __float2half(acc[mi][ni][0]); p0.y = __float2half(acc[mi][ni][1]);
            p1.x = __float2half(acc[mi][ni][2]); p1.y = __float2half(acc[mi][ni][3]);
            *(__half2*)(C16 + (size_t)r_lo * Nc + cc)       = p0;
            *(__half2*)(C16 + (size_t)(r_lo + 8) * Nc + cc) = p1;
        }
    }
}

// ==================== attention scores (fp16 h) ====================
__global__ void s_kernel_h16(const __half* __restrict__ h, const float* __restrict__ a_s,
                             const float* __restrict__ a_d, int F) {
    int node = blockIdx.x * (blockDim.x >> 5) + (threadIdx.x >> 5);
    int lane = threadIdx.x & 31;
    if (node >= N_NODES) return;
    const __half* hr = h + (size_t)node * F;
    float vs = 0.0f, vd = 0.0f;
    for (int f = lane * 8; f < F; f += 256) {
        uint4 raw = *(const uint4*)(hr + f);
        const __half2* hp = (const __half2*)&raw;
        #pragma unroll
        for (int q = 0; q < 4; q++) {
            float2 v = __half22float2(hp[q]);
            float2 as2 = *(const float2*)(a_s + f + q * 2);
            float2 ad2 = *(const float2*)(a_d + f + q * 2);
            vs += v.x * as2.x + v.y * as2.y;
            vd += v.x * ad2.x + v.y * ad2.y;
        }
    }
    #pragma unroll
    for (int o = 16; o > 0; o >>= 1) {
        vs += __shfl_down_sync(0xffffffffu, vs, o);
        vd += __shfl_down_sync(0xffffffffu, vd, o);
    }
    if (lane == 0) {
        g_ss[node] = vs;
        g_sd[node] = vd;
    }
}

__global__ void s_kernel_scalar(const float* __restrict__ h, const float* __restrict__ a_s,
                                const float* __restrict__ a_d, int F) {
    int node = blockIdx.x * (blockDim.x >> 5) + (threadIdx.x >> 5);
    int lane = threadIdx.x & 31;
    if (node >= N_NODES) return;
    const float* hr = h + (size_t)node * F;
    float vs = 0.0f, vd = 0.0f;
    for (int f = lane; f < F; f += 32) {
        float x = hr[f];
        vs += x * a_s[f];
        vd += x * a_d[f];
    }
    #pragma unroll
    for (int o = 16; o > 0; o >>= 1) {
        vs += __shfl_down_sync(0xffffffffu, vs, o);
        vd += __shfl_down_sync(0xffffffffu, vd, o);
    }
    if (lane == 0) {
        g_ss[node] = vs;
        g_sd[node] = vd;
    }
}

// ==================== alpha prepass (warp per node; fully lane-parallel) ====================
__global__ void __launch_bounds__(256)
alpha_kernel() {
    int node = blockIdx.x * 8 + (threadIdx.x >> 5);
    int lane = threadIdx.x & 31;
    if (node >= N_NODES) return;
    const int beg = g_rowoff[node], end = g_rowoff[node + 1];
    const float sd = g_sd[node];

    float m = -INFINITY;
    for (int i = beg + lane; i < end; i += 32) {
        float e = g_ss[g_csr_src[i]] + sd;
        e = e > 0.0f ? e : 0.2f * e;
        m = fmaxf(m, e);
    }
    #pragma unroll
    for (int o = 16; o > 0; o >>= 1) m = fmaxf(m, __shfl_xor_sync(0xffffffffu, m, o));

    float den = 0.0f;
    for (int i = beg + lane; i < end; i += 32) {
        float e = g_ss[g_csr_src[i]] + sd;
        e = e > 0.0f ? e : 0.2f * e;
        float ee = __expf(e - m);
        g_alpha[i] = ee;
        den += ee;
    }
    #pragma unroll
    for (int o = 16; o > 0; o >>= 1) den += __shfl_xor_sync(0xffffffffu, den, o);
    float inv = 1.0f / den;
    for (int i = beg + lane; i < end; i += 32) g_alpha[i] *= inv;
}

// ==================== weighted gather aggregation ====================
// NW warps per node, each owns F/NW = 256-halves (one 16B/lane step).
// OUT_F16=1: write fp16 out (next GEMM A); else fp32.
template <int F, int NW, int OUT_F16>
__global__ void __launch_bounds__(256)
gat_agg_kernel(const __half* __restrict__ h, const float* __restrict__ bias,
               float* __restrict__ outf, __half* __restrict__ oh) {
    int gw = blockIdx.x * 8 + (threadIdx.x >> 5);
    int lane = threadIdx.x & 31;
    int node = gw / NW, part = gw % NW;
    if (node >= N_NODES) return;
    const int beg = g_rowoff[node], end = g_rowoff[node + 1];
    const uint32_t c8 = part * (F / NW) + lane * 8;

    float acc[8];
    #pragma unroll
    for (int q = 0; q < 8; q++) acc[q] = 0.0f;

    int i = beg;
    for (; i + 1 < end; i += 2) {
        int s0 = g_csr_src[i], s1 = g_csr_src[i + 1];
        float w0 = g_alpha[i], w1 = g_alpha[i + 1];
        uint4 r0 = *(const uint4*)(h + (size_t)s0 * F + c8);
        uint4 r1 = *(const uint4*)(h + (size_t)s1 * F + c8);
        const __half2* p0 = (const __half2*)&r0;
        const __half2* p1 = (const __half2*)&r1;
        #pragma unroll
        for (int q = 0; q < 4; q++) {
            float2 v0 = __half22float2(p0[q]);
            float2 v1 = __half22float2(p1[q]);
            acc[2*q+0] += w0 * v0.x + w1 * v1.x;
            acc[2*q+1] += w0 * v0.y + w1 * v1.y;
        }
    }
    if (i < end) {
        int s0 = g_csr_src[i];
        float w0 = g_alpha[i];
        uint4 r0 = *(const uint4*)(h + (size_t)s0 * F + c8);
        const __half2* p0 = (const __half2*)&r0;
        #pragma unroll
        for (int q = 0; q < 4; q++) {
            float2 v0 = __half22float2(p0[q]);
            acc[2*q+0] += w0 * v0.x;
            acc[2*q+1] += w0 * v0.y;
        }
    }

    float v[8];
    #pragma unroll
    for (int q = 0; q < 8; q++) v[q] = fmaxf(acc[q] + bias[c8 + q], 0.0f);
    size_t o = (size_t)node * F + c8;
    if (OUT_F16) {
        uint4 packed;
        __half2* hp = (__half2*)&packed;
        #pragma unroll
        for (int q = 0; q < 4; q++) {
            __half2 p;
            p.x = __float2half(v[2*q]); p.y = __float2half(v[2*q+1]);
            hp[q] = p;
        }
        *(uint4*)(oh + o) = packed;
    } else {
        *(float4*)(outf + o)     = make_float4(v[0], v[1], v[2], v[3]);
        *(float4*)(outf + o + 4) = make_float4(v[4], v[5], v[6], v[7]);
    }
}

// ==================== layer 3: skinny GEMM (smem W) + fused agg+logsoftmax ====================
__global__ void __launch_bounds__(256)
gemm3_kernel(const float* __restrict__ A, const float* __restrict__ W,
             float* __restrict__ C) {
    __shared__ float sW[H2 * NC];
    for (int i = threadIdx.x; i < H2 * NC; i += blockDim.x) sW[i] = W[i];
    __syncthreads();
    int node = blockIdx.x * blockDim.x + threadIdx.x;
    if (node >= N_NODES) return;
    const float4* a4 = (const float4*)(A + (size_t)node * H2);
    float acc[NC] = {0,0,0,0,0,0,0};
    #pragma unroll 4
    for (int k4 = 0; k4 < H2 / 4; k4++) {
        float4 a = a4[k4];
        const float* w0 = sW + (k4 * 4) * NC;
        #pragma unroll
        for (int c = 0; c < NC; c++)
            acc[c] += a.x * w0[c] + a.y * w0[NC + c] + a.z * w0[2 * NC + c] + a.w * w0[3 * NC + c];
    }
    #pragma unroll
    for (int c = 0; c < NC; c++) C[(size_t)node * NC + c] = acc[c];
}

__global__ void __launch_bounds__(256)
gat_agg3_final_kernel(const float* __restrict__ h, const float* __restrict__ bias,
                      float* __restrict__ out) {
    int node = blockIdx.x * 8 + (threadIdx.x >> 5);
    int lane = threadIdx.x & 31;
    if (node >= N_NODES) return;
    const int beg = g_rowoff[node], end = g_rowoff[node + 1];
    const float sd = g_sd[node];

    float m = -INFINITY;
    for (int i = beg + lane; i < end; i += 32) {
        float e = g_ss[g_csr_src[i]] + sd;
        e = e > 0.0f ? e : 0.2f * e;
        m = fmaxf(m, e);
    }
    #pragma unroll
    for (int o = 16; o > 0; o >>= 1) m = fmaxf(m, __shfl_xor_sync(0xffffffffu, m, o));

    float acc[NC] = {0,0,0,0,0,0,0};
    float den = 0.0f;
    for (int i = beg + lane; i < end; i += 32) {
        int s = g_csr_src[i];
        float e = g_ss[s] + sd;
        e = e > 0.0f ? e : 0.2f * e;
        float ee = __expf(e - m);
        den += ee;
        const float* hr = h + (size_t)s * NC;
        #pragma unroll
        for (int c = 0; c < NC; c++) acc[c] += ee * hr[c];
    }
    #pragma unroll
    for (int o = 16; o > 0; o >>= 1) {
        den += __shfl_xor_sync(0xffffffffu, den, o);
        #pragma unroll
        for (int c = 0; c < NC; c++) acc[c] += __shfl_xor_sync(0xffffffffu, acc[c], o);
    }
    if (lane == 0) {
        float inv = 1.0f / den;
        float z[NC], mx = -INFINITY;
        #pragma unroll
        for (int c = 0; c < NC; c++) {
            z[c] = acc[c] * inv + bias[c];
            mx = fmaxf(mx, z[c]);
        }
        float ssum = 0.0f;
        #pragma unroll
        for (int c = 0; c < NC; c++) ssum += __expf(z[c] - mx);
        float l = logf(ssum);
        float* o = out + (size_t)node * NC;
        #pragma unroll
        for (int c = 0; c < NC; c++) o[c] = z[c] - mx - l;
    }
}

// ==================== launcher ====================
extern "C" void kernel_launch(void* const* d_in, const int* in_sizes, int n_in,
                              void* d_out, int out_size) {
    const float* x   = (const float*)d_in[0];
    const void*  ei  = d_in[1];
    const float* W1  = (const float*)d_in[2];
    const float* as1 = (const float*)d_in[3];
    const float* ad1 = (const float*)d_in[4];
    const float* b1  = (const float*)d_in[5];
    const float* W2  = (const float*)d_in[6];
    const float* as2 = (const float*)d_in[7];
    const float* ad2 = (const float*)d_in[8];
    const float* b2  = (const float*)d_in[9];
    const float* W3  = (const float*)d_in[10];
    const float* as3 = (const float*)d_in[11];
    const float* ad3 = (const float*)d_in[12];
    const float* b3  = (const float*)d_in[13];
    float* out = (float*)d_out;

    float *buf1, *buf2;
    __half *h16, *a16, *bhi, *blo;
    cudaGetSymbolAddress((void**)&buf1, g_buf1);
    cudaGetSymbolAddress((void**)&buf2, g_buf2);
    cudaGetSymbolAddress((void**)&h16, g_h16);
    cudaGetSymbolAddress((void**)&a16, g_A16);
    cudaGetSymbolAddress((void**)&bhi, g_Bhi);
    cudaGetSymbolAddress((void**)&blo, g_Blo);

    cudaFuncSetAttribute(gemm1_tc_kernel, cudaFuncAttributeMaxDynamicSharedMemorySize, G1_SMEM);
    cudaFuncSetAttribute(gemm_tc_kernel, cudaFuncAttributeMaxDynamicSharedMemorySize, SMEM_DYN);

    const int BT = 256;
    const int edge_blocks      = (NE + BT - 1) / BT;
    const int node_warp_blocks = (N_NODES + (BT / 32) - 1) / (BT / 32);
    const int node_blocks      = (N_NODES + BT - 1) / BT;
    const int agg1_blocks      = (N_NODES * 2 + 7) / 8;   // 2 warps per node

    // ---- CSR build ----
    detect_kernel<<<1, 128>>>((const unsigned int*)ei);
    zero_deg_kernel<<<node_blocks, BT>>>();
    prep_edges_kernel<<<edge_blocks, BT>>>(ei);
    reduce_deg_kernel<<<NB, 256>>>();
    scan_bsums_kernel<<<1, 256>>>();
    scan_write_kernel<<<NB, 256>>>();
    scatter_kernel<<<edge_blocks, BT>>>();

    // ---------------- layer 1: F_IN -> H1 ----------------
    split_Wt_kernel<<<2048, BT>>>(W1, F_IN, H1, K1PAD, bhi, blo);
    gemm1_tc_kernel<<<dim3(H1 / 256, MPAD / 128), 512, G1_SMEM>>>(x, bhi, blo, h16);
    s_kernel_h16<<<node_warp_blocks, BT>>>(h16, as1, ad1, H1);
    alpha_kernel<<<node_warp_blocks, BT>>>();
    gat_agg_kernel<H1, 2, 1><<<agg1_blocks, BT>>>(h16, b1, nullptr, a16);

    // ---------------- layer 2: H1 -> H2 ----------------
    split_Wt_kernel<<<2048, BT>>>(W2, H1, H2, H1, bhi, blo);
    gemm_tc_kernel<<<dim3(H2 / 128, MPAD / 128), BT, SMEM_DYN>>>(a16, bhi, blo, h16, H1, H2);
    s_kernel_h16<<<node_warp_blocks, BT>>>(h16, as2, ad2, H2);
    alpha_kernel<<<node_warp_blocks, BT>>>();
    gat_agg_kernel<H2, 1, 0><<<node_warp_blocks, BT>>>(h16, b2, buf2, nullptr);

    // ---------------- layer 3: H2 -> NC ----------------
    gemm3_kernel<<<node_blocks, BT>>>(buf2, W3, buf1);
    s_kernel_scalar<<<node_warp_blocks, BT>>>(buf1, as3, ad3, NC);
    gat_agg3_final_kernel<<<node_warp_blocks, BT>>>(buf1, b3, out);
}

// round 14
// speedup vs baseline: 4.2909x; 1.3817x over previous
#include <cuda_runtime.h>
#include <cuda_fp16.h>
#include <math.h>
#include <stdint.h>

#define N_NODES 50000
#define MPAD    50048   // 391 * 128
#define E0      800000
#define NE      850000
#define F_IN    1433
#define K1PAD   1472    // 46 * 32
#define H1      512
#define H2      256
#define NC      7
#define NB      196     // ceil(N_NODES / 256)

// ==================== scratch (device globals) ====================
__device__ __half g_h16[(size_t)MPAD * H1];
__device__ __half g_A16[(size_t)MPAD * H1];
__device__ __half g_B16[(size_t)H1 * K1PAD];
__device__ float g_buf1[(size_t)MPAD * NC];
__device__ float g_buf2[(size_t)MPAD * H2];
__device__ float g_ss[N_NODES];
__device__ float g_sd[N_NODES];
__device__ float g_alpha[NE];
__device__ int   g_src[NE];
__device__ int   g_dst[NE];
__device__ int   g_csr_src[NE];
__device__ int   g_deg[N_NODES];
__device__ int   g_rowoff[N_NODES + 1];
__device__ int   g_cursor[N_NODES];
__device__ int   g_bsum[NB];
__device__ int   g_boff[NB];
__device__ int   g_is64;

// ==================== PTX helpers (base-arch only) ====================
__device__ __forceinline__ uint32_t smem_u32(const void* p) {
    uint32_t a;
    asm("{ .reg .u64 t; cvta.to.shared.u64 t, %1; cvt.u32.u64 %0, t; }" : "=r"(a) : "l"(p));
    return a;
}
__device__ __forceinline__ void cp16(uint32_t dst, const void* src) {
    asm volatile("cp.async.cg.shared.global [%0], [%1], 16;" :: "r"(dst), "l"(src));
}
__device__ __forceinline__ void ldm_x4(uint32_t& r0, uint32_t& r1, uint32_t& r2, uint32_t& r3,
                                       uint32_t addr) {
    asm volatile("ldmatrix.sync.aligned.m8n8.x4.shared.b16 {%0,%1,%2,%3}, [%4];"
                 : "=r"(r0), "=r"(r1), "=r"(r2), "=r"(r3) : "r"(addr));
}
__device__ __forceinline__ void mma_f16(float* c, const uint32_t* a, const uint32_t* b) {
    asm volatile("mma.sync.aligned.m16n8k16.row.col.f32.f16.f16.f32 "
                 "{%0,%1,%2,%3}, {%4,%5,%6,%7}, {%8,%9}, {%0,%1,%2,%3};"
                 : "+f"(c[0]), "+f"(c[1]), "+f"(c[2]), "+f"(c[3])
                 : "r"(a[0]), "r"(a[1]), "r"(a[2]), "r"(a[3]), "r"(b[0]), "r"(b[1]));
}

// ==================== edge prep + CSR build ====================
__global__ void detect_kernel(const unsigned int* __restrict__ w) {
    __shared__ int nz;
    if (threadIdx.x == 0) nz = 0;
    __syncthreads();
    if (w[threadIdx.x * 2 + 1] != 0u) atomicOr(&nz, 1);
    __syncthreads();
    if (threadIdx.x == 0) g_is64 = (nz == 0);
}

__global__ void zero_deg_kernel() {
    int i = blockIdx.x * blockDim.x + threadIdx.x;
    if (i < N_NODES) g_deg[i] = 0;
}

__global__ void prep_edges_kernel(const void* __restrict__ ei) {
    int i = blockIdx.x * blockDim.x + threadIdx.x;
    if (i >= NE) return;
    int s, d;
    if (i < E0) {
        if (g_is64) {
            const long long* e = (const long long*)ei;
            s = (int)e[i]; d = (int)e[E0 + i];
        } else {
            const int* e = (const int*)ei;
            s = e[i]; d = e[E0 + i];
        }
    } else {
        s = d = i - E0;
    }
    s = min(max(s, 0), N_NODES - 1);
    d = min(max(d, 0), N_NODES - 1);
    g_src[i] = s;
    g_dst[i] = d;
    atomicAdd(&g_deg[d], 1);
}

__global__ void reduce_deg_kernel() {          // grid NB, 256
    __shared__ int sh[256];
    int i = blockIdx.x * 256 + threadIdx.x;
    sh[threadIdx.x] = (i < N_NODES) ? g_deg[i] : 0;
    __syncthreads();
    for (int o = 128; o > 0; o >>= 1) {
        if (threadIdx.x < o) sh[threadIdx.x] += sh[threadIdx.x + o];
        __syncthreads();
    }
    if (threadIdx.x == 0) g_bsum[blockIdx.x] = sh[0];
}

__global__ void scan_bsums_kernel() {          // 1 block, 256
    __shared__ int sh[256];
    int t = threadIdx.x;
    int mine = (t < NB) ? g_bsum[t] : 0;
    sh[t] = mine;
    __syncthreads();
    for (int o = 1; o < 256; o <<= 1) {
        int v = (t >= o) ? sh[t - o] : 0;
        __syncthreads();
        sh[t] += v;
        __syncthreads();
    }
    if (t < NB) g_boff[t] = sh[t] - mine;
    if (t == 0) g_rowoff[N_NODES] = NE;
}

__global__ void scan_write_kernel() {          // grid NB, 256
    __shared__ int sh[256];
    int i = blockIdx.x * 256 + threadIdx.x;
    int v = (i < N_NODES) ? g_deg[i] : 0;
    sh[threadIdx.x] = v;
    __syncthreads();
    for (int o = 1; o < 256; o <<= 1) {
        int u = (threadIdx.x >= o) ? sh[threadIdx.x - o] : 0;
        __syncthreads();
        sh[threadIdx.x] += u;
        __syncthreads();
    }
    if (i < N_NODES) {
        int excl = g_boff[blockIdx.x] + sh[threadIdx.x] - v;
        g_rowoff[i] = excl;
        g_cursor[i] = excl;
    }
}

__global__ void scatter_kernel() {
    int i = blockIdx.x * blockDim.x + threadIdx.x;
    if (i >= NE) return;
    int pos = atomicAdd(&g_cursor[g_dst[i]], 1);
    g_csr_src[pos] = g_src[i];
}

// ==================== weight transpose+convert (fp16) ====================
__global__ void split_Wt_kernel(const float* __restrict__ W, int K, int N, int Kpad,
                                __half* __restrict__ hi) {
    size_t total = (size_t)N * Kpad;
    size_t i = (size_t)blockIdx.x * blockDim.x + threadIdx.x;
    size_t stride = (size_t)gridDim.x * blockDim.x;
    for (; i < total; i += stride) {
        int n = (int)(i / Kpad), k = (int)(i % Kpad);
        float v = (k < K) ? W[(size_t)k * N + n] : 0.0f;
        hi[i] = __float2half(v);
    }
}

// ==================== GEMM common ====================
#define KC        32
#define SPITCH    80
#define ARR_BYTES (128 * SPITCH)     // 10240 (128-row arrays)
#define B1_BYTES  (256 * SPITCH)     // 20480 (256-row B arrays for gemm1)

// ---------- layer-1 GEMM: CTA tile 128x256, 512 threads, fp32 A converted in-kernel ----------
// smem: A16 [0,10240), B stage s at 10240 + s*20480
#define G1_OFF_A  0
#define G1_B(s)   (ARR_BYTES + (s) * B1_BYTES)
#define G1_SMEM   (ARR_BYTES + 2 * B1_BYTES)   // 51200

__global__ void __launch_bounds__(512)
gemm1_tc_kernel(const float* __restrict__ Af,
                const __half* __restrict__ B16,
                __half* __restrict__ C16) {
    extern __shared__ char smem[];
    const uint32_t sb = smem_u32(smem);
    const int tid = threadIdx.x;
    const int wid = tid >> 5, lane = tid & 31;
    const int warp_m = wid & 3, warp_n = wid >> 2;   // 4 x 4 warps
    const int m0 = blockIdx.y * 128;
    const int n0 = blockIdx.x * 256;
    const int nchunks = K1PAD / KC;   // 46

    // B cp.async mapping: 256 rows x 4 segs = 1024 tasks, 2 per thread
    uint32_t bs[2]; size_t gB[2];
    #pragma unroll
    for (int t = 0; t < 2; t++) {
        int idx = tid + t * 512;
        int row = idx >> 2, seg = idx & 3;
        bs[t] = (uint32_t)row * SPITCH + seg * 16;
        gB[t] = (size_t)(n0 + row) * K1PAD + seg * 8;
    }

    // A fp32 load mapping: 128 rows x 32 floats = 4096; 512 threads x 8 floats
    const int arow = tid >> 2;
    const int acol0 = (tid & 3) * 8;
    const bool row_ok = (m0 + arow) < N_NODES;
    const float* arow_ptr = Af + (size_t)(m0 + arow) * F_IN;

    const int lr = lane & 7, g = lane >> 3;
    const uint32_t offA = (uint32_t)(warp_m * 32 + lr + (g & 1) * 8) * SPITCH + (g >> 1) * 16;
    const uint32_t offB = (uint32_t)(warp_n * 64 + lr + (g >> 1) * 8) * SPITCH + (g & 1) * 16;

    float acc[2][8][4];
    #pragma unroll
    for (int mi = 0; mi < 2; mi++)
        #pragma unroll
        for (int ni = 0; ni < 8; ni++)
            #pragma unroll
            for (int q = 0; q < 4; q++) acc[mi][ni][q] = 0.0f;

    float areg[8];
    {
        const uint32_t d = sb + G1_B(0);
        #pragma unroll
        for (int t = 0; t < 2; t++) cp16(d + bs[t], B16 + gB[t]);
        asm volatile("cp.async.commit_group;");
        if (row_ok) {
            #pragma unroll
            for (int j = 0; j < 8; j++) areg[j] = arow_ptr[acol0 + j];
        } else {
            #pragma unroll
            for (int j = 0; j < 8; j++) areg[j] = 0.0f;
        }
    }

    char* const aDst = smem + G1_OFF_A + (size_t)arow * SPITCH + acol0 * 2;

    for (int c = 0; c < nchunks; c++) {
        #pragma unroll
        for (int j = 0; j < 4; j++) {
            __half2 hh;
            hh.x = __float2half(areg[2 * j]);
            hh.y = __float2half(areg[2 * j + 1]);
            *(__half2*)(aDst + j * 4) = hh;
        }
        if (c + 1 < nchunks) {
            const uint32_t d = sb + G1_B((c + 1) & 1);
            const size_t ko = (size_t)(c + 1) * KC;
            #pragma unroll
            for (int t = 0; t < 2; t++) cp16(d + bs[t], B16 + gB[t] + ko);
            asm volatile("cp.async.commit_group;");
            const int cb = (c + 1) * KC + acol0;
            if (row_ok && cb + 8 <= F_IN) {
                #pragma unroll
                for (int j = 0; j < 8; j++) areg[j] = arow_ptr[cb + j];
            } else if (row_ok) {
                #pragma unroll
                for (int j = 0; j < 8; j++) areg[j] = (cb + j < F_IN) ? arow_ptr[cb + j] : 0.0f;
            } else {
                #pragma unroll
                for (int j = 0; j < 8; j++) areg[j] = 0.0f;
            }
            asm volatile("cp.async.wait_group 1;");
        } else {
            asm volatile("cp.async.wait_group 0;");
        }
        __syncthreads();

        const uint32_t bbase = sb + G1_B(c & 1);
        #pragma unroll
        for (int ks = 0; ks < 2; ks++) {
            const uint32_t kadd = ks * 32;
            uint32_t a16[2][4], b16[8][2];
            #pragma unroll
            for (int mt = 0; mt < 2; mt++)
                ldm_x4(a16[mt][0], a16[mt][1], a16[mt][2], a16[mt][3],
                       sb + G1_OFF_A + offA + mt * 16 * SPITCH + kadd);
            #pragma unroll
            for (int np = 0; np < 4; np++)
                ldm_x4(b16[2*np][0], b16[2*np][1], b16[2*np+1][0], b16[2*np+1][1],
                       bbase + offB + np * 16 * SPITCH + kadd);
            #pragma unroll
            for (int mi = 0; mi < 2; mi++)
                #pragma unroll
                for (int ni = 0; ni < 8; ni++)
                    mma_f16(acc[mi][ni], a16[mi], b16[ni]);
        }
        __syncthreads();
    }

    const int er = lane >> 2, ec = (lane & 3) * 2;
    #pragma unroll
    for (int mi = 0; mi < 2; mi++) {
        const int r_lo = m0 + warp_m * 32 + mi * 16 + er;
        #pragma unroll
        for (int ni = 0; ni < 8; ni++) {
            const int cc = n0 + warp_n * 64 + ni * 8 + ec;
            __half2 p0, p1;
            p0.x = __float2half(acc[mi][ni][0]); p0.y = __float2half(acc[mi][ni][1]);
            p1.x = __float2half(acc[mi][ni][2]); p1.y = __float2half(acc[mi][ni][3]);
            *(__half2*)(C16 + (size_t)r_lo * H1 + cc)       = p0;
            *(__half2*)(C16 + (size_t)(r_lo + 8) * H1 + cc) = p1;
        }
    }
}

// ---------- layer-2 GEMM: fp16 A (cp.async), fp16 B, fp16 out ----------
#define STG_BYTES (2 * ARR_BYTES)    // 20480
#define OFF_A16   0
#define OFF_B16   ARR_BYTES
#define SMEM_DYN  (2 * STG_BYTES)    // 40960

__global__ void __launch_bounds__(256)
gemm_tc_kernel(const __half* __restrict__ A16,
               const __half* __restrict__ B16,
               __half* __restrict__ C16, int Kpad, int Nc) {
    extern __shared__ char smem[];
    const uint32_t sb = smem_u32(smem);
    const int tid = threadIdx.x;
    const int wid = tid >> 5, lane = tid & 31;
    const int warp_m = wid & 3, warp_n = wid >> 2;
    const int m0 = blockIdx.y * 128;
    const int n0 = blockIdx.x * 128;
    const int nchunks = Kpad / KC;

    const int row0 = tid >> 2, seg = tid & 3;
    const int row1 = row0 + 64;
    const uint32_t s0 = (uint32_t)row0 * SPITCH + seg * 16;
    const uint32_t s1 = (uint32_t)row1 * SPITCH + seg * 16;
    const size_t gA0 = (size_t)(m0 + row0) * Kpad + seg * 8;
    const size_t gA1 = (size_t)(m0 + row1) * Kpad + seg * 8;
    const size_t gB0 = (size_t)(n0 + row0) * Kpad + seg * 8;
    const size_t gB1 = (size_t)(n0 + row1) * Kpad + seg * 8;

    const int lr = lane & 7, g = lane >> 3;
    const uint32_t offA = (uint32_t)(warp_m * 32 + lr + (g & 1) * 8) * SPITCH + (g >> 1) * 16;
    const uint32_t offB = (uint32_t)(warp_n * 64 + lr + (g >> 1) * 8) * SPITCH + (g & 1) * 16;

    float acc[2][8][4];
    #pragma unroll
    for (int mi = 0; mi < 2; mi++)
        #pragma unroll
        for (int ni = 0; ni < 8; ni++)
            #pragma unroll
            for (int q = 0; q < 4; q++) acc[mi][ni][q] = 0.0f;

    {
        const uint32_t d = sb;
        cp16(d + OFF_A16 + s0, A16 + gA0); cp16(d + OFF_A16 + s1, A16 + gA1);
        cp16(d + OFF_B16 + s0, B16 + gB0); cp16(d + OFF_B16 + s1, B16 + gB1);
        asm volatile("cp.async.commit_group;");
    }

    for (int c = 0; c < nchunks; c++) {
        if (c + 1 < nchunks) {
            const uint32_t d = sb + ((c + 1) & 1) * STG_BYTES;
            const size_t ko = (size_t)(c + 1) * KC;
            cp16(d + OFF_A16 + s0, A16 + gA0 + ko); cp16(d + OFF_A16 + s1, A16 + gA1 + ko);
            cp16(d + OFF_B16 + s0, B16 + gB0 + ko); cp16(d + OFF_B16 + s1, B16 + gB1 + ko);
            asm volatile("cp.async.commit_group;");
            asm volatile("cp.async.wait_group 1;");
        } else {
            asm volatile("cp.async.wait_group 0;");
        }
        __syncthreads();

        const uint32_t base = sb + (c & 1) * STG_BYTES;
        #pragma unroll
        for (int ks = 0; ks < 2; ks++) {
            const uint32_t kadd = ks * 32;
            uint32_t a16[2][4], b16[8][2];
            #pragma unroll
            for (int mt = 0; mt < 2; mt++)
                ldm_x4(a16[mt][0], a16[mt][1], a16[mt][2], a16[mt][3],
                       base + OFF_A16 + offA + mt * 16 * SPITCH + kadd);
            #pragma unroll
            for (int np = 0; np < 4; np++)
                ldm_x4(b16[2*np][0], b16[2*np][1], b16[2*np+1][0], b16[2*np+1][1],
                       base + OFF_B16 + offB + np * 16 * SPITCH + kadd);
            #pragma unroll
            for (int mi = 0; mi < 2; mi++)
                #pragma unroll
                for (int ni = 0; ni < 8; ni++)
                    mma_f16(acc[mi][ni], a16[mi], b16[ni]);
        }
        __syncthreads();
    }

    const int er = lane >> 2, ec = (lane & 3) * 2;
    #pragma unroll
    for (int mi = 0; mi < 2; mi++) {
        const int r_lo = m0 + warp_m * 32 + mi * 16 + er;
        #pragma unroll
        for (int ni = 0; ni < 8; ni++) {
            const int cc = n0 + warp_n * 64 + ni * 8 + ec;
            __half2 p0, p1;
            p0.x = __float2half(acc[mi][ni][0]); p0.y = __float2half(acc[mi][ni][1]);
            p1.x = __float2half(acc[mi][ni][2]); p1.y = __float2half(acc[mi][ni][3]);
            *(__half2*)(C16 + (size_t)r_lo * Nc + cc)       = p0;
            *(__half2*)(C16 + (size_t)(r_lo + 8) * Nc + cc) = p1;
        }
    }
}

// ==================== attention scores (fp16 h) ====================
__global__ void s_kernel_h16(const __half* __restrict__ h, const float* __restrict__ a_s,
                             const float* __restrict__ a_d, int F) {
    int node = blockIdx.x * (blockDim.x >> 5) + (threadIdx.x >> 5);
    int lane = threadIdx.x & 31;
    if (node >= N_NODES) return;
    const __half* hr = h + (size_t)node * F;
    float vs = 0.0f, vd = 0.0f;
    for (int f = lane * 8; f < F; f += 256) {
        uint4 raw = *(const uint4*)(hr + f);
        const __half2* hp = (const __half2*)&raw;
        #pragma unroll
        for (int q = 0; q < 4; q++) {
            float2 v = __half22float2(hp[q]);
            float2 as2 = *(const float2*)(a_s + f + q * 2);
            float2 ad2 = *(const float2*)(a_d + f + q * 2);
            vs += v.x * as2.x + v.y * as2.y;
            vd += v.x * ad2.x + v.y * ad2.y;
        }
    }
    #pragma unroll
    for (int o = 16; o > 0; o >>= 1) {
        vs += __shfl_down_sync(0xffffffffu, vs, o);
        vd += __shfl_down_sync(0xffffffffu, vd, o);
    }
    if (lane == 0) {
        g_ss[node] = vs;
        g_sd[node] = vd;
    }
}

__global__ void s_kernel_scalar(const float* __restrict__ h, const float* __restrict__ a_s,
                                const float* __restrict__ a_d, int F) {
    int node = blockIdx.x * (blockDim.x >> 5) + (threadIdx.x >> 5);
    int lane = threadIdx.x & 31;
    if (node >= N_NODES) return;
    const float* hr = h + (size_t)node * F;
    float vs = 0.0f, vd = 0.0f;
    for (int f = lane; f < F; f += 32) {
        float x = hr[f];
        vs += x * a_s[f];
        vd += x * a_d[f];
    }
    #pragma unroll
    for (int o = 16; o > 0; o >>= 1) {
        vs += __shfl_down_sync(0xffffffffu, vs, o);
        vd += __shfl_down_sync(0xffffffffu, vd, o);
    }
    if (lane == 0) {
        g_ss[node] = vs;
        g_sd[node] = vd;
    }
}

// ==================== alpha prepass (warp per node) ====================
__global__ void __launch_bounds__(256)
alpha_kernel() {
    int node = blockIdx.x * 8 + (threadIdx.x >> 5);
    int lane = threadIdx.x & 31;
    if (node >= N_NODES) return;
    const int beg = g_rowoff[node], end = g_rowoff[node + 1];
    const float sd = g_sd[node];

    float m = -INFINITY;
    for (int i = beg + lane; i < end; i += 32) {
        float e = g_ss[g_csr_src[i]] + sd;
        e = e > 0.0f ? e : 0.2f * e;
        m = fmaxf(m, e);
    }
    #pragma unroll
    for (int o = 16; o > 0; o >>= 1) m = fmaxf(m, __shfl_xor_sync(0xffffffffu, m, o));

    float den = 0.0f;
    for (int i = beg + lane; i < end; i += 32) {
        float e = g_ss[g_csr_src[i]] + sd;
        e = e > 0.0f ? e : 0.2f * e;
        float ee = __expf(e - m);
        g_alpha[i] = ee;
        den += ee;
    }
    #pragma unroll
    for (int o = 16; o > 0; o >>= 1) den += __shfl_xor_sync(0xffffffffu, den, o);
    float inv = 1.0f / den;
    for (int i = beg + lane; i < end; i += 32) g_alpha[i] *= inv;
}

// ==================== weighted gather aggregation ====================
template <int F, int NW, int OUT_F16>
__global__ void __launch_bounds__(256)
gat_agg_kernel(const __half* __restrict__ h, const float* __restrict__ bias,
               float* __restrict__ outf, __half* __restrict__ oh) {
    int gw = blockIdx.x * 8 + (threadIdx.x >> 5);
    int lane = threadIdx.x & 31;
    int node = gw / NW, part = gw % NW;
    if (node >= N_NODES) return;
    const int beg = g_rowoff[node], end = g_rowoff[node + 1];
    const uint32_t c8 = part * (F / NW) + lane * 8;

    float acc[8];
    #pragma unroll
    for (int q = 0; q < 8; q++) acc[q] = 0.0f;

    int i = beg;
    for (; i + 1 < end; i += 2) {
        int s0 = g_csr_src[i], s1 = g_csr_src[i + 1];
        float w0 = g_alpha[i], w1 = g_alpha[i + 1];
        uint4 r0 = *(const uint4*)(h + (size_t)s0 * F + c8);
        uint4 r1 = *(const uint4*)(h + (size_t)s1 * F + c8);
        const __half2* p0 = (const __half2*)&r0;
        const __half2* p1 = (const __half2*)&r1;
        #pragma unroll
        for (int q = 0; q < 4; q++) {
            float2 v0 = __half22float2(p0[q]);
            float2 v1 = __half22float2(p1[q]);
            acc[2*q+0] += w0 * v0.x + w1 * v1.x;
            acc[2*q+1] += w0 * v0.y + w1 * v1.y;
        }
    }
    if (i < end) {
        int s0 = g_csr_src[i];
        float w0 = g_alpha[i];
        uint4 r0 = *(const uint4*)(h + (size_t)s0 * F + c8);
        const __half2* p0 = (const __half2*)&r0;
        #pragma unroll
        for (int q = 0; q < 4; q++) {
            float2 v0 = __half22float2(p0[q]);
            acc[2*q+0] += w0 * v0.x;
            acc[2*q+1] += w0 * v0.y;
        }
    }

    float v[8];
    #pragma unroll
    for (int q = 0; q < 8; q++) v[q] = fmaxf(acc[q] + bias[c8 + q], 0.0f);
    size_t o = (size_t)node * F + c8;
    if (OUT_F16) {
        uint4 packed;
        __half2* hp = (__half2*)&packed;
        #pragma unroll
        for (int q = 0; q < 4; q++) {
            __half2 p;
            p.x = __float2half(v[2*q]); p.y = __float2half(v[2*q+1]);
            hp[q] = p;
        }
        *(uint4*)(oh + o) = packed;
    } else {
        *(float4*)(outf + o)     = make_float4(v[0], v[1], v[2], v[3]);
        *(float4*)(outf + o + 4) = make_float4(v[4], v[5], v[6], v[7]);
    }
}

// ==================== layer 3: skinny GEMM (smem W) + fused agg+logsoftmax ====================
__global__ void __launch_bounds__(256)
gemm3_kernel(const float* __restrict__ A, const float* __restrict__ W,
             float* __restrict__ C) {
    __shared__ float sW[H2 * NC];
    for (int i = threadIdx.x; i < H2 * NC; i += blockDim.x) sW[i] = W[i];
    __syncthreads();
    int node = blockIdx.x * blockDim.x + threadIdx.x;
    if (node >= N_NODES) return;
    const float4* a4 = (const float4*)(A + (size_t)node * H2);
    float acc[NC] = {0,0,0,0,0,0,0};
    #pragma unroll 4
    for (int k4 = 0; k4 < H2 / 4; k4++) {
        float4 a = a4[k4];
        const float* w0 = sW + (k4 * 4) * NC;
        #pragma unroll
        for (int c = 0; c < NC; c++)
            acc[c] += a.x * w0[c] + a.y * w0[NC + c] + a.z * w0[2 * NC + c] + a.w * w0[3 * NC + c];
    }
    #pragma unroll
    for (int c = 0; c < NC; c++) C[(size_t)node * NC + c] = acc[c];
}

__global__ void __launch_bounds__(256)
gat_agg3_final_kernel(const float* __restrict__ h, const float* __restrict__ bias,
                      float* __restrict__ out) {
    int node = blockIdx.x * 8 + (threadIdx.x >> 5);
    int lane = threadIdx.x & 31;
    if (node >= N_NODES) return;
    const int beg = g_rowoff[node], end = g_rowoff[node + 1];
    const float sd = g_sd[node];

    float m = -INFINITY;
    for (int i = beg + lane; i < end; i += 32) {
        float e = g_ss[g_csr_src[i]] + sd;
        e = e > 0.0f ? e : 0.2f * e;
        m = fmaxf(m, e);
    }
    #pragma unroll
    for (int o = 16; o > 0; o >>= 1) m = fmaxf(m, __shfl_xor_sync(0xffffffffu, m, o));

    float acc[NC] = {0,0,0,0,0,0,0};
    float den = 0.0f;
    for (int i = beg + lane; i < end; i += 32) {
        int s = g_csr_src[i];
        float e = g_ss[s] + sd;
        e = e > 0.0f ? e : 0.2f * e;
        float ee = __expf(e - m);
        den += ee;
        const float* hr = h + (size_t)s * NC;
        #pragma unroll
        for (int c = 0; c < NC; c++) acc[c] += ee * hr[c];
    }
    #pragma unroll
    for (int o = 16; o > 0; o >>= 1) {
        den += __shfl_xor_sync(0xffffffffu, den, o);
        #pragma unroll
        for (int c = 0; c < NC; c++) acc[c] += __shfl_xor_sync(0xffffffffu, acc[c], o);
    }
    if (lane == 0) {
        float inv = 1.0f / den;
        float z[NC], mx = -INFINITY;
        #pragma unroll
        for (int c = 0; c < NC; c++) {
            z[c] = acc[c] * inv + bias[c];
            mx = fmaxf(mx, z[c]);
        }
        float ssum = 0.0f;
        #pragma unroll
        for (int c = 0; c < NC; c++) ssum += __expf(z[c] - mx);
        float l = logf(ssum);
        float* o = out + (size_t)node * NC;
        #pragma unroll
        for (int c = 0; c < NC; c++) o[c] = z[c] - mx - l;
    }
}

// ==================== launcher ====================
extern "C" void kernel_launch(void* const* d_in, const int* in_sizes, int n_in,
                              void* d_out, int out_size) {
    const float* x   = (const float*)d_in[0];
    const void*  ei  = d_in[1];
    const float* W1  = (const float*)d_in[2];
    const float* as1 = (const float*)d_in[3];
    const float* ad1 = (const float*)d_in[4];
    const float* b1  = (const float*)d_in[5];
    const float* W2  = (const float*)d_in[6];
    const float* as2 = (const float*)d_in[7];
    const float* ad2 = (const float*)d_in[8];
    const float* b2  = (const float*)d_in[9];
    const float* W3  = (const float*)d_in[10];
    const float* as3 = (const float*)d_in[11];
    const float* ad3 = (const float*)d_in[12];
    const float* b3  = (const float*)d_in[13];
    float* out = (float*)d_out;

    float *buf1, *buf2;
    __half *h16, *a16, *b16;
    cudaGetSymbolAddress((void**)&buf1, g_buf1);
    cudaGetSymbolAddress((void**)&buf2, g_buf2);
    cudaGetSymbolAddress((void**)&h16, g_h16);
    cudaGetSymbolAddress((void**)&a16, g_A16);
    cudaGetSymbolAddress((void**)&b16, g_B16);

    cudaFuncSetAttribute(gemm1_tc_kernel, cudaFuncAttributeMaxDynamicSharedMemorySize, G1_SMEM);
    cudaFuncSetAttribute(gemm_tc_kernel, cudaFuncAttributeMaxDynamicSharedMemorySize, SMEM_DYN);

    const int BT = 256;
    const int edge_blocks      = (NE + BT - 1) / BT;
    const int node_warp_blocks = (N_NODES + (BT / 32) - 1) / (BT / 32);
    const int node_blocks      = (N_NODES + BT - 1) / BT;
    const int agg1_blocks      = (N_NODES * 2 + 7) / 8;   // 2 warps per node

    // ---- CSR build ----
    detect_kernel<<<1, 128>>>((const unsigned int*)ei);
    zero_deg_kernel<<<node_blocks, BT>>>();
    prep_edges_kernel<<<edge_blocks, BT>>>(ei);
    reduce_deg_kernel<<<NB, 256>>>();
    scan_bsums_kernel<<<1, 256>>>();
    scan_write_kernel<<<NB, 256>>>();
    scatter_kernel<<<edge_blocks, BT>>>();

    // ---------------- layer 1: F_IN -> H1 ----------------
    split_Wt_kernel<<<2048, BT>>>(W1, F_IN, H1, K1PAD, b16);
    gemm1_tc_kernel<<<dim3(H1 / 256, MPAD / 128), 512, G1_SMEM>>>(x, b16, h16);
    s_kernel_h16<<<node_warp_blocks, BT>>>(h16, as1, ad1, H1);
    alpha_kernel<<<node_warp_blocks, BT>>>();
    gat_agg_kernel<H1, 2, 1><<<agg1_blocks, BT>>>(h16, b1, nullptr, a16);

    // ---------------- layer 2: H1 -> H2 ----------------
    split_Wt_kernel<<<2048, BT>>>(W2, H1, H2, H1, b16);
    gemm_tc_kernel<<<dim3(H2 / 128, MPAD / 128), BT, SMEM_DYN>>>(a16, b16, h16, H1, H2);
    s_kernel_h16<<<node_warp_blocks, BT>>>(h16, as2, ad2, H2);
    alpha_kernel<<<node_warp_blocks, BT>>>();
    gat_agg_kernel<H2, 1, 0><<<node_warp_blocks, BT>>>(h16, b2, buf2, nullptr);

    // ---------------- layer 3: H2 -> NC ----------------
    gemm3_kernel<<<node_blocks, BT>>>(buf2, W3, buf1);
    s_kernel_scalar<<<node_warp_blocks, BT>>>(buf1, as3, ad3, NC);
    gat_agg3_final_kernel<<<node_warp_blocks, BT>>>(buf1, b3, out);
}

// round 15
// speedup vs baseline: 4.3962x; 1.0245x over previous
#include <cuda_runtime.h>
#include <cuda_fp16.h>
#include <math.h>
#include <stdint.h>

#define N_NODES 50000
#define MPAD    50048   // 391 * 128
#define E0      800000
#define NE      850000
#define F_IN    1433
#define K1PAD   1472    // 46 * 32
#define H1      512
#define H2      256
#define NC      7
#define NB      196     // ceil(N_NODES / 256)

// ==================== scratch (device globals) ====================
__device__ __half g_h16[(size_t)MPAD * H1];
__device__ __half g_A16[(size_t)MPAD * H1];
__device__ __half g_B16[(size_t)H1 * K1PAD];
__device__ float g_buf1[(size_t)MPAD * NC];
__device__ float g_buf2[(size_t)MPAD * H2];
__device__ float g_ss[N_NODES];
__device__ float g_sd[N_NODES];
__device__ float g_alpha[NE];
__device__ int   g_src[NE];
__device__ int   g_dst[NE];
__device__ int   g_csr_src[NE];
__device__ int   g_deg[N_NODES];
__device__ int   g_rowoff[N_NODES + 1];
__device__ int   g_cursor[N_NODES];
__device__ int   g_bsum[NB];
__device__ int   g_boff[NB];
__device__ int   g_is64;

// ==================== PTX helpers (base-arch only) ====================
__device__ __forceinline__ uint32_t smem_u32(const void* p) {
    uint32_t a;
    asm("{ .reg .u64 t; cvta.to.shared.u64 t, %1; cvt.u32.u64 %0, t; }" : "=r"(a) : "l"(p));
    return a;
}
__device__ __forceinline__ void cp16(uint32_t dst, const void* src) {
    asm volatile("cp.async.cg.shared.global [%0], [%1], 16;" :: "r"(dst), "l"(src));
}
__device__ __forceinline__ void ldm_x4(uint32_t& r0, uint32_t& r1, uint32_t& r2, uint32_t& r3,
                                       uint32_t addr) {
    asm volatile("ldmatrix.sync.aligned.m8n8.x4.shared.b16 {%0,%1,%2,%3}, [%4];"
                 : "=r"(r0), "=r"(r1), "=r"(r2), "=r"(r3) : "r"(addr));
}
__device__ __forceinline__ void mma_f16(float* c, const uint32_t* a, const uint32_t* b) {
    asm volatile("mma.sync.aligned.m16n8k16.row.col.f32.f16.f16.f32 "
                 "{%0,%1,%2,%3}, {%4,%5,%6,%7}, {%8,%9}, {%0,%1,%2,%3};"
                 : "+f"(c[0]), "+f"(c[1]), "+f"(c[2]), "+f"(c[3])
                 : "r"(a[0]), "r"(a[1]), "r"(a[2]), "r"(a[3]), "r"(b[0]), "r"(b[1]));
}

// Fused attention-score epilogue: partial dots from acc fragments -> atomic per-row.
// acc layout: acc[mi][ni][4]; rows (r_lo, r_lo+8); cols cc, cc+1.
__device__ __forceinline__ void epilogue_scores(
    const float acc[2][8][4], const float* __restrict__ a_s, const float* __restrict__ a_d,
    int m0, int n0, int warp_m, int warp_n, int lane) {
    const int er = lane >> 2, ec = (lane & 3) * 2;
    #pragma unroll
    for (int mi = 0; mi < 2; mi++) {
        float ss0 = 0.f, ss1 = 0.f, sd0 = 0.f, sd1 = 0.f;
        #pragma unroll
        for (int ni = 0; ni < 8; ni++) {
            const int cc = n0 + warp_n * 64 + ni * 8 + ec;
            float as0 = a_s[cc], as1 = a_s[cc + 1];
            float ad0 = a_d[cc], ad1 = a_d[cc + 1];
            ss0 += acc[mi][ni][0] * as0 + acc[mi][ni][1] * as1;
            ss1 += acc[mi][ni][2] * as0 + acc[mi][ni][3] * as1;
            sd0 += acc[mi][ni][0] * ad0 + acc[mi][ni][1] * ad1;
            sd1 += acc[mi][ni][2] * ad0 + acc[mi][ni][3] * ad1;
        }
        #pragma unroll
        for (int o = 1; o <= 2; o <<= 1) {
            ss0 += __shfl_xor_sync(0xffffffffu, ss0, o);
            ss1 += __shfl_xor_sync(0xffffffffu, ss1, o);
            sd0 += __shfl_xor_sync(0xffffffffu, sd0, o);
            sd1 += __shfl_xor_sync(0xffffffffu, sd1, o);
        }
        if ((lane & 3) == 0) {
            int r0 = m0 + warp_m * 32 + mi * 16 + er;
            int r1 = r0 + 8;
            if (r0 < N_NODES) { atomicAdd(&g_ss[r0], ss0); atomicAdd(&g_sd[r0], sd0); }
            if (r1 < N_NODES) { atomicAdd(&g_ss[r1], ss1); atomicAdd(&g_sd[r1], sd1); }
        }
    }
}

// ==================== edge prep + CSR build ====================
// merged: detect int64/int32 (block 0) + zero degree array (all blocks)
__global__ void init_kernel(const unsigned int* __restrict__ w) {
    if (blockIdx.x == 0) {
        __shared__ int nz;
        if (threadIdx.x == 0) nz = 0;
        __syncthreads();
        if (threadIdx.x < 128 && w[threadIdx.x * 2 + 1] != 0u) atomicOr(&nz, 1);
        __syncthreads();
        if (threadIdx.x == 0) g_is64 = (nz == 0);
    }
    int i = blockIdx.x * blockDim.x + threadIdx.x;
    if (i < N_NODES) g_deg[i] = 0;
}

__global__ void prep_edges_kernel(const void* __restrict__ ei) {
    int i = blockIdx.x * blockDim.x + threadIdx.x;
    if (i >= NE) return;
    int s, d;
    if (i < E0) {
        if (g_is64) {
            const long long* e = (const long long*)ei;
            s = (int)e[i]; d = (int)e[E0 + i];
        } else {
            const int* e = (const int*)ei;
            s = e[i]; d = e[E0 + i];
        }
    } else {
        s = d = i - E0;
    }
    s = min(max(s, 0), N_NODES - 1);
    d = min(max(d, 0), N_NODES - 1);
    g_src[i] = s;
    g_dst[i] = d;
    atomicAdd(&g_deg[d], 1);
}

__global__ void reduce_deg_kernel() {          // grid NB, 256
    __shared__ int sh[256];
    int i = blockIdx.x * 256 + threadIdx.x;
    sh[threadIdx.x] = (i < N_NODES) ? g_deg[i] : 0;
    __syncthreads();
    for (int o = 128; o > 0; o >>= 1) {
        if (threadIdx.x < o) sh[threadIdx.x] += sh[threadIdx.x + o];
        __syncthreads();
    }
    if (threadIdx.x == 0) g_bsum[blockIdx.x] = sh[0];
}

__global__ void scan_bsums_kernel() {          // 1 block, 256
    __shared__ int sh[256];
    int t = threadIdx.x;
    int mine = (t < NB) ? g_bsum[t] : 0;
    sh[t] = mine;
    __syncthreads();
    for (int o = 1; o < 256; o <<= 1) {
        int v = (t >= o) ? sh[t - o] : 0;
        __syncthreads();
        sh[t] += v;
        __syncthreads();
    }
    if (t < NB) g_boff[t] = sh[t] - mine;
    if (t == 0) g_rowoff[N_NODES] = NE;
}

__global__ void scan_write_kernel() {          // grid NB, 256
    __shared__ int sh[256];
    int i = blockIdx.x * 256 + threadIdx.x;
    int v = (i < N_NODES) ? g_deg[i] : 0;
    sh[threadIdx.x] = v;
    __syncthreads();
    for (int o = 1; o < 256; o <<= 1) {
        int u = (threadIdx.x >= o) ? sh[threadIdx.x - o] : 0;
        __syncthreads();
        sh[threadIdx.x] += u;
        __syncthreads();
    }
    if (i < N_NODES) {
        int excl = g_boff[blockIdx.x] + sh[threadIdx.x] - v;
        g_rowoff[i] = excl;
        g_cursor[i] = excl;
        g_ss[i] = 0.0f;     // layer-1 fused scores accumulate into these
        g_sd[i] = 0.0f;
    }
}

__global__ void scatter_kernel() {
    int i = blockIdx.x * blockDim.x + threadIdx.x;
    if (i >= NE) return;
    int pos = atomicAdd(&g_cursor[g_dst[i]], 1);
    g_csr_src[pos] = g_src[i];
}

// ==================== weight transpose+convert (fp16) ====================
__global__ void split_Wt_kernel(const float* __restrict__ W, int K, int N, int Kpad,
                                __half* __restrict__ hi) {
    size_t total = (size_t)N * Kpad;
    size_t i = (size_t)blockIdx.x * blockDim.x + threadIdx.x;
    size_t stride = (size_t)gridDim.x * blockDim.x;
    for (; i < total; i += stride) {
        int n = (int)(i / Kpad), k = (int)(i % Kpad);
        float v = (k < K) ? W[(size_t)k * N + n] : 0.0f;
        hi[i] = __float2half(v);
    }
}

// ==================== GEMM common ====================
#define KC        32
#define SPITCH    80
#define ARR_BYTES (128 * SPITCH)     // 10240 (128-row arrays)
#define B1_BYTES  (256 * SPITCH)     // 20480 (256-row B arrays for gemm1)

// ---------- layer-1 GEMM: CTA tile 128x256, 512 threads, fp32 A converted in-kernel ----------
#define G1_OFF_A  0
#define G1_B(s)   (ARR_BYTES + (s) * B1_BYTES)
#define G1_SMEM   (ARR_BYTES + 2 * B1_BYTES)   // 51200

__global__ void __launch_bounds__(512)
gemm1_tc_kernel(const float* __restrict__ Af,
                const __half* __restrict__ B16,
                __half* __restrict__ C16,
                const float* __restrict__ a_s, const float* __restrict__ a_d) {
    extern __shared__ char smem[];
    const uint32_t sb = smem_u32(smem);
    const int tid = threadIdx.x;
    const int wid = tid >> 5, lane = tid & 31;
    const int warp_m = wid & 3, warp_n = wid >> 2;   // 4 x 4 warps
    const int m0 = blockIdx.y * 128;
    const int n0 = blockIdx.x * 256;
    const int nchunks = K1PAD / KC;   // 46

    uint32_t bs[2]; size_t gB[2];
    #pragma unroll
    for (int t = 0; t < 2; t++) {
        int idx = tid + t * 512;
        int row = idx >> 2, seg = idx & 3;
        bs[t] = (uint32_t)row * SPITCH + seg * 16;
        gB[t] = (size_t)(n0 + row) * K1PAD + seg * 8;
    }

    const int arow = tid >> 2;
    const int acol0 = (tid & 3) * 8;
    const bool row_ok = (m0 + arow) < N_NODES;
    const float* arow_ptr = Af + (size_t)(m0 + arow) * F_IN;

    const int lr = lane & 7, g = lane >> 3;
    const uint32_t offA = (uint32_t)(warp_m * 32 + lr + (g & 1) * 8) * SPITCH + (g >> 1) * 16;
    const uint32_t offB = (uint32_t)(warp_n * 64 + lr + (g >> 1) * 8) * SPITCH + (g & 1) * 16;

    float acc[2][8][4];
    #pragma unroll
    for (int mi = 0; mi < 2; mi++)
        #pragma unroll
        for (int ni = 0; ni < 8; ni++)
            #pragma unroll
            for (int q = 0; q < 4; q++) acc[mi][ni][q] = 0.0f;

    float areg[8];
    {
        const uint32_t d = sb + G1_B(0);
        #pragma unroll
        for (int t = 0; t < 2; t++) cp16(d + bs[t], B16 + gB[t]);
        asm volatile("cp.async.commit_group;");
        if (row_ok) {
            #pragma unroll
            for (int j = 0; j < 8; j++) areg[j] = arow_ptr[acol0 + j];
        } else {
            #pragma unroll
            for (int j = 0; j < 8; j++) areg[j] = 0.0f;
        }
    }

    char* const aDst = smem + G1_OFF_A + (size_t)arow * SPITCH + acol0 * 2;

    for (int c = 0; c < nchunks; c++) {
        #pragma unroll
        for (int j = 0; j < 4; j++) {
            __half2 hh;
            hh.x = __float2half(areg[2 * j]);
            hh.y = __float2half(areg[2 * j + 1]);
            *(__half2*)(aDst + j * 4) = hh;
        }
        if (c + 1 < nchunks) {
            const uint32_t d = sb + G1_B((c + 1) & 1);
            const size_t ko = (size_t)(c + 1) * KC;
            #pragma unroll
            for (int t = 0; t < 2; t++) cp16(d + bs[t], B16 + gB[t] + ko);
            asm volatile("cp.async.commit_group;");
            const int cb = (c + 1) * KC + acol0;
            if (row_ok && cb + 8 <= F_IN) {
                #pragma unroll
                for (int j = 0; j < 8; j++) areg[j] = arow_ptr[cb + j];
            } else if (row_ok) {
                #pragma unroll
                for (int j = 0; j < 8; j++) areg[j] = (cb + j < F_IN) ? arow_ptr[cb + j] : 0.0f;
            } else {
                #pragma unroll
                for (int j = 0; j < 8; j++) areg[j] = 0.0f;
            }
            asm volatile("cp.async.wait_group 1;");
        } else {
            asm volatile("cp.async.wait_group 0;");
        }
        __syncthreads();

        const uint32_t bbase = sb + G1_B(c & 1);
        #pragma unroll
        for (int ks = 0; ks < 2; ks++) {
            const uint32_t kadd = ks * 32;
            uint32_t a16[2][4], b16[8][2];
            #pragma unroll
            for (int mt = 0; mt < 2; mt++)
                ldm_x4(a16[mt][0], a16[mt][1], a16[mt][2], a16[mt][3],
                       sb + G1_OFF_A + offA + mt * 16 * SPITCH + kadd);
            #pragma unroll
            for (int np = 0; np < 4; np++)
                ldm_x4(b16[2*np][0], b16[2*np][1], b16[2*np+1][0], b16[2*np+1][1],
                       bbase + offB + np * 16 * SPITCH + kadd);
            #pragma unroll
            for (int mi = 0; mi < 2; mi++)
                #pragma unroll
                for (int ni = 0; ni < 8; ni++)
                    mma_f16(acc[mi][ni], a16[mi], b16[ni]);
        }
        __syncthreads();
    }

    const int er = lane >> 2, ec = (lane & 3) * 2;
    #pragma unroll
    for (int mi = 0; mi < 2; mi++) {
        const int r_lo = m0 + warp_m * 32 + mi * 16 + er;
        #pragma unroll
        for (int ni = 0; ni < 8; ni++) {
            const int cc = n0 + warp_n * 64 + ni * 8 + ec;
            __half2 p0, p1;
            p0.x = __float2half(acc[mi][ni][0]); p0.y = __float2half(acc[mi][ni][1]);
            p1.x = __float2half(acc[mi][ni][2]); p1.y = __float2half(acc[mi][ni][3]);
            *(__half2*)(C16 + (size_t)r_lo * H1 + cc)       = p0;
            *(__half2*)(C16 + (size_t)(r_lo + 8) * H1 + cc) = p1;
        }
    }
    // fused attention scores
    epilogue_scores(acc, a_s, a_d, m0, n0, warp_m, warp_n, lane);
}

// ---------- layer-2 GEMM: fp16 A (cp.async), fp16 B, fp16 out, fused scores ----------
#define STG_BYTES (2 * ARR_BYTES)    // 20480
#define OFF_A16   0
#define OFF_B16   ARR_BYTES
#define SMEM_DYN  (2 * STG_BYTES)    // 40960

__global__ void __launch_bounds__(256)
gemm_tc_kernel(const __half* __restrict__ A16,
               const __half* __restrict__ B16,
               __half* __restrict__ C16, int Kpad, int Nc,
               const float* __restrict__ a_s, const float* __restrict__ a_d) {
    extern __shared__ char smem[];
    const uint32_t sb = smem_u32(smem);
    const int tid = threadIdx.x;
    const int wid = tid >> 5, lane = tid & 31;
    const int warp_m = wid & 3, warp_n = wid >> 2;
    const int m0 = blockIdx.y * 128;
    const int n0 = blockIdx.x * 128;
    const int nchunks = Kpad / KC;

    const int row0 = tid >> 2, seg = tid & 3;
    const int row1 = row0 + 64;
    const uint32_t s0 = (uint32_t)row0 * SPITCH + seg * 16;
    const uint32_t s1 = (uint32_t)row1 * SPITCH + seg * 16;
    const size_t gA0 = (size_t)(m0 + row0) * Kpad + seg * 8;
    const size_t gA1 = (size_t)(m0 + row1) * Kpad + seg * 8;
    const size_t gB0 = (size_t)(n0 + row0) * Kpad + seg * 8;
    const size_t gB1 = (size_t)(n0 + row1) * Kpad + seg * 8;

    const int lr = lane & 7, g = lane >> 3;
    const uint32_t offA = (uint32_t)(warp_m * 32 + lr + (g & 1) * 8) * SPITCH + (g >> 1) * 16;
    const uint32_t offB = (uint32_t)(warp_n * 64 + lr + (g >> 1) * 8) * SPITCH + (g & 1) * 16;

    float acc[2][8][4];
    #pragma unroll
    for (int mi = 0; mi < 2; mi++)
        #pragma unroll
        for (int ni = 0; ni < 8; ni++)
            #pragma unroll
            for (int q = 0; q < 4; q++) acc[mi][ni][q] = 0.0f;

    {
        const uint32_t d = sb;
        cp16(d + OFF_A16 + s0, A16 + gA0); cp16(d + OFF_A16 + s1, A16 + gA1);
        cp16(d + OFF_B16 + s0, B16 + gB0); cp16(d + OFF_B16 + s1, B16 + gB1);
        asm volatile("cp.async.commit_group;");
    }

    for (int c = 0; c < nchunks; c++) {
        if (c + 1 < nchunks) {
            const uint32_t d = sb + ((c + 1) & 1) * STG_BYTES;
            const size_t ko = (size_t)(c + 1) * KC;
            cp16(d + OFF_A16 + s0, A16 + gA0 + ko); cp16(d + OFF_A16 + s1, A16 + gA1 + ko);
            cp16(d + OFF_B16 + s0, B16 + gB0 + ko); cp16(d + OFF_B16 + s1, B16 + gB1 + ko);
            asm volatile("cp.async.commit_group;");
            asm volatile("cp.async.wait_group 1;");
        } else {
            asm volatile("cp.async.wait_group 0;");
        }
        __syncthreads();

        const uint32_t base = sb + (c & 1) * STG_BYTES;
        #pragma unroll
        for (int ks = 0; ks < 2; ks++) {
            const uint32_t kadd = ks * 32;
            uint32_t a16[2][4], b16[8][2];
            #pragma unroll
            for (int mt = 0; mt < 2; mt++)
                ldm_x4(a16[mt][0], a16[mt][1], a16[mt][2], a16[mt][3],
                       base + OFF_A16 + offA + mt * 16 * SPITCH + kadd);
            #pragma unroll
            for (int np = 0; np < 4; np++)
                ldm_x4(b16[2*np][0], b16[2*np][1], b16[2*np+1][0], b16[2*np+1][1],
                       base + OFF_B16 + offB + np * 16 * SPITCH + kadd);
            #pragma unroll
            for (int mi = 0; mi < 2; mi++)
                #pragma unroll
                for (int ni = 0; ni < 8; ni++)
                    mma_f16(acc[mi][ni], a16[mi], b16[ni]);
        }
        __syncthreads();
    }

    const int er = lane >> 2, ec = (lane & 3) * 2;
    #pragma unroll
    for (int mi = 0; mi < 2; mi++) {
        const int r_lo = m0 + warp_m * 32 + mi * 16 + er;
        #pragma unroll
        for (int ni = 0; ni < 8; ni++) {
            const int cc = n0 + warp_n * 64 + ni * 8 + ec;
            __half2 p0, p1;
            p0.x = __float2half(acc[mi][ni][0]); p0.y = __float2half(acc[mi][ni][1]);
            p1.x = __float2half(acc[mi][ni][2]); p1.y = __float2half(acc[mi][ni][3]);
            *(__half2*)(C16 + (size_t)r_lo * Nc + cc)       = p0;
            *(__half2*)(C16 + (size_t)(r_lo + 8) * Nc + cc) = p1;
        }
    }
    epilogue_scores(acc, a_s, a_d, m0, n0, warp_m, warp_n, lane);
}

// ==================== layer-3 attention scores (fp32 h, small) ====================
__global__ void s_kernel_scalar(const float* __restrict__ h, const float* __restrict__ a_s,
                                const float* __restrict__ a_d, int F) {
    int node = blockIdx.x * (blockDim.x >> 5) + (threadIdx.x >> 5);
    int lane = threadIdx.x & 31;
    if (node >= N_NODES) return;
    const float* hr = h + (size_t)node * F;
    float vs = 0.0f, vd = 0.0f;
    for (int f = lane; f < F; f += 32) {
        float x = hr[f];
        vs += x * a_s[f];
        vd += x * a_d[f];
    }
    #pragma unroll
    for (int o = 16; o > 0; o >>= 1) {
        vs += __shfl_down_sync(0xffffffffu, vs, o);
        vd += __shfl_down_sync(0xffffffffu, vd, o);
    }
    if (lane == 0) {
        g_ss[node] = vs;
        g_sd[node] = vd;
    }
}

// ==================== alpha prepass (warp per node) ====================
__global__ void __launch_bounds__(256)
alpha_kernel() {
    int node = blockIdx.x * 8 + (threadIdx.x >> 5);
    int lane = threadIdx.x & 31;
    if (node >= N_NODES) return;
    const int beg = g_rowoff[node], end = g_rowoff[node + 1];
    const float sd = g_sd[node];

    float m = -INFINITY;
    for (int i = beg + lane; i < end; i += 32) {
        float e = g_ss[g_csr_src[i]] + sd;
        e = e > 0.0f ? e : 0.2f * e;
        m = fmaxf(m, e);
    }
    #pragma unroll
    for (int o = 16; o > 0; o >>= 1) m = fmaxf(m, __shfl_xor_sync(0xffffffffu, m, o));

    float den = 0.0f;
    for (int i = beg + lane; i < end; i += 32) {
        float e = g_ss[g_csr_src[i]] + sd;
        e = e > 0.0f ? e : 0.2f * e;
        float ee = __expf(e - m);
        g_alpha[i] = ee;
        den += ee;
    }
    #pragma unroll
    for (int o = 16; o > 0; o >>= 1) den += __shfl_xor_sync(0xffffffffu, den, o);
    float inv = 1.0f / den;
    for (int i = beg + lane; i < end; i += 32) g_alpha[i] *= inv;
}

// ==================== weighted gather aggregation ====================
// ZERO_S=1 (agg1): zero ss/sd for next layer's fused-score atomics.
template <int F, int NW, int OUT_F16, int ZERO_S>
__global__ void __launch_bounds__(256)
gat_agg_kernel(const __half* __restrict__ h, const float* __restrict__ bias,
               float* __restrict__ outf, __half* __restrict__ oh) {
    int gw = blockIdx.x * 8 + (threadIdx.x >> 5);
    int lane = threadIdx.x & 31;
    int node = gw / NW, part = gw % NW;
    if (node >= N_NODES) return;
    if (ZERO_S && part == 0 && lane == 0) {
        g_ss[node] = 0.0f;
        g_sd[node] = 0.0f;
    }
    const int beg = g_rowoff[node], end = g_rowoff[node + 1];
    const uint32_t c8 = part * (F / NW) + lane * 8;

    float acc[8];
    #pragma unroll
    for (int q = 0; q < 8; q++) acc[q] = 0.0f;

    int i = beg;
    for (; i + 1 < end; i += 2) {
        int s0 = g_csr_src[i], s1 = g_csr_src[i + 1];
        float w0 = g_alpha[i], w1 = g_alpha[i + 1];
        uint4 r0 = *(const uint4*)(h + (size_t)s0 * F + c8);
        uint4 r1 = *(const uint4*)(h + (size_t)s1 * F + c8);
        const __half2* p0 = (const __half2*)&r0;
        const __half2* p1 = (const __half2*)&r1;
        #pragma unroll
        for (int q = 0; q < 4; q++) {
            float2 v0 = __half22float2(p0[q]);
            float2 v1 = __half22float2(p1[q]);
            acc[2*q+0] += w0 * v0.x + w1 * v1.x;
            acc[2*q+1] += w0 * v0.y + w1 * v1.y;
        }
    }
    if (i < end) {
        int s0 = g_csr_src[i];
        float w0 = g_alpha[i];
        uint4 r0 = *(const uint4*)(h + (size_t)s0 * F + c8);
        const __half2* p0 = (const __half2*)&r0;
        #pragma unroll
        for (int q = 0; q < 4; q++) {
            float2 v0 = __half22float2(p0[q]);
            acc[2*q+0] += w0 * v0.x;
            acc[2*q+1] += w0 * v0.y;
        }
    }

    float v[8];
    #pragma unroll
    for (int q = 0; q < 8; q++) v[q] = fmaxf(acc[q] + bias[c8 + q], 0.0f);
    size_t o = (size_t)node * F + c8;
    if (OUT_F16) {
        uint4 packed;
        __half2* hp = (__half2*)&packed;
        #pragma unroll
        for (int q = 0; q < 4; q++) {
            __half2 p;
            p.x = __float2half(v[2*q]); p.y = __float2half(v[2*q+1]);
            hp[q] = p;
        }
        *(uint4*)(oh + o) = packed;
    } else {
        *(float4*)(outf + o)     = make_float4(v[0], v[1], v[2], v[3]);
        *(float4*)(outf + o + 4) = make_float4(v[4], v[5], v[6], v[7]);
    }
}

// ==================== layer 3: skinny GEMM (smem W) + fused agg+logsoftmax ====================
__global__ void __launch_bounds__(256)
gemm3_kernel(const float* __restrict__ A, const float* __restrict__ W,
             float* __restrict__ C) {
    __shared__ float sW[H2 * NC];
    for (int i = threadIdx.x; i < H2 * NC; i += blockDim.x) sW[i] = W[i];
    __syncthreads();
    int node = blockIdx.x * blockDim.x + threadIdx.x;
    if (node >= N_NODES) return;
    const float4* a4 = (const float4*)(A + (size_t)node * H2);
    float acc[NC] = {0,0,0,0,0,0,0};
    #pragma unroll 4
    for (int k4 = 0; k4 < H2 / 4; k4++) {
        float4 a = a4[k4];
        const float* w0 = sW + (k4 * 4) * NC;
        #pragma unroll
        for (int c = 0; c < NC; c++)
            acc[c] += a.x * w0[c] + a.y * w0[NC + c] + a.z * w0[2 * NC + c] + a.w * w0[3 * NC + c];
    }
    #pragma unroll
    for (int c = 0; c < NC; c++) C[(size_t)node * NC + c] = acc[c];
}

__global__ void __launch_bounds__(256)
gat_agg3_final_kernel(const float* __restrict__ h, const float* __restrict__ bias,
                      float* __restrict__ out) {
    int node = blockIdx.x * 8 + (threadIdx.x >> 5);
    int lane = threadIdx.x & 31;
    if (node >= N_NODES) return;
    const int beg = g_rowoff[node], end = g_rowoff[node + 1];
    const float sd = g_sd[node];

    float m = -INFINITY;
    for (int i = beg + lane; i < end; i += 32) {
        float e = g_ss[g_csr_src[i]] + sd;
        e = e > 0.0f ? e : 0.2f * e;
        m = fmaxf(m, e);
    }
    #pragma unroll
    for (int o = 16; o > 0; o >>= 1) m = fmaxf(m, __shfl_xor_sync(0xffffffffu, m, o));

    float acc[NC] = {0,0,0,0,0,0,0};
    float den = 0.0f;
    for (int i = beg + lane; i < end; i += 32) {
        int s = g_csr_src[i];
        float e = g_ss[s] + sd;
        e = e > 0.0f ? e : 0.2f * e;
        float ee = __expf(e - m);
        den += ee;
        const float* hr = h + (size_t)s * NC;
        #pragma unroll
        for (int c = 0; c < NC; c++) acc[c] += ee * hr[c];
    }
    #pragma unroll
    for (int o = 16; o > 0; o >>= 1) {
        den += __shfl_xor_sync(0xffffffffu, den, o);
        #pragma unroll
        for (int c = 0; c < NC; c++) acc[c] += __shfl_xor_sync(0xffffffffu, acc[c], o);
    }
    if (lane == 0) {
        float inv = 1.0f / den;
        float z[NC], mx = -INFINITY;
        #pragma unroll
        for (int c = 0; c < NC; c++) {
            z[c] = acc[c] * inv + bias[c];
            mx = fmaxf(mx, z[c]);
        }
        float ssum = 0.0f;
        #pragma unroll
        for (int c = 0; c < NC; c++) ssum += __expf(z[c] - mx);
        float l = logf(ssum);
        float* o = out + (size_t)node * NC;
        #pragma unroll
        for (int c = 0; c < NC; c++) o[c] = z[c] - mx - l;
    }
}

// ==================== launcher ====================
extern "C" void kernel_launch(void* const* d_in, const int* in_sizes, int n_in,
                              void* d_out, int out_size) {
    const float* x   = (const float*)d_in[0];
    const void*  ei  = d_in[1];
    const float* W1  = (const float*)d_in[2];
    const float* as1 = (const float*)d_in[3];
    const float* ad1 = (const float*)d_in[4];
    const float* b1  = (const float*)d_in[5];
    const float* W2  = (const float*)d_in[6];
    const float* as2 = (const float*)d_in[7];
    const float* ad2 = (const float*)d_in[8];
    const float* b2  = (const float*)d_in[9];
    const float* W3  = (const float*)d_in[10];
    const float* as3 = (const float*)d_in[11];
    const float* ad3 = (const float*)d_in[12];
    const float* b3  = (const float*)d_in[13];
    float* out = (float*)d_out;

    float *buf1, *buf2;
    __half *h16, *a16, *b16;
    cudaGetSymbolAddress((void**)&buf1, g_buf1);
    cudaGetSymbolAddress((void**)&buf2, g_buf2);
    cudaGetSymbolAddress((void**)&h16, g_h16);
    cudaGetSymbolAddress((void**)&a16, g_A16);
    cudaGetSymbolAddress((void**)&b16, g_B16);

    cudaFuncSetAttribute(gemm1_tc_kernel, cudaFuncAttributeMaxDynamicSharedMemorySize, G1_SMEM);
    cudaFuncSetAttribute(gemm_tc_kernel, cudaFuncAttributeMaxDynamicSharedMemorySize, SMEM_DYN);

    const int BT = 256;
    const int edge_blocks      = (NE + BT - 1) / BT;
    const int node_warp_blocks = (N_NODES + (BT / 32) - 1) / (BT / 32);
    const int node_blocks      = (N_NODES + BT - 1) / BT;
    const int agg1_blocks      = (N_NODES * 2 + 7) / 8;   // 2 warps per node

    // ---- CSR build (also zeroes ss/sd for layer-1 fused scores) ----
    init_kernel<<<node_blocks, BT>>>((const unsigned int*)ei);
    prep_edges_kernel<<<edge_blocks, BT>>>(ei);
    reduce_deg_kernel<<<NB, 256>>>();
    scan_bsums_kernel<<<1, 256>>>();
    scan_write_kernel<<<NB, 256>>>();
    scatter_kernel<<<edge_blocks, BT>>>();

    // ---------------- layer 1: F_IN -> H1 (scores fused into GEMM) ----------------
    split_Wt_kernel<<<2048, BT>>>(W1, F_IN, H1, K1PAD, b16);
    gemm1_tc_kernel<<<dim3(H1 / 256, MPAD / 128), 512, G1_SMEM>>>(x, b16, h16, as1, ad1);
    alpha_kernel<<<node_warp_blocks, BT>>>();
    gat_agg_kernel<H1, 2, 1, 1><<<agg1_blocks, BT>>>(h16, b1, nullptr, a16);

    // ---------------- layer 2: H1 -> H2 (scores fused into GEMM) ----------------
    split_Wt_kernel<<<2048, BT>>>(W2, H1, H2, H1, b16);
    gemm_tc_kernel<<<dim3(H2 / 128, MPAD / 128), BT, SMEM_DYN>>>(a16, b16, h16, H1, H2, as2, ad2);
    alpha_kernel<<<node_warp_blocks, BT>>>();
    gat_agg_kernel<H2, 1, 0, 0><<<node_warp_blocks, BT>>>(h16, b2, buf2, nullptr);

    // ---------------- layer 3: H2 -> NC ----------------
    gemm3_kernel<<<node_blocks, BT>>>(buf2, W3, buf1);
    s_kernel_scalar<<<node_warp_blocks, BT>>>(buf1, as3, ad3, NC);
    gat_agg3_final_kernel<<<node_warp_blocks, BT>>>(buf1, b3, out);
}

// round 16
// speedup vs baseline: 4.5421x; 1.0332x over previous
#include <cuda_runtime.h>
#include <cuda_fp16.h>
#include <math.h>
#include <stdint.h>

#define N_NODES 50000
#define MPAD    50048   // 391 * 128
#define E0      800000
#define NE      850000
#define F_IN    1433
#define K1PAD   1472    // 46 * 32
#define H1      512
#define H2      256
#define NC      7
#define NB      196     // ceil(N_NODES / 256)

// ==================== scratch (device globals) ====================
__device__ __half g_h16[(size_t)MPAD * H1];
__device__ __half g_A16[(size_t)MPAD * H1];
__device__ __half g_B16[(size_t)H1 * K1PAD];
__device__ __half g_B16b[(size_t)H2 * H1];
__device__ float g_buf1[(size_t)MPAD * NC];
__device__ float g_buf2[(size_t)MPAD * H2];
__device__ float g_ss[N_NODES];
__device__ float g_sd[N_NODES];
__device__ float g_alpha[NE];
__device__ int   g_src[NE];
__device__ int   g_dst[NE];
__device__ int   g_csr_src[NE];
__device__ int   g_deg[N_NODES];
__device__ int   g_rowoff[N_NODES + 1];
__device__ int   g_cursor[N_NODES];
__device__ int   g_bsum[NB];
__device__ int   g_boff[NB];
__device__ int   g_is64;

// ==================== PTX helpers (base-arch only) ====================
__device__ __forceinline__ uint32_t smem_u32(const void* p) {
    uint32_t a;
    asm("{ .reg .u64 t; cvta.to.shared.u64 t, %1; cvt.u32.u64 %0, t; }" : "=r"(a) : "l"(p));
    return a;
}
__device__ __forceinline__ void cp16(uint32_t dst, const void* src) {
    asm volatile("cp.async.cg.shared.global [%0], [%1], 16;" :: "r"(dst), "l"(src));
}
__device__ __forceinline__ void ldm_x4(uint32_t& r0, uint32_t& r1, uint32_t& r2, uint32_t& r3,
                                       uint32_t addr) {
    asm volatile("ldmatrix.sync.aligned.m8n8.x4.shared.b16 {%0,%1,%2,%3}, [%4];"
                 : "=r"(r0), "=r"(r1), "=r"(r2), "=r"(r3) : "r"(addr));
}
__device__ __forceinline__ void mma_f16(float* c, const uint32_t* a, const uint32_t* b) {
    asm volatile("mma.sync.aligned.m16n8k16.row.col.f32.f16.f16.f32 "
                 "{%0,%1,%2,%3}, {%4,%5,%6,%7}, {%8,%9}, {%0,%1,%2,%3};"
                 : "+f"(c[0]), "+f"(c[1]), "+f"(c[2]), "+f"(c[3])
                 : "r"(a[0]), "r"(a[1]), "r"(a[2]), "r"(a[3]), "r"(b[0]), "r"(b[1]));
}

// Fused attention-score epilogue: partial dots from acc fragments -> atomic per-row.
__device__ __forceinline__ void epilogue_scores(
    const float acc[2][8][4], const float* __restrict__ a_s, const float* __restrict__ a_d,
    int m0, int n0, int warp_m, int warp_n, int lane) {
    const int er = lane >> 2, ec = (lane & 3) * 2;
    #pragma unroll
    for (int mi = 0; mi < 2; mi++) {
        float ss0 = 0.f, ss1 = 0.f, sd0 = 0.f, sd1 = 0.f;
        #pragma unroll
        for (int ni = 0; ni < 8; ni++) {
            const int cc = n0 + warp_n * 64 + ni * 8 + ec;
            float as0 = a_s[cc], as1 = a_s[cc + 1];
            float ad0 = a_d[cc], ad1 = a_d[cc + 1];
            ss0 += acc[mi][ni][0] * as0 + acc[mi][ni][1] * as1;
            ss1 += acc[mi][ni][2] * as0 + acc[mi][ni][3] * as1;
            sd0 += acc[mi][ni][0] * ad0 + acc[mi][ni][1] * ad1;
            sd1 += acc[mi][ni][2] * ad0 + acc[mi][ni][3] * ad1;
        }
        #pragma unroll
        for (int o = 1; o <= 2; o <<= 1) {
            ss0 += __shfl_xor_sync(0xffffffffu, ss0, o);
            ss1 += __shfl_xor_sync(0xffffffffu, ss1, o);
            sd0 += __shfl_xor_sync(0xffffffffu, sd0, o);
            sd1 += __shfl_xor_sync(0xffffffffu, sd1, o);
        }
        if ((lane & 3) == 0) {
            int r0 = m0 + warp_m * 32 + mi * 16 + er;
            int r1 = r0 + 8;
            if (r0 < N_NODES) { atomicAdd(&g_ss[r0], ss0); atomicAdd(&g_sd[r0], sd0); }
            if (r1 < N_NODES) { atomicAdd(&g_ss[r1], ss1); atomicAdd(&g_sd[r1], sd1); }
        }
    }
}

// ==================== edge prep + CSR build ====================
__global__ void init_kernel(const unsigned int* __restrict__ w) {
    if (blockIdx.x == 0) {
        __shared__ int nz;
        if (threadIdx.x == 0) nz = 0;
        __syncthreads();
        if (threadIdx.x < 128 && w[threadIdx.x * 2 + 1] != 0u) atomicOr(&nz, 1);
        __syncthreads();
        if (threadIdx.x == 0) g_is64 = (nz == 0);
    }
    int i = blockIdx.x * blockDim.x + threadIdx.x;
    if (i < N_NODES) g_deg[i] = 0;
}

__global__ void zero_s_kernel() {
    int i = blockIdx.x * blockDim.x + threadIdx.x;
    if (i < N_NODES) {
        g_ss[i] = 0.0f;
        g_sd[i] = 0.0f;
    }
}

__global__ void prep_edges_kernel(const void* __restrict__ ei) {
    int i = blockIdx.x * blockDim.x + threadIdx.x;
    if (i >= NE) return;
    int s, d;
    if (i < E0) {
        if (g_is64) {
            const long long* e = (const long long*)ei;
            s = (int)e[i]; d = (int)e[E0 + i];
        } else {
            const int* e = (const int*)ei;
            s = e[i]; d = e[E0 + i];
        }
    } else {
        s = d = i - E0;
    }
    s = min(max(s, 0), N_NODES - 1);
    d = min(max(d, 0), N_NODES - 1);
    g_src[i] = s;
    g_dst[i] = d;
    atomicAdd(&g_deg[d], 1);
}

__global__ void reduce_deg_kernel() {          // grid NB, 256
    __shared__ int sh[256];
    int i = blockIdx.x * 256 + threadIdx.x;
    sh[threadIdx.x] = (i < N_NODES) ? g_deg[i] : 0;
    __syncthreads();
    for (int o = 128; o > 0; o >>= 1) {
        if (threadIdx.x < o) sh[threadIdx.x] += sh[threadIdx.x + o];
        __syncthreads();
    }
    if (threadIdx.x == 0) g_bsum[blockIdx.x] = sh[0];
}

__global__ void scan_bsums_kernel() {          // 1 block, 256
    __shared__ int sh[256];
    int t = threadIdx.x;
    int mine = (t < NB) ? g_bsum[t] : 0;
    sh[t] = mine;
    __syncthreads();
    for (int o = 1; o < 256; o <<= 1) {
        int v = (t >= o) ? sh[t - o] : 0;
        __syncthreads();
        sh[t] += v;
        __syncthreads();
    }
    if (t < NB) g_boff[t] = sh[t] - mine;
    if (t == 0) g_rowoff[N_NODES] = NE;
}

__global__ void scan_write_kernel() {          // grid NB, 256
    __shared__ int sh[256];
    int i = blockIdx.x * 256 + threadIdx.x;
    int v = (i < N_NODES) ? g_deg[i] : 0;
    sh[threadIdx.x] = v;
    __syncthreads();
    for (int o = 1; o < 256; o <<= 1) {
        int u = (threadIdx.x >= o) ? sh[threadIdx.x - o] : 0;
        __syncthreads();
        sh[threadIdx.x] += u;
        __syncthreads();
    }
    if (i < N_NODES) {
        int excl = g_boff[blockIdx.x] + sh[threadIdx.x] - v;
        g_rowoff[i] = excl;
        g_cursor[i] = excl;
    }
}

__global__ void scatter_kernel() {
    int i = blockIdx.x * blockDim.x + threadIdx.x;
    if (i >= NE) return;
    int pos = atomicAdd(&g_cursor[g_dst[i]], 1);
    g_csr_src[pos] = g_src[i];
}

// ==================== weight transpose+convert (fp16) ====================
__global__ void split_Wt_kernel(const float* __restrict__ W, int K, int N, int Kpad,
                                __half* __restrict__ hi) {
    size_t total = (size_t)N * Kpad;
    size_t i = (size_t)blockIdx.x * blockDim.x + threadIdx.x;
    size_t stride = (size_t)gridDim.x * blockDim.x;
    for (; i < total; i += stride) {
        int n = (int)(i / Kpad), k = (int)(i % Kpad);
        float v = (k < K) ? W[(size_t)k * N + n] : 0.0f;
        hi[i] = __float2half(v);
    }
}

// ==================== GEMM common ====================
#define KC        32
#define SPITCH    80
#define ARR_BYTES (128 * SPITCH)     // 10240
#define B1_BYTES  (256 * SPITCH)     // 20480

// ---------- layer-1 GEMM: CTA tile 128x256, 512 threads, fp32 A converted in-kernel ----------
#define G1_OFF_A  0
#define G1_B(s)   (ARR_BYTES + (s) * B1_BYTES)
#define G1_SMEM   (ARR_BYTES + 2 * B1_BYTES)   // 51200

__global__ void __launch_bounds__(512)
gemm1_tc_kernel(const float* __restrict__ Af,
                const __half* __restrict__ B16,
                __half* __restrict__ C16,
                const float* __restrict__ a_s, const float* __restrict__ a_d) {
    extern __shared__ char smem[];
    const uint32_t sb = smem_u32(smem);
    const int tid = threadIdx.x;
    const int wid = tid >> 5, lane = tid & 31;
    const int warp_m = wid & 3, warp_n = wid >> 2;   // 4 x 4 warps
    const int m0 = blockIdx.y * 128;
    const int n0 = blockIdx.x * 256;
    const int nchunks = K1PAD / KC;   // 46

    uint32_t bs[2]; size_t gB[2];
    #pragma unroll
    for (int t = 0; t < 2; t++) {
        int idx = tid + t * 512;
        int row = idx >> 2, seg = idx & 3;
        bs[t] = (uint32_t)row * SPITCH + seg * 16;
        gB[t] = (size_t)(n0 + row) * K1PAD + seg * 8;
    }

    const int arow = tid >> 2;
    const int acol0 = (tid & 3) * 8;
    const bool row_ok = (m0 + arow) < N_NODES;
    const float* arow_ptr = Af + (size_t)(m0 + arow) * F_IN;

    const int lr = lane & 7, g = lane >> 3;
    const uint32_t offA = (uint32_t)(warp_m * 32 + lr + (g & 1) * 8) * SPITCH + (g >> 1) * 16;
    const uint32_t offB = (uint32_t)(warp_n * 64 + lr + (g >> 1) * 8) * SPITCH + (g & 1) * 16;

    float acc[2][8][4];
    #pragma unroll
    for (int mi = 0; mi < 2; mi++)
        #pragma unroll
        for (int ni = 0; ni < 8; ni++)
            #pragma unroll
            for (int q = 0; q < 4; q++) acc[mi][ni][q] = 0.0f;

    float areg[8];
    {
        const uint32_t d = sb + G1_B(0);
        #pragma unroll
        for (int t = 0; t < 2; t++) cp16(d + bs[t], B16 + gB[t]);
        asm volatile("cp.async.commit_group;");
        if (row_ok) {
            #pragma unroll
            for (int j = 0; j < 8; j++) areg[j] = arow_ptr[acol0 + j];
        } else {
            #pragma unroll
            for (int j = 0; j < 8; j++) areg[j] = 0.0f;
        }
    }

    char* const aDst = smem + G1_OFF_A + (size_t)arow * SPITCH + acol0 * 2;

    for (int c = 0; c < nchunks; c++) {
        #pragma unroll
        for (int j = 0; j < 4; j++) {
            __half2 hh;
            hh.x = __float2half(areg[2 * j]);
            hh.y = __float2half(areg[2 * j + 1]);
            *(__half2*)(aDst + j * 4) = hh;
        }
        if (c + 1 < nchunks) {
            const uint32_t d = sb + G1_B((c + 1) & 1);
            const size_t ko = (size_t)(c + 1) * KC;
            #pragma unroll
            for (int t = 0; t < 2; t++) cp16(d + bs[t], B16 + gB[t] + ko);
            asm volatile("cp.async.commit_group;");
            const int cb = (c + 1) * KC + acol0;
            if (row_ok && cb + 8 <= F_IN) {
                #pragma unroll
                for (int j = 0; j < 8; j++) areg[j] = arow_ptr[cb + j];
            } else if (row_ok) {
                #pragma unroll
                for (int j = 0; j < 8; j++) areg[j] = (cb + j < F_IN) ? arow_ptr[cb + j] : 0.0f;
            } else {
                #pragma unroll
                for (int j = 0; j < 8; j++) areg[j] = 0.0f;
            }
            asm volatile("cp.async.wait_group 1;");
        } else {
            asm volatile("cp.async.wait_group 0;");
        }
        __syncthreads();

        const uint32_t bbase = sb + G1_B(c & 1);
        #pragma unroll
        for (int ks = 0; ks < 2; ks++) {
            const uint32_t kadd = ks * 32;
            uint32_t a16[2][4], b16[8][2];
            #pragma unroll
            for (int mt = 0; mt < 2; mt++)
                ldm_x4(a16[mt][0], a16[mt][1], a16[mt][2], a16[mt][3],
                       sb + G1_OFF_A + offA + mt * 16 * SPITCH + kadd);
            #pragma unroll
            for (int np = 0; np < 4; np++)
                ldm_x4(b16[2*np][0], b16[2*np][1], b16[2*np+1][0], b16[2*np+1][1],
                       bbase + offB + np * 16 * SPITCH + kadd);
            #pragma unroll
            for (int mi = 0; mi < 2; mi++)
                #pragma unroll
                for (int ni = 0; ni < 8; ni++)
                    mma_f16(acc[mi][ni], a16[mi], b16[ni]);
        }
        __syncthreads();
    }

    const int er = lane >> 2, ec = (lane & 3) * 2;
    #pragma unroll
    for (int mi = 0; mi < 2; mi++) {
        const int r_lo = m0 + warp_m * 32 + mi * 16 + er;
        #pragma unroll
        for (int ni = 0; ni < 8; ni++) {
            const int cc = n0 + warp_n * 64 + ni * 8 + ec;
            __half2 p0, p1;
            p0.x = __float2half(acc[mi][ni][0]); p0.y = __float2half(acc[mi][ni][1]);
            p1.x = __float2half(acc[mi][ni][2]); p1.y = __float2half(acc[mi][ni][3]);
            *(__half2*)(C16 + (size_t)r_lo * H1 + cc)       = p0;
            *(__half2*)(C16 + (size_t)(r_lo + 8) * H1 + cc) = p1;
        }
    }
    epilogue_scores(acc, a_s, a_d, m0, n0, warp_m, warp_n, lane);
}

// ---------- layer-2 GEMM: fp16 A (cp.async), fp16 B, fp16 out, fused scores ----------
#define STG_BYTES (2 * ARR_BYTES)
#define OFF_A16   0
#define OFF_B16   ARR_BYTES
#define SMEM_DYN  (2 * STG_BYTES)

__global__ void __launch_bounds__(256)
gemm_tc_kernel(const __half* __restrict__ A16,
               const __half* __restrict__ B16,
               __half* __restrict__ C16, int Kpad, int Nc,
               const float* __restrict__ a_s, const float* __restrict__ a_d) {
    extern __shared__ char smem[];
    const uint32_t sb = smem_u32(smem);
    const int tid = threadIdx.x;
    const int wid = tid >> 5, lane = tid & 31;
    const int warp_m = wid & 3, warp_n = wid >> 2;
    const int m0 = blockIdx.y * 128;
    const int n0 = blockIdx.x * 128;
    const int nchunks = Kpad / KC;

    const int row0 = tid >> 2, seg = tid & 3;
    const int row1 = row0 + 64;
    const uint32_t s0 = (uint32_t)row0 * SPITCH + seg * 16;
    const uint32_t s1 = (uint32_t)row1 * SPITCH + seg * 16;
    const size_t gA0 = (size_t)(m0 + row0) * Kpad + seg * 8;
    const size_t gA1 = (size_t)(m0 + row1) * Kpad + seg * 8;
    const size_t gB0 = (size_t)(n0 + row0) * Kpad + seg * 8;
    const size_t gB1 = (size_t)(n0 + row1) * Kpad + seg * 8;

    const int lr = lane & 7, g = lane >> 3;
    const uint32_t offA = (uint32_t)(warp_m * 32 + lr + (g & 1) * 8) * SPITCH + (g >> 1) * 16;
    const uint32_t offB = (uint32_t)(warp_n * 64 + lr + (g >> 1) * 8) * SPITCH + (g & 1) * 16;

    float acc[2][8][4];
    #pragma unroll
    for (int mi = 0; mi < 2; mi++)
        #pragma unroll
        for (int ni = 0; ni < 8; ni++)
            #pragma unroll
            for (int q = 0; q < 4; q++) acc[mi][ni][q] = 0.0f;

    {
        const uint32_t d = sb;
        cp16(d + OFF_A16 + s0, A16 + gA0); cp16(d + OFF_A16 + s1, A16 + gA1);
        cp16(d + OFF_B16 + s0, B16 + gB0); cp16(d + OFF_B16 + s1, B16 + gB1);
        asm volatile("cp.async.commit_group;");
    }

    for (int c = 0; c < nchunks; c++) {
        if (c + 1 < nchunks) {
            const uint32_t d = sb + ((c + 1) & 1) * STG_BYTES;
            const size_t ko = (size_t)(c + 1) * KC;
            cp16(d + OFF_A16 + s0, A16 + gA0 + ko); cp16(d + OFF_A16 + s1, A16 + gA1 + ko);
            cp16(d + OFF_B16 + s0, B16 + gB0 + ko); cp16(d + OFF_B16 + s1, B16 + gB1 + ko);
            asm volatile("cp.async.commit_group;");
            asm volatile("cp.async.wait_group 1;");
        } else {
            asm volatile("cp.async.wait_group 0;");
        }
        __syncthreads();

        const uint32_t base = sb + (c & 1) * STG_BYTES;
        #pragma unroll
        for (int ks = 0; ks < 2; ks++) {
            const uint32_t kadd = ks * 32;
            uint32_t a16[2][4], b16[8][2];
            #pragma unroll
            for (int mt = 0; mt < 2; mt++)
                ldm_x4(a16[mt][0], a16[mt][1], a16[mt][2], a16[mt][3],
                       base + OFF_A16 + offA + mt * 16 * SPITCH + kadd);
            #pragma unroll
            for (int np = 0; np < 4; np++)
                ldm_x4(b16[2*np][0], b16[2*np][1], b16[2*np+1][0], b16[2*np+1][1],
                       base + OFF_B16 + offB + np * 16 * SPITCH + kadd);
            #pragma unroll
            for (int mi = 0; mi < 2; mi++)
                #pragma unroll
                for (int ni = 0; ni < 8; ni++)
                    mma_f16(acc[mi][ni], a16[mi], b16[ni]);
        }
        __syncthreads();
    }

    const int er = lane >> 2, ec = (lane & 3) * 2;
    #pragma unroll
    for (int mi = 0; mi < 2; mi++) {
        const int r_lo = m0 + warp_m * 32 + mi * 16 + er;
        #pragma unroll
        for (int ni = 0; ni < 8; ni++) {
            const int cc = n0 + warp_n * 64 + ni * 8 + ec;
            __half2 p0, p1;
            p0.x = __float2half(acc[mi][ni][0]); p0.y = __float2half(acc[mi][ni][1]);
            p1.x = __float2half(acc[mi][ni][2]); p1.y = __float2half(acc[mi][ni][3]);
            *(__half2*)(C16 + (size_t)r_lo * Nc + cc)       = p0;
            *(__half2*)(C16 + (size_t)(r_lo + 8) * Nc + cc) = p1;
        }
    }
    epilogue_scores(acc, a_s, a_d, m0, n0, warp_m, warp_n, lane);
}

// ==================== alpha prepass (warp per node) ====================
__global__ void __launch_bounds__(256)
alpha_kernel() {
    int node = blockIdx.x * 8 + (threadIdx.x >> 5);
    int lane = threadIdx.x & 31;
    if (node >= N_NODES) return;
    const int beg = g_rowoff[node], end = g_rowoff[node + 1];
    const float sd = g_sd[node];

    float m = -INFINITY;
    for (int i = beg + lane; i < end; i += 32) {
        float e = g_ss[g_csr_src[i]] + sd;
        e = e > 0.0f ? e : 0.2f * e;
        m = fmaxf(m, e);
    }
    #pragma unroll
    for (int o = 16; o > 0; o >>= 1) m = fmaxf(m, __shfl_xor_sync(0xffffffffu, m, o));

    float den = 0.0f;
    for (int i = beg + lane; i < end; i += 32) {
        float e = g_ss[g_csr_src[i]] + sd;
        e = e > 0.0f ? e : 0.2f * e;
        float ee = __expf(e - m);
        g_alpha[i] = ee;
        den += ee;
    }
    #pragma unroll
    for (int o = 16; o > 0; o >>= 1) den += __shfl_xor_sync(0xffffffffu, den, o);
    float inv = 1.0f / den;
    for (int i = beg + lane; i < end; i += 32) g_alpha[i] *= inv;
}

// ==================== weighted gather aggregation ====================
template <int F, int NW, int OUT_F16, int ZERO_S>
__global__ void __launch_bounds__(256)
gat_agg_kernel(const __half* __restrict__ h, const float* __restrict__ bias,
               float* __restrict__ outf, __half* __restrict__ oh) {
    int gw = blockIdx.x * 8 + (threadIdx.x >> 5);
    int lane = threadIdx.x & 31;
    int node = gw / NW, part = gw % NW;
    if (node >= N_NODES) return;
    if (ZERO_S && part == 0 && lane == 0) {
        g_ss[node] = 0.0f;
        g_sd[node] = 0.0f;
    }
    const int beg = g_rowoff[node], end = g_rowoff[node + 1];
    const uint32_t c8 = part * (F / NW) + lane * 8;

    float acc[8];
    #pragma unroll
    for (int q = 0; q < 8; q++) acc[q] = 0.0f;

    int i = beg;
    for (; i + 1 < end; i += 2) {
        int s0 = g_csr_src[i], s1 = g_csr_src[i + 1];
        float w0 = g_alpha[i], w1 = g_alpha[i + 1];
        uint4 r0 = *(const uint4*)(h + (size_t)s0 * F + c8);
        uint4 r1 = *(const uint4*)(h + (size_t)s1 * F + c8);
        const __half2* p0 = (const __half2*)&r0;
        const __half2* p1 = (const __half2*)&r1;
        #pragma unroll
        for (int q = 0; q < 4; q++) {
            float2 v0 = __half22float2(p0[q]);
            float2 v1 = __half22float2(p1[q]);
            acc[2*q+0] += w0 * v0.x + w1 * v1.x;
            acc[2*q+1] += w0 * v0.y + w1 * v1.y;
        }
    }
    if (i < end) {
        int s0 = g_csr_src[i];
        float w0 = g_alpha[i];
        uint4 r0 = *(const uint4*)(h + (size_t)s0 * F + c8);
        const __half2* p0 = (const __half2*)&r0;
        #pragma unroll
        for (int q = 0; q < 4; q++) {
            float2 v0 = __half22float2(p0[q]);
            acc[2*q+0] += w0 * v0.x;
            acc[2*q+1] += w0 * v0.y;
        }
    }

    float v[8];
    #pragma unroll
    for (int q = 0; q < 8; q++) v[q] = fmaxf(acc[q] + bias[c8 + q], 0.0f);
    size_t o = (size_t)node * F + c8;
    if (OUT_F16) {
        uint4 packed;
        __half2* hp = (__half2*)&packed;
        #pragma unroll
        for (int q = 0; q < 4; q++) {
            __half2 p;
            p.x = __float2half(v[2*q]); p.y = __float2half(v[2*q+1]);
            hp[q] = p;
        }
        *(uint4*)(oh + o) = packed;
    } else {
        *(float4*)(outf + o)     = make_float4(v[0], v[1], v[2], v[3]);
        *(float4*)(outf + o + 4) = make_float4(v[4], v[5], v[6], v[7]);
    }
}

// ==================== layer 3: skinny GEMM (smem W) + fused scores ====================
__global__ void __launch_bounds__(256)
gemm3_kernel(const float* __restrict__ A, const float* __restrict__ W,
             float* __restrict__ C,
             const float* __restrict__ a_s, const float* __restrict__ a_d) {
    __shared__ float sW[H2 * NC];
    __shared__ float sAs[NC], sAd[NC];
    for (int i = threadIdx.x; i < H2 * NC; i += blockDim.x) sW[i] = W[i];
    if (threadIdx.x < NC) {
        sAs[threadIdx.x] = a_s[threadIdx.x];
        sAd[threadIdx.x] = a_d[threadIdx.x];
    }
    __syncthreads();
    int node = blockIdx.x * blockDim.x + threadIdx.x;
    if (node >= N_NODES) return;
    const float4* a4 = (const float4*)(A + (size_t)node * H2);
    float acc[NC] = {0,0,0,0,0,0,0};
    #pragma unroll 4
    for (int k4 = 0; k4 < H2 / 4; k4++) {
        float4 a = a4[k4];
        const float* w0 = sW + (k4 * 4) * NC;
        #pragma unroll
        for (int c = 0; c < NC; c++)
            acc[c] += a.x * w0[c] + a.y * w0[NC + c] + a.z * w0[2 * NC + c] + a.w * w0[3 * NC + c];
    }
    float vs = 0.0f, vd = 0.0f;
    #pragma unroll
    for (int c = 0; c < NC; c++) {
        C[(size_t)node * NC + c] = acc[c];
        vs += acc[c] * sAs[c];
        vd += acc[c] * sAd[c];
    }
    g_ss[node] = vs;
    g_sd[node] = vd;
}

__global__ void __launch_bounds__(256)
gat_agg3_final_kernel(const float* __restrict__ h, const float* __restrict__ bias,
                      float* __restrict__ out) {
    int node = blockIdx.x * 8 + (threadIdx.x >> 5);
    int lane = threadIdx.x & 31;
    if (node >= N_NODES) return;
    const int beg = g_rowoff[node], end = g_rowoff[node + 1];
    const float sd = g_sd[node];

    float m = -INFINITY;
    for (int i = beg + lane; i < end; i += 32) {
        float e = g_ss[g_csr_src[i]] + sd;
        e = e > 0.0f ? e : 0.2f * e;
        m = fmaxf(m, e);
    }
    #pragma unroll
    for (int o = 16; o > 0; o >>= 1) m = fmaxf(m, __shfl_xor_sync(0xffffffffu, m, o));

    float acc[NC] = {0,0,0,0,0,0,0};
    float den = 0.0f;
    for (int i = beg + lane; i < end; i += 32) {
        int s = g_csr_src[i];
        float e = g_ss[s] + sd;
        e = e > 0.0f ? e : 0.2f * e;
        float ee = __expf(e - m);
        den += ee;
        const float* hr = h + (size_t)s * NC;
        #pragma unroll
        for (int c = 0; c < NC; c++) acc[c] += ee * hr[c];
    }
    #pragma unroll
    for (int o = 16; o > 0; o >>= 1) {
        den += __shfl_xor_sync(0xffffffffu, den, o);
        #pragma unroll
        for (int c = 0; c < NC; c++) acc[c] += __shfl_xor_sync(0xffffffffu, acc[c], o);
    }
    if (lane == 0) {
        float inv = 1.0f / den;
        float z[NC], mx = -INFINITY;
        #pragma unroll
        for (int c = 0; c < NC; c++) {
            z[c] = acc[c] * inv + bias[c];
            mx = fmaxf(mx, z[c]);
        }
        float ssum = 0.0f;
        #pragma unroll
        for (int c = 0; c < NC; c++) ssum += __expf(z[c] - mx);
        float l = logf(ssum);
        float* o = out + (size_t)node * NC;
        #pragma unroll
        for (int c = 0; c < NC; c++) o[c] = z[c] - mx - l;
    }
}

// ==================== launcher ====================
extern "C" void kernel_launch(void* const* d_in, const int* in_sizes, int n_in,
                              void* d_out, int out_size) {
    const float* x   = (const float*)d_in[0];
    const void*  ei  = d_in[1];
    const float* W1  = (const float*)d_in[2];
    const float* as1 = (const float*)d_in[3];
    const float* ad1 = (const float*)d_in[4];
    const float* b1  = (const float*)d_in[5];
    const float* W2  = (const float*)d_in[6];
    const float* as2 = (const float*)d_in[7];
    const float* ad2 = (const float*)d_in[8];
    const float* b2  = (const float*)d_in[9];
    const float* W3  = (const float*)d_in[10];
    const float* as3 = (const float*)d_in[11];
    const float* ad3 = (const float*)d_in[12];
    const float* b3  = (const float*)d_in[13];
    float* out = (float*)d_out;

    float *buf1, *buf2;
    __half *h16, *a16, *b16, *b16b;
    cudaGetSymbolAddress((void**)&buf1, g_buf1);
    cudaGetSymbolAddress((void**)&buf2, g_buf2);
    cudaGetSymbolAddress((void**)&h16, g_h16);
    cudaGetSymbolAddress((void**)&a16, g_A16);
    cudaGetSymbolAddress((void**)&b16, g_B16);
    cudaGetSymbolAddress((void**)&b16b, g_B16b);

    cudaFuncSetAttribute(gemm1_tc_kernel, cudaFuncAttributeMaxDynamicSharedMemorySize, G1_SMEM);
    cudaFuncSetAttribute(gemm_tc_kernel, cudaFuncAttributeMaxDynamicSharedMemorySize, SMEM_DYN);

    const int BT = 256;
    const int edge_blocks      = (NE + BT - 1) / BT;
    const int node_warp_blocks = (N_NODES + (BT / 32) - 1) / (BT / 32);
    const int node_blocks      = (N_NODES + BT - 1) / BT;
    const int agg1_blocks      = (N_NODES * 2 + 7) / 8;   // 2 warps per node

    // ---- fork: CSR build + W2 split on side stream, overlapped with gemm1 chain ----
    cudaStream_t s2;
    cudaStreamCreateWithFlags(&s2, cudaStreamNonBlocking);
    cudaEvent_t evRoot, evSide;
    cudaEventCreateWithFlags(&evRoot, cudaEventDisableTiming);
    cudaEventCreateWithFlags(&evSide, cudaEventDisableTiming);

    cudaEventRecord(evRoot, 0);
    cudaStreamWaitEvent(s2, evRoot, 0);

    // side stream: W2 split + full CSR build
    split_Wt_kernel<<<512, BT, 0, s2>>>(W2, H1, H2, H1, b16b);
    init_kernel<<<node_blocks, BT, 0, s2>>>((const unsigned int*)ei);
    prep_edges_kernel<<<edge_blocks, BT, 0, s2>>>(ei);
    reduce_deg_kernel<<<NB, 256, 0, s2>>>();
    scan_bsums_kernel<<<1, 256, 0, s2>>>();
    scan_write_kernel<<<NB, 256, 0, s2>>>();
    scatter_kernel<<<edge_blocks, BT, 0, s2>>>();
    cudaEventRecord(evSide, s2);

    // main stream: layer-1 GEMM chain (scores fused; needs ss/sd zeroed first)
    zero_s_kernel<<<node_blocks, BT>>>();
    split_Wt_kernel<<<2048, BT>>>(W1, F_IN, H1, K1PAD, b16);
    gemm1_tc_kernel<<<dim3(H1 / 256, MPAD / 128), 512, G1_SMEM>>>(x, b16, h16, as1, ad1);

    // join: alpha needs CSR (side) + scores (main)
    cudaStreamWaitEvent(0, evSide, 0);
    alpha_kernel<<<node_warp_blocks, BT>>>();
    gat_agg_kernel<H1, 2, 1, 1><<<agg1_blocks, BT>>>(h16, b1, nullptr, a16);

    // ---------------- layer 2: H1 -> H2 (scores fused into GEMM) ----------------
    gemm_tc_kernel<<<dim3(H2 / 128, MPAD / 128), BT, SMEM_DYN>>>(a16, b16b, h16, H1, H2, as2, ad2);
    alpha_kernel<<<node_warp_blocks, BT>>>();
    gat_agg_kernel<H2, 1, 0, 0><<<node_warp_blocks, BT>>>(h16, b2, buf2, nullptr);

    // ---------------- layer 3: H2 -> NC (scores fused into GEMM) ----------------
    gemm3_kernel<<<node_blocks, BT>>>(buf2, W3, buf1, as3, ad3);
    alpha_kernel<<<node_warp_blocks, BT>>>();
    gat_agg3_final_kernel<<<node_warp_blocks, BT>>>(buf1, b3, out);

    cudaEventDestroy(evRoot);
    cudaEventDestroy(evSide);
    cudaStreamDestroy(s2);
}